// round 6
// baseline (speedup 1.0000x reference)
#include <cuda_runtime.h>
#include <cuda_bf16.h>
#include <cstdint>
#include <cstddef>

// ---------------------------------------------------------------------------
// Problem constants
// ---------------------------------------------------------------------------
#define Bq   4
#define Tq   2048
#define Dq   1024
#define Hq   16
#define DHq  64
#define INNERq 1024
#define SCALEq 0.125f     // 64^-0.5

#define KVPLANE ((size_t)Bq * Tq * INNERq)

// ---------------------------------------------------------------------------
// Scratch (device globals; allocation is forbidden)
// ---------------------------------------------------------------------------
__device__ __nv_bfloat16 s_xh[(size_t)Bq * Tq * Dq];
__device__ __nv_bfloat16 s_xl[(size_t)Bq * Tq * Dq];
__device__ __nv_bfloat16 s_qh[(size_t)Bq * Tq * INNERq];
__device__ __nv_bfloat16 s_ql[(size_t)Bq * Tq * INNERq];
// K hi, K lo, V hi, V lo packed as 4 planes (single base pointer in flash)
__device__ __nv_bfloat16 s_kv[4 * KVPLANE];
__device__ __nv_bfloat16 s_ah[(size_t)Bq * Tq * INNERq];
__device__ __nv_bfloat16 s_al[(size_t)Bq * Tq * INNERq];
// transposed weights: Wt[n][k] = W[k][n]
__device__ __nv_bfloat16 s_wqh[(size_t)Dq * INNERq];
__device__ __nv_bfloat16 s_wql[(size_t)Dq * INNERq];
__device__ __nv_bfloat16 s_wkh[(size_t)Dq * INNERq];
__device__ __nv_bfloat16 s_wkl[(size_t)Dq * INNERq];
__device__ __nv_bfloat16 s_wvh[(size_t)Dq * INNERq];
__device__ __nv_bfloat16 s_wvl[(size_t)Dq * INNERq];
__device__ __nv_bfloat16 s_woh[(size_t)Dq * INNERq];
__device__ __nv_bfloat16 s_wol[(size_t)Dq * INNERq];

// ---------------------------------------------------------------------------
// PTX helpers (arch-agnostic: mma.sync / ldmatrix / cp.async only)
// ---------------------------------------------------------------------------
__device__ __forceinline__ uint32_t smem_u32(const void* p) {
    uint32_t a;
    asm("{ .reg .u64 t; cvta.to.shared.u64 t, %1; cvt.u32.u64 %0, t; }" : "=r"(a) : "l"(p));
    return a;
}

#define CP_ASYNC16(s, g) \
    asm volatile("cp.async.cg.shared.global [%0], [%1], 16;" :: "r"(s), "l"(g))
#define CP_COMMIT() asm volatile("cp.async.commit_group;" ::: "memory")
#define CP_WAIT0()  asm volatile("cp.async.wait_group 0;" ::: "memory")
#define CP_WAIT1()  asm volatile("cp.async.wait_group 1;" ::: "memory")

#define LDSM_X4(r0, r1, r2, r3, addr) \
    asm volatile("ldmatrix.sync.aligned.m8n8.x4.shared.b16 {%0,%1,%2,%3}, [%4];" \
                 : "=r"(r0), "=r"(r1), "=r"(r2), "=r"(r3) : "r"(addr))

#define LDSM_X4_T(r0, r1, r2, r3, addr) \
    asm volatile("ldmatrix.sync.aligned.m8n8.x4.trans.shared.b16 {%0,%1,%2,%3}, [%4];" \
                 : "=r"(r0), "=r"(r1), "=r"(r2), "=r"(r3) : "r"(addr))

#define MMA_BF16(c0, c1, c2, c3, a0, a1, a2, a3, b0, b1) \
    asm volatile("mma.sync.aligned.m16n8k16.row.col.f32.bf16.bf16.f32 " \
                 "{%0,%1,%2,%3}, {%4,%5,%6,%7}, {%8,%9}, {%0,%1,%2,%3};" \
                 : "+f"(c0), "+f"(c1), "+f"(c2), "+f"(c3) \
                 : "r"(a0), "r"(a1), "r"(a2), "r"(a3), "r"(b0), "r"(b1))

// ---------------------------------------------------------------------------
// fp32 -> bf16 hi/lo split (elementwise)
// ---------------------------------------------------------------------------
__global__ __launch_bounds__(256) void split_kernel(
    const float* __restrict__ in, __nv_bfloat16* __restrict__ hi,
    __nv_bfloat16* __restrict__ lo, int n)
{
    int i = (blockIdx.x * 256 + threadIdx.x) * 4;
    if (i >= n) return;
    float4 v = *reinterpret_cast<const float4*>(in + i);
    __nv_bfloat16 h0 = __float2bfloat16(v.x);
    __nv_bfloat16 h1 = __float2bfloat16(v.y);
    __nv_bfloat16 h2 = __float2bfloat16(v.z);
    __nv_bfloat16 h3 = __float2bfloat16(v.w);
    __nv_bfloat162 H0; H0.x = h0; H0.y = h1;
    __nv_bfloat162 H1; H1.x = h2; H1.y = h3;
    *reinterpret_cast<__nv_bfloat162*>(hi + i)     = H0;
    *reinterpret_cast<__nv_bfloat162*>(hi + i + 2) = H1;
    __nv_bfloat162 L0, L1;
    L0.x = __float2bfloat16(v.x - __bfloat162float(h0));
    L0.y = __float2bfloat16(v.y - __bfloat162float(h1));
    L1.x = __float2bfloat16(v.z - __bfloat162float(h2));
    L1.y = __float2bfloat16(v.w - __bfloat162float(h3));
    *reinterpret_cast<__nv_bfloat162*>(lo + i)     = L0;
    *reinterpret_cast<__nv_bfloat162*>(lo + i + 2) = L1;
}

// ---------------------------------------------------------------------------
// W[K,N] fp32 -> Wt[N,K] bf16 hi/lo (transpose + split)
// ---------------------------------------------------------------------------
__global__ __launch_bounds__(256) void tsplit_kernel(
    const float* __restrict__ W, __nv_bfloat16* __restrict__ th,
    __nv_bfloat16* __restrict__ tl, int K, int N)
{
    __shared__ float t[32][33];
    const int tx = threadIdx.x, ty = threadIdx.y;
    const int bx = blockIdx.x, by = blockIdx.y;
#pragma unroll
    for (int j = 0; j < 32; j += 8)
        t[ty + j][tx] = W[(size_t)(by * 32 + ty + j) * N + bx * 32 + tx];
    __syncthreads();
#pragma unroll
    for (int j = 0; j < 32; j += 8) {
        float v = t[tx][ty + j];
        const int n = bx * 32 + ty + j;
        const int k = by * 32 + tx;
        __nv_bfloat16 h = __float2bfloat16(v);
        th[(size_t)n * K + k] = h;
        tl[(size_t)n * K + k] = __float2bfloat16(v - __bfloat162float(h));
    }
}

// ---------------------------------------------------------------------------
// mma.sync bf16 split GEMM: C = (Ah+Al)[M,K] @ (Bh+Bl)^T, B given [N,K].
// Output: either fp32 (+bias) or bf16 hi/lo split (scaled).
// ---------------------------------------------------------------------------
#define GBM 128
#define GBN 128
#define GBK 32
#define TILEB (128 * 40 * 2)
#define STAGEB (4 * TILEB)
#define GEMM_SMEM (2 * STAGEB)           // 81920 bytes

__global__ __launch_bounds__(256, 2) void gemm_mma_kernel(
    const __nv_bfloat16* __restrict__ Ah, const __nv_bfloat16* __restrict__ Al,
    const __nv_bfloat16* __restrict__ Bh, const __nv_bfloat16* __restrict__ Bl,
    float* __restrict__ C, const float* __restrict__ bias,
    __nv_bfloat16* __restrict__ outH, __nv_bfloat16* __restrict__ outL,
    float scale, int M, int N, int K)
{
    extern __shared__ char smem[];
    const uint32_t sb = smem_u32(smem);

    const int tid = threadIdx.x;
    const int wid = tid >> 5;
    const int lane = tid & 31;
    const int warp_m = wid >> 1;
    const int warp_n = wid & 1;
    const int row0 = blockIdx.y * GBM;
    const int col0 = blockIdx.x * GBN;

    const int r0l = (tid * 2) >> 2;
    const int c0l = (tid * 2) & 3;
    const int r1l = (tid * 2 + 1) >> 2;
    const int c1l = (tid * 2 + 1) & 3;

    float acc[2][8][4];
#pragma unroll
    for (int i = 0; i < 2; ++i)
#pragma unroll
        for (int j = 0; j < 8; ++j)
#pragma unroll
            for (int q = 0; q < 4; ++q) acc[i][j][q] = 0.0f;

    auto load_stage = [&](int stage, int k0) {
        const uint32_t st = sb + stage * STAGEB;
        const __nv_bfloat16* gA[2] = { Ah, Al };
        const __nv_bfloat16* gB[2] = { Bh, Bl };
#pragma unroll
        for (int half = 0; half < 2; ++half) {
            {
                const uint32_t s0 = st + half * TILEB + r0l * 80 + c0l * 16;
                const uint32_t s1 = st + half * TILEB + r1l * 80 + c1l * 16;
                CP_ASYNC16(s0, gA[half] + (size_t)(row0 + r0l) * K + k0 + c0l * 8);
                CP_ASYNC16(s1, gA[half] + (size_t)(row0 + r1l) * K + k0 + c1l * 8);
            }
            {
                const uint32_t s0 = st + (2 + half) * TILEB + r0l * 80 + c0l * 16;
                const uint32_t s1 = st + (2 + half) * TILEB + r1l * 80 + c1l * 16;
                CP_ASYNC16(s0, gB[half] + (size_t)(col0 + r0l) * K + k0 + c0l * 8);
                CP_ASYNC16(s1, gB[half] + (size_t)(col0 + r1l) * K + k0 + c1l * 8);
            }
        }
    };

    load_stage(0, 0);
    CP_COMMIT();

    const int chunks = K / GBK;
    for (int c = 0; c < chunks; ++c) {
        if (c + 1 < chunks) {
            load_stage((c + 1) & 1, (c + 1) * GBK);
            CP_COMMIT();
            CP_WAIT1();
        } else {
            CP_WAIT0();
        }
        __syncthreads();

        const uint32_t st = sb + (c & 1) * STAGEB;
        const uint32_t aH = st;
        const uint32_t aL = st + TILEB;
        const uint32_t bH = st + 2 * TILEB;
        const uint32_t bL = st + 3 * TILEB;

#pragma unroll
        for (int kst = 0; kst < 2; ++kst) {
            const int kb = kst * 32 + (lane >> 4) * 16;

            uint32_t ah[2][4], al[2][4];
#pragma unroll
            for (int mt = 0; mt < 2; ++mt) {
                const int arow = warp_m * 32 + mt * 16 + (lane & 15);
                LDSM_X4(ah[mt][0], ah[mt][1], ah[mt][2], ah[mt][3], aH + arow * 80 + kb);
                LDSM_X4(al[mt][0], al[mt][1], al[mt][2], al[mt][3], aL + arow * 80 + kb);
            }

#pragma unroll
            for (int g = 0; g < 2; ++g) {
                uint32_t bh[4][2], bl[4][2];
                const int brow_in = (lane & 7) + ((lane >> 4) << 3);
                const int bkb = kst * 32 + ((lane >> 3) & 1) * 16;
#pragma unroll
                for (int p = 0; p < 2; ++p) {
                    const int nb = warp_n * 64 + g * 32 + p * 16;
                    const uint32_t ba = (nb + brow_in) * 80 + bkb;
                    LDSM_X4(bh[2 * p][0], bh[2 * p][1], bh[2 * p + 1][0], bh[2 * p + 1][1],
                            bH + ba);
                    LDSM_X4(bl[2 * p][0], bl[2 * p][1], bl[2 * p + 1][0], bl[2 * p + 1][1],
                            bL + ba);
                }
#pragma unroll
                for (int mt = 0; mt < 2; ++mt)
#pragma unroll
                    for (int nt = 0; nt < 4; ++nt) {
                        float* cc = acc[mt][g * 4 + nt];
                        MMA_BF16(cc[0], cc[1], cc[2], cc[3],
                                 ah[mt][0], ah[mt][1], ah[mt][2], ah[mt][3],
                                 bh[nt][0], bh[nt][1]);
                        MMA_BF16(cc[0], cc[1], cc[2], cc[3],
                                 ah[mt][0], ah[mt][1], ah[mt][2], ah[mt][3],
                                 bl[nt][0], bl[nt][1]);
                        MMA_BF16(cc[0], cc[1], cc[2], cc[3],
                                 al[mt][0], al[mt][1], al[mt][2], al[mt][3],
                                 bh[nt][0], bh[nt][1]);
                    }
            }
        }
        __syncthreads();
    }

    // epilogue
#pragma unroll
    for (int mt = 0; mt < 2; ++mt) {
        const int rbase = row0 + warp_m * 32 + mt * 16 + (lane >> 2);
#pragma unroll
        for (int nt = 0; nt < 8; ++nt) {
            const int cbase = col0 + warp_n * 64 + nt * 8 + (lane & 3) * 2;
            float v0 = acc[mt][nt][0], v1 = acc[mt][nt][1];
            float v2 = acc[mt][nt][2], v3 = acc[mt][nt][3];
            if (outH) {
                v0 *= scale; v1 *= scale; v2 *= scale; v3 *= scale;
                __nv_bfloat162 h01 = __float22bfloat162_rn(make_float2(v0, v1));
                __nv_bfloat162 h23 = __float22bfloat162_rn(make_float2(v2, v3));
                float2 f01 = __bfloat1622float2(h01);
                float2 f23 = __bfloat1622float2(h23);
                __nv_bfloat162 l01 = __float22bfloat162_rn(make_float2(v0 - f01.x, v1 - f01.y));
                __nv_bfloat162 l23 = __float22bfloat162_rn(make_float2(v2 - f23.x, v3 - f23.y));
                *reinterpret_cast<__nv_bfloat162*>(outH + (size_t)rbase * N + cbase) = h01;
                *reinterpret_cast<__nv_bfloat162*>(outH + (size_t)(rbase + 8) * N + cbase) = h23;
                *reinterpret_cast<__nv_bfloat162*>(outL + (size_t)rbase * N + cbase) = l01;
                *reinterpret_cast<__nv_bfloat162*>(outL + (size_t)(rbase + 8) * N + cbase) = l23;
            } else {
                if (bias) {
                    const float b0 = bias[cbase], b1 = bias[cbase + 1];
                    v0 += b0; v1 += b1; v2 += b0; v3 += b1;
                }
                float2 w0 = make_float2(v0, v1), w1 = make_float2(v2, v3);
                *reinterpret_cast<float2*>(C + (size_t)rbase * N + cbase) = w0;
                *reinterpret_cast<float2*>(C + (size_t)(rbase + 8) * N + cbase) = w1;
            }
        }
    }
}

// ---------------------------------------------------------------------------
// Tensor-core flash attention (bf16 split, mma.sync).
// Register-pressure-optimized: P frags built per-j inside PV loop; KV packed
// (1 base pointer); mask preloaded as S-accumulator initializer.
// ---------------------------------------------------------------------------
#define FBQ 128
#define FBK 64
#define FROWB 144
#define FQ_TILE (FBQ * FROWB)             // 18432 B
#define FKV_TILE (FBK * FROWB)            // 9216 B
#define F_ST (2 * FQ_TILE)                // 36864
#define F_STAGE (4 * FKV_TILE)            // 36864
#define FLASH_SMEM (F_ST + 2 * F_STAGE)   // 110592 B

__global__ __launch_bounds__(256, 2) void flash_mma_kernel(
    const float* __restrict__ mask,
    const __nv_bfloat16* __restrict__ Qh, const __nv_bfloat16* __restrict__ Ql,
    const __nv_bfloat16* __restrict__ KV,   // 4 planes: Kh, Kl, Vh, Vl
    __nv_bfloat16* __restrict__ Oh, __nv_bfloat16* __restrict__ Ol)
{
    extern __shared__ char smem[];
    const uint32_t sb = smem_u32(smem);

    const int tid  = threadIdx.x;
    const int wid  = tid >> 5;
    const int lane = tid & 31;
    const int q0 = blockIdx.x * FBQ;
    const int h  = blockIdx.y;
    const int b  = blockIdx.z;

    const size_t headoff = (size_t)b * Tq * INNERq + (size_t)h * DHq;
    const __nv_bfloat16* gQh = Qh + headoff;
    const __nv_bfloat16* gQl = Ql + headoff;
    const __nv_bfloat16* gKV = KV + headoff;
    const float* Mg = mask + (size_t)b * Tq * Tq;

    // ---- prologue: Q tiles (hi/lo) + KV stage 0 via cp.async ----
    {
#pragma unroll
        for (int t = 0; t < 8; ++t) {
            const int id = t * 256 + tid;
            const int tile = id >> 10;
            const int rem = id & 1023;
            const int row = rem >> 3;
            const int seg = rem & 7;
            const uint32_t s = sb + tile * FQ_TILE + row * FROWB + seg * 16;
            const __nv_bfloat16* g = (tile ? gQl : gQh) + (size_t)(q0 + row) * INNERq + seg * 8;
            CP_ASYNC16(s, g);
        }
#pragma unroll
        for (int t = 0; t < 8; ++t) {
            const int id = t * 256 + tid;
            const int tile = id >> 9;           // 0=Kh,1=Kl,2=Vh,3=Vl
            const int rem = id & 511;
            const int row = rem >> 3;
            const int seg = rem & 7;
            const uint32_t s = sb + F_ST + tile * FKV_TILE + row * FROWB + seg * 16;
            CP_ASYNC16(s, gKV + (size_t)tile * KVPLANE + (size_t)row * INNERq + seg * 8);
        }
        CP_COMMIT();
    }

    float o[8][4];
#pragma unroll
    for (int t = 0; t < 8; ++t)
#pragma unroll
        for (int j = 0; j < 4; ++j) o[t][j] = 0.0f;
    float m0 = -1e30f, m1 = -1e30f, l0 = 0.0f, l1 = 0.0f;

    const int r0g = q0 + wid * 16 + (lane >> 2);
    const int quadcol = (lane & 3) * 2;

    const int chunks = Tq / FBK;   // 32
    for (int c = 0; c < chunks; ++c) {
        const int j0 = c * FBK;
        if (c + 1 < chunks) {
            const int jn = j0 + FBK;
            const uint32_t stn = sb + F_ST + ((c + 1) & 1) * F_STAGE;
#pragma unroll
            for (int t = 0; t < 8; ++t) {
                const int id = t * 256 + tid;
                const int tile = id >> 9;
                const int rem = id & 511;
                const int row = rem >> 3;
                const int seg = rem & 7;
                const uint32_t s = stn + tile * FKV_TILE + row * FROWB + seg * 16;
                CP_ASYNC16(s, gKV + (size_t)tile * KVPLANE + (size_t)(jn + row) * INNERq + seg * 8);
            }
            CP_COMMIT();
            CP_WAIT1();
        } else {
            CP_WAIT0();
        }
        __syncthreads();

        const uint32_t st = sb + F_ST + (c & 1) * F_STAGE;
        const uint32_t kH = st;
        const uint32_t kL = st + FKV_TILE;
        const uint32_t vH = st + 2 * FKV_TILE;
        const uint32_t vL = st + 3 * FKV_TILE;

        // ---- S accumulators initialized with mask (free add + early L2 loads) ----
        float s[8][4];
        {
            const float* m0p = Mg + (size_t)r0g * Tq + j0 + quadcol;
            const float* m1p = m0p + 8 * Tq;
#pragma unroll
            for (int t = 0; t < 8; ++t) {
                float2 mv0 = *reinterpret_cast<const float2*>(m0p + t * 8);
                float2 mv1 = *reinterpret_cast<const float2*>(m1p + t * 8);
                s[t][0] = mv0.x; s[t][1] = mv0.y;
                s[t][2] = mv1.x; s[t][3] = mv1.y;
            }
        }

        // ---- S += Q K^T (split, 3 passes) ----
        const int brow_in = (lane & 7) + ((lane >> 4) << 3);
#pragma unroll
        for (int kk = 0; kk < 4; ++kk) {
            uint32_t qh4[4], ql4[4];
            const uint32_t qa = sb + (wid * 16 + (lane & 15)) * FROWB
                              + kk * 32 + (lane >> 4) * 16;
            LDSM_X4(qh4[0], qh4[1], qh4[2], qh4[3], qa);
            LDSM_X4(ql4[0], ql4[1], ql4[2], ql4[3], qa + FQ_TILE);

            const int bkb = kk * 32 + ((lane >> 3) & 1) * 16;
#pragma unroll
            for (int p = 0; p < 4; ++p) {
                uint32_t bh[2][2], bl[2][2];
                const uint32_t ba = (p * 16 + brow_in) * FROWB + bkb;
                LDSM_X4(bh[0][0], bh[0][1], bh[1][0], bh[1][1], kH + ba);
                LDSM_X4(bl[0][0], bl[0][1], bl[1][0], bl[1][1], kL + ba);
#pragma unroll
                for (int u = 0; u < 2; ++u) {
                    float* cc = s[2 * p + u];
                    MMA_BF16(cc[0], cc[1], cc[2], cc[3],
                             qh4[0], qh4[1], qh4[2], qh4[3], bh[u][0], bh[u][1]);
                    MMA_BF16(cc[0], cc[1], cc[2], cc[3],
                             ql4[0], ql4[1], ql4[2], ql4[3], bh[u][0], bh[u][1]);
                    MMA_BF16(cc[0], cc[1], cc[2], cc[3],
                             qh4[0], qh4[1], qh4[2], qh4[3], bl[u][0], bl[u][1]);
                }
            }
        }

        // ---- online softmax ----
        float mx0 = -1e30f, mx1 = -1e30f;
#pragma unroll
        for (int t = 0; t < 8; ++t) {
            mx0 = fmaxf(mx0, fmaxf(s[t][0], s[t][1]));
            mx1 = fmaxf(mx1, fmaxf(s[t][2], s[t][3]));
        }
        mx0 = fmaxf(mx0, __shfl_xor_sync(0xffffffffu, mx0, 1));
        mx0 = fmaxf(mx0, __shfl_xor_sync(0xffffffffu, mx0, 2));
        mx1 = fmaxf(mx1, __shfl_xor_sync(0xffffffffu, mx1, 1));
        mx1 = fmaxf(mx1, __shfl_xor_sync(0xffffffffu, mx1, 2));

        const float mn0 = fmaxf(m0, mx0);
        const float mn1 = fmaxf(m1, mx1);
        const float a0 = __expf(m0 - mn0);
        const float a1 = __expf(m1 - mn1);
        m0 = mn0; m1 = mn1;

        float sum0 = 0.0f, sum1 = 0.0f;
#pragma unroll
        for (int t = 0; t < 8; ++t) {
            s[t][0] = __expf(s[t][0] - mn0);
            s[t][1] = __expf(s[t][1] - mn0);
            s[t][2] = __expf(s[t][2] - mn1);
            s[t][3] = __expf(s[t][3] - mn1);
            sum0 += s[t][0] + s[t][1];
            sum1 += s[t][2] + s[t][3];
        }
        sum0 += __shfl_xor_sync(0xffffffffu, sum0, 1);
        sum0 += __shfl_xor_sync(0xffffffffu, sum0, 2);
        sum1 += __shfl_xor_sync(0xffffffffu, sum1, 1);
        sum1 += __shfl_xor_sync(0xffffffffu, sum1, 2);
        l0 = l0 * a0 + sum0;
        l1 = l1 * a1 + sum1;

#pragma unroll
        for (int t = 0; t < 8; ++t) {
            o[t][0] *= a0; o[t][1] *= a0;
            o[t][2] *= a1; o[t][3] *= a1;
        }

        // ---- O += P V: build P hi/lo fragments per j (low reg pressure) ----
#pragma unroll
        for (int j = 0; j < 4; ++j) {
            uint32_t pH[4], pL[4];
#pragma unroll
            for (int u = 0; u < 2; ++u) {
#pragma unroll
                for (int w = 0; w < 2; ++w) {
                    const float e0 = s[2 * j + w][2 * u + 0];
                    const float e1 = s[2 * j + w][2 * u + 1];
                    __nv_bfloat162 hh = __float22bfloat162_rn(make_float2(e0, e1));
                    float2 hf = __bfloat1622float2(hh);
                    __nv_bfloat162 ll = __float22bfloat162_rn(
                        make_float2(e0 - hf.x, e1 - hf.y));
                    pH[2 * w + u] = *reinterpret_cast<uint32_t*>(&hh);
                    pL[2 * w + u] = *reinterpret_cast<uint32_t*>(&ll);
                }
            }
#pragma unroll
            for (int p = 0; p < 4; ++p) {
                uint32_t vh4[2][2], vl4[2][2];
                const uint32_t va = (j * 16 + (lane & 15)) * FROWB
                                  + p * 32 + (lane >> 4) * 16;
                LDSM_X4_T(vh4[0][0], vh4[0][1], vh4[1][0], vh4[1][1], vH + va);
                LDSM_X4_T(vl4[0][0], vl4[0][1], vl4[1][0], vl4[1][1], vL + va);
#pragma unroll
                for (int u = 0; u < 2; ++u) {
                    float* cc = o[2 * p + u];
                    MMA_BF16(cc[0], cc[1], cc[2], cc[3],
                             pH[0], pH[1], pH[2], pH[3], vh4[u][0], vh4[u][1]);
                    MMA_BF16(cc[0], cc[1], cc[2], cc[3],
                             pL[0], pL[1], pL[2], pL[3], vh4[u][0], vh4[u][1]);
                    MMA_BF16(cc[0], cc[1], cc[2], cc[3],
                             pH[0], pH[1], pH[2], pH[3], vl4[u][0], vl4[u][1]);
                }
            }
        }
        __syncthreads();
    }

    // ---- epilogue: normalize, split to bf16 hi/lo, store ----
    const float inv0 = 1.0f / l0;
    const float inv1 = 1.0f / l1;
    const size_t row0o = ((size_t)b * Tq + r0g) * INNERq + (size_t)h * DHq;
    const size_t row1o = row0o + 8 * INNERq;
#pragma unroll
    for (int t = 0; t < 8; ++t) {
        const int col = t * 8 + quadcol;
        float v0 = o[t][0] * inv0, v1 = o[t][1] * inv0;
        float v2 = o[t][2] * inv1, v3 = o[t][3] * inv1;
        __nv_bfloat162 h01 = __float22bfloat162_rn(make_float2(v0, v1));
        __nv_bfloat162 h23 = __float22bfloat162_rn(make_float2(v2, v3));
        float2 f01 = __bfloat1622float2(h01);
        float2 f23 = __bfloat1622float2(h23);
        __nv_bfloat162 l01 = __float22bfloat162_rn(make_float2(v0 - f01.x, v1 - f01.y));
        __nv_bfloat162 l23 = __float22bfloat162_rn(make_float2(v2 - f23.x, v3 - f23.y));
        *reinterpret_cast<__nv_bfloat162*>(Oh + row0o + col) = h01;
        *reinterpret_cast<__nv_bfloat162*>(Ol + row0o + col) = l01;
        *reinterpret_cast<__nv_bfloat162*>(Oh + row1o + col) = h23;
        *reinterpret_cast<__nv_bfloat162*>(Ol + row1o + col) = l23;
    }
}

// ---------------------------------------------------------------------------
// kernel_launch
// Inputs: x, attention_mask, Wq, Wk, Wv, Wo, bo
// ---------------------------------------------------------------------------
extern "C" void kernel_launch(void* const* d_in, const int* in_sizes, int n_in,
                              void* d_out, int out_size)
{
    (void)in_sizes; (void)n_in; (void)out_size;
    const float* x    = (const float*)d_in[0];
    const float* mask = (const float*)d_in[1];
    const float* Wq   = (const float*)d_in[2];
    const float* Wk   = (const float*)d_in[3];
    const float* Wv   = (const float*)d_in[4];
    const float* Wo   = (const float*)d_in[5];
    const float* bo   = (const float*)d_in[6];
    float* out = (float*)d_out;

    __nv_bfloat16 *xh, *xl, *ah, *al, *qh, *ql, *kv;
    cudaGetSymbolAddress((void**)&xh, s_xh);
    cudaGetSymbolAddress((void**)&xl, s_xl);
    cudaGetSymbolAddress((void**)&ah, s_ah);
    cudaGetSymbolAddress((void**)&al, s_al);
    cudaGetSymbolAddress((void**)&qh, s_qh);
    cudaGetSymbolAddress((void**)&ql, s_ql);
    cudaGetSymbolAddress((void**)&kv, s_kv);
    __nv_bfloat16 *wqh, *wql, *wkh, *wkl, *wvh, *wvl, *woh, *wol;
    cudaGetSymbolAddress((void**)&wqh, s_wqh);
    cudaGetSymbolAddress((void**)&wql, s_wql);
    cudaGetSymbolAddress((void**)&wkh, s_wkh);
    cudaGetSymbolAddress((void**)&wkl, s_wkl);
    cudaGetSymbolAddress((void**)&wvh, s_wvh);
    cudaGetSymbolAddress((void**)&wvl, s_wvl);
    cudaGetSymbolAddress((void**)&woh, s_woh);
    cudaGetSymbolAddress((void**)&wol, s_wol);

    const int M = Bq * Tq;     // 8192
    const int N = INNERq;      // 1024
    const int K = Dq;          // 1024
    const int nx = M * K;

    // conversions
    split_kernel<<<nx / (256 * 4), 256>>>(x, xh, xl, nx);
    dim3 tGrid(N / 32, K / 32), tBlk(32, 8);
    tsplit_kernel<<<tGrid, tBlk>>>(Wq, wqh, wql, K, N);
    tsplit_kernel<<<tGrid, tBlk>>>(Wk, wkh, wkl, K, N);
    tsplit_kernel<<<tGrid, tBlk>>>(Wv, wvh, wvl, K, N);
    tsplit_kernel<<<tGrid, tBlk>>>(Wo, woh, wol, K, N);

    // projections -> bf16 hi/lo (Q pre-scaled; K/V into packed planes)
    cudaFuncSetAttribute(gemm_mma_kernel,
                         cudaFuncAttributeMaxDynamicSharedMemorySize, GEMM_SMEM);
    dim3 gGrid(N / GBN, M / GBM);
    gemm_mma_kernel<<<gGrid, 256, GEMM_SMEM>>>(xh, xl, wqh, wql,
        nullptr, nullptr, qh, ql, SCALEq, M, N, K);
    gemm_mma_kernel<<<gGrid, 256, GEMM_SMEM>>>(xh, xl, wkh, wkl,
        nullptr, nullptr, kv + 0 * KVPLANE, kv + 1 * KVPLANE, 1.0f, M, N, K);
    gemm_mma_kernel<<<gGrid, 256, GEMM_SMEM>>>(xh, xl, wvh, wvl,
        nullptr, nullptr, kv + 2 * KVPLANE, kv + 3 * KVPLANE, 1.0f, M, N, K);

    // flash attention (tensor cores) -> bf16 hi/lo
    cudaFuncSetAttribute(flash_mma_kernel,
                         cudaFuncAttributeMaxDynamicSharedMemorySize, FLASH_SMEM);
    dim3 fGrid(Tq / FBQ, Hq, Bq);   // (16, 16, 4)
    flash_mma_kernel<<<fGrid, 256, FLASH_SMEM>>>(mask, qh, ql, kv, ah, al);

    // output projection (fp32 + bias)
    gemm_mma_kernel<<<gGrid, 256, GEMM_SMEM>>>(ah, al, woh, wol,
        out, bo, nullptr, nullptr, 1.0f, M, Dq, INNERq);
}

// round 7
// speedup vs baseline: 1.1270x; 1.1270x over previous
#include <cuda_runtime.h>
#include <cuda_bf16.h>
#include <cstdint>
#include <cstddef>

// ---------------------------------------------------------------------------
// Problem constants
// ---------------------------------------------------------------------------
#define Bq   4
#define Tq   2048
#define Dq   1024
#define Hq   16
#define DHq  64
#define INNERq 1024
#define SCALEq 0.125f     // 64^-0.5

#define KVPLANE ((size_t)Bq * Tq * INNERq)
#define WPLANE  ((size_t)Dq * INNERq)

// ---------------------------------------------------------------------------
// Scratch (device globals; allocation is forbidden)
// ---------------------------------------------------------------------------
__device__ __nv_bfloat16 s_xh[(size_t)Bq * Tq * Dq];
__device__ __nv_bfloat16 s_xl[(size_t)Bq * Tq * Dq];
// Q hi, Q lo, K hi, K lo, V hi, V lo as 6 contiguous planes
__device__ __nv_bfloat16 s_qkv[6 * KVPLANE];
__device__ __nv_bfloat16 s_ah[(size_t)Bq * Tq * INNERq];
__device__ __nv_bfloat16 s_al[(size_t)Bq * Tq * INNERq];
// transposed weights, 8 contiguous planes: Wq h, Wq l, Wk h, Wk l, Wv h, Wv l, Wo h, Wo l
__device__ __nv_bfloat16 s_w8[8 * WPLANE];

// ---------------------------------------------------------------------------
// PTX helpers (arch-agnostic: mma.sync / ldmatrix / cp.async only)
// ---------------------------------------------------------------------------
__device__ __forceinline__ uint32_t smem_u32(const void* p) {
    uint32_t a;
    asm("{ .reg .u64 t; cvta.to.shared.u64 t, %1; cvt.u32.u64 %0, t; }" : "=r"(a) : "l"(p));
    return a;
}

#define CP_ASYNC16(s, g) \
    asm volatile("cp.async.cg.shared.global [%0], [%1], 16;" :: "r"(s), "l"(g))
#define CP_COMMIT() asm volatile("cp.async.commit_group;" ::: "memory")
#define CP_WAIT0()  asm volatile("cp.async.wait_group 0;" ::: "memory")
#define CP_WAIT1()  asm volatile("cp.async.wait_group 1;" ::: "memory")

#define LDSM_X4(r0, r1, r2, r3, addr) \
    asm volatile("ldmatrix.sync.aligned.m8n8.x4.shared.b16 {%0,%1,%2,%3}, [%4];" \
                 : "=r"(r0), "=r"(r1), "=r"(r2), "=r"(r3) : "r"(addr))

#define LDSM_X4_T(r0, r1, r2, r3, addr) \
    asm volatile("ldmatrix.sync.aligned.m8n8.x4.trans.shared.b16 {%0,%1,%2,%3}, [%4];" \
                 : "=r"(r0), "=r"(r1), "=r"(r2), "=r"(r3) : "r"(addr))

#define MMA_BF16(c0, c1, c2, c3, a0, a1, a2, a3, b0, b1) \
    asm volatile("mma.sync.aligned.m16n8k16.row.col.f32.bf16.bf16.f32 " \
                 "{%0,%1,%2,%3}, {%4,%5,%6,%7}, {%8,%9}, {%0,%1,%2,%3};" \
                 : "+f"(c0), "+f"(c1), "+f"(c2), "+f"(c3) \
                 : "r"(a0), "r"(a1), "r"(a2), "r"(a3), "r"(b0), "r"(b1))

// ---------------------------------------------------------------------------
// fp32 -> bf16 hi/lo split (elementwise)
// ---------------------------------------------------------------------------
__global__ __launch_bounds__(256) void split_kernel(
    const float* __restrict__ in, __nv_bfloat16* __restrict__ hi,
    __nv_bfloat16* __restrict__ lo, int n)
{
    int i = (blockIdx.x * 256 + threadIdx.x) * 4;
    if (i >= n) return;
    float4 v = *reinterpret_cast<const float4*>(in + i);
    __nv_bfloat16 h0 = __float2bfloat16(v.x);
    __nv_bfloat16 h1 = __float2bfloat16(v.y);
    __nv_bfloat16 h2 = __float2bfloat16(v.z);
    __nv_bfloat16 h3 = __float2bfloat16(v.w);
    __nv_bfloat162 H0; H0.x = h0; H0.y = h1;
    __nv_bfloat162 H1; H1.x = h2; H1.y = h3;
    *reinterpret_cast<__nv_bfloat162*>(hi + i)     = H0;
    *reinterpret_cast<__nv_bfloat162*>(hi + i + 2) = H1;
    __nv_bfloat162 L0, L1;
    L0.x = __float2bfloat16(v.x - __bfloat162float(h0));
    L0.y = __float2bfloat16(v.y - __bfloat162float(h1));
    L1.x = __float2bfloat16(v.z - __bfloat162float(h2));
    L1.y = __float2bfloat16(v.w - __bfloat162float(h3));
    *reinterpret_cast<__nv_bfloat162*>(lo + i)     = L0;
    *reinterpret_cast<__nv_bfloat162*>(lo + i + 2) = L1;
}

// ---------------------------------------------------------------------------
// W[K,N] fp32 -> Wt[N,K] bf16 hi/lo (transpose + split)
// ---------------------------------------------------------------------------
__global__ __launch_bounds__(256) void tsplit_kernel(
    const float* __restrict__ W, __nv_bfloat16* __restrict__ th,
    __nv_bfloat16* __restrict__ tl, int K, int N)
{
    __shared__ float t[32][33];
    const int tx = threadIdx.x, ty = threadIdx.y;
    const int bx = blockIdx.x, by = blockIdx.y;
#pragma unroll
    for (int j = 0; j < 32; j += 8)
        t[ty + j][tx] = W[(size_t)(by * 32 + ty + j) * N + bx * 32 + tx];
    __syncthreads();
#pragma unroll
    for (int j = 0; j < 32; j += 8) {
        float v = t[tx][ty + j];
        const int n = bx * 32 + ty + j;
        const int k = by * 32 + tx;
        __nv_bfloat16 h = __float2bfloat16(v);
        th[(size_t)n * K + k] = h;
        tl[(size_t)n * K + k] = __float2bfloat16(v - __bfloat162float(h));
    }
}

// ---------------------------------------------------------------------------
// mma.sync bf16 split GEMM: C = (Ah+Al)[M,K] @ (Bh+Bl)^T, B given [N,K].
// If W8/QKV given, blockIdx.z selects weight planes 2z,2z+1 and output planes
// 2z,2z+1 (z=0 scaled by SCALEq). Else C (+bias) fp32 output.
// ---------------------------------------------------------------------------
#define GBM 128
#define GBN 128
#define GBK 32
#define TILEB (128 * 40 * 2)
#define STAGEB (4 * TILEB)
#define GEMM_SMEM (2 * STAGEB)           // 81920 bytes

__global__ __launch_bounds__(256, 2) void gemm_mma_kernel(
    const __nv_bfloat16* __restrict__ Ah, const __nv_bfloat16* __restrict__ Al,
    const __nv_bfloat16* __restrict__ W8,    // 8-plane weight base (QKV mode) or null
    __nv_bfloat16* __restrict__ QKV,         // 6-plane output base (QKV mode) or null
    const __nv_bfloat16* __restrict__ Bh_, const __nv_bfloat16* __restrict__ Bl_,
    float* __restrict__ C, const float* __restrict__ bias,
    __nv_bfloat16* __restrict__ outH_, __nv_bfloat16* __restrict__ outL_,
    float scale_, int M, int N, int K)
{
    extern __shared__ char smem[];
    const uint32_t sb = smem_u32(smem);

    const __nv_bfloat16* Bh = Bh_;
    const __nv_bfloat16* Bl = Bl_;
    __nv_bfloat16* outH = outH_;
    __nv_bfloat16* outL = outL_;
    float scale = scale_;
    if (W8) {
        const int z = blockIdx.z;
        Bh = W8 + (size_t)(2 * z) * WPLANE;
        Bl = W8 + (size_t)(2 * z + 1) * WPLANE;
        outH = QKV + (size_t)(2 * z) * KVPLANE;
        outL = QKV + (size_t)(2 * z + 1) * KVPLANE;
        scale = (z == 0) ? SCALEq : 1.0f;
    }

    const int tid = threadIdx.x;
    const int wid = tid >> 5;
    const int lane = tid & 31;
    const int warp_m = wid >> 1;
    const int warp_n = wid & 1;
    const int row0 = blockIdx.y * GBM;
    const int col0 = blockIdx.x * GBN;

    const int r0l = (tid * 2) >> 2;
    const int c0l = (tid * 2) & 3;
    const int r1l = (tid * 2 + 1) >> 2;
    const int c1l = (tid * 2 + 1) & 3;

    float acc[2][8][4];
#pragma unroll
    for (int i = 0; i < 2; ++i)
#pragma unroll
        for (int j = 0; j < 8; ++j)
#pragma unroll
            for (int q = 0; q < 4; ++q) acc[i][j][q] = 0.0f;

    auto load_stage = [&](int stage, int k0) {
        const uint32_t st = sb + stage * STAGEB;
        const __nv_bfloat16* gA[2] = { Ah, Al };
        const __nv_bfloat16* gB[2] = { Bh, Bl };
#pragma unroll
        for (int half = 0; half < 2; ++half) {
            {
                const uint32_t s0 = st + half * TILEB + r0l * 80 + c0l * 16;
                const uint32_t s1 = st + half * TILEB + r1l * 80 + c1l * 16;
                CP_ASYNC16(s0, gA[half] + (size_t)(row0 + r0l) * K + k0 + c0l * 8);
                CP_ASYNC16(s1, gA[half] + (size_t)(row0 + r1l) * K + k0 + c1l * 8);
            }
            {
                const uint32_t s0 = st + (2 + half) * TILEB + r0l * 80 + c0l * 16;
                const uint32_t s1 = st + (2 + half) * TILEB + r1l * 80 + c1l * 16;
                CP_ASYNC16(s0, gB[half] + (size_t)(col0 + r0l) * K + k0 + c0l * 8);
                CP_ASYNC16(s1, gB[half] + (size_t)(col0 + r1l) * K + k0 + c1l * 8);
            }
        }
    };

    load_stage(0, 0);
    CP_COMMIT();

    const int chunks = K / GBK;
    for (int c = 0; c < chunks; ++c) {
        if (c + 1 < chunks) {
            load_stage((c + 1) & 1, (c + 1) * GBK);
            CP_COMMIT();
            CP_WAIT1();
        } else {
            CP_WAIT0();
        }
        __syncthreads();

        const uint32_t st = sb + (c & 1) * STAGEB;
        const uint32_t aH = st;
        const uint32_t aL = st + TILEB;
        const uint32_t bH = st + 2 * TILEB;
        const uint32_t bL = st + 3 * TILEB;

#pragma unroll
        for (int kst = 0; kst < 2; ++kst) {
            const int kb = kst * 32 + (lane >> 4) * 16;

            uint32_t ah[2][4], al[2][4];
#pragma unroll
            for (int mt = 0; mt < 2; ++mt) {
                const int arow = warp_m * 32 + mt * 16 + (lane & 15);
                LDSM_X4(ah[mt][0], ah[mt][1], ah[mt][2], ah[mt][3], aH + arow * 80 + kb);
                LDSM_X4(al[mt][0], al[mt][1], al[mt][2], al[mt][3], aL + arow * 80 + kb);
            }

#pragma unroll
            for (int g = 0; g < 2; ++g) {
                uint32_t bh[4][2], bl[4][2];
                const int brow_in = (lane & 7) + ((lane >> 4) << 3);
                const int bkb = kst * 32 + ((lane >> 3) & 1) * 16;
#pragma unroll
                for (int p = 0; p < 2; ++p) {
                    const int nb = warp_n * 64 + g * 32 + p * 16;
                    const uint32_t ba = (nb + brow_in) * 80 + bkb;
                    LDSM_X4(bh[2 * p][0], bh[2 * p][1], bh[2 * p + 1][0], bh[2 * p + 1][1],
                            bH + ba);
                    LDSM_X4(bl[2 * p][0], bl[2 * p][1], bl[2 * p + 1][0], bl[2 * p + 1][1],
                            bL + ba);
                }
#pragma unroll
                for (int mt = 0; mt < 2; ++mt)
#pragma unroll
                    for (int nt = 0; nt < 4; ++nt) {
                        float* cc = acc[mt][g * 4 + nt];
                        MMA_BF16(cc[0], cc[1], cc[2], cc[3],
                                 ah[mt][0], ah[mt][1], ah[mt][2], ah[mt][3],
                                 bh[nt][0], bh[nt][1]);
                        MMA_BF16(cc[0], cc[1], cc[2], cc[3],
                                 ah[mt][0], ah[mt][1], ah[mt][2], ah[mt][3],
                                 bl[nt][0], bl[nt][1]);
                        MMA_BF16(cc[0], cc[1], cc[2], cc[3],
                                 al[mt][0], al[mt][1], al[mt][2], al[mt][3],
                                 bh[nt][0], bh[nt][1]);
                    }
            }
        }
        __syncthreads();
    }

    // epilogue
#pragma unroll
    for (int mt = 0; mt < 2; ++mt) {
        const int rbase = row0 + warp_m * 32 + mt * 16 + (lane >> 2);
#pragma unroll
        for (int nt = 0; nt < 8; ++nt) {
            const int cbase = col0 + warp_n * 64 + nt * 8 + (lane & 3) * 2;
            float v0 = acc[mt][nt][0], v1 = acc[mt][nt][1];
            float v2 = acc[mt][nt][2], v3 = acc[mt][nt][3];
            if (outH) {
                v0 *= scale; v1 *= scale; v2 *= scale; v3 *= scale;
                __nv_bfloat162 h01 = __float22bfloat162_rn(make_float2(v0, v1));
                __nv_bfloat162 h23 = __float22bfloat162_rn(make_float2(v2, v3));
                float2 f01 = __bfloat1622float2(h01);
                float2 f23 = __bfloat1622float2(h23);
                __nv_bfloat162 l01 = __float22bfloat162_rn(make_float2(v0 - f01.x, v1 - f01.y));
                __nv_bfloat162 l23 = __float22bfloat162_rn(make_float2(v2 - f23.x, v3 - f23.y));
                *reinterpret_cast<__nv_bfloat162*>(outH + (size_t)rbase * N + cbase) = h01;
                *reinterpret_cast<__nv_bfloat162*>(outH + (size_t)(rbase + 8) * N + cbase) = h23;
                *reinterpret_cast<__nv_bfloat162*>(outL + (size_t)rbase * N + cbase) = l01;
                *reinterpret_cast<__nv_bfloat162*>(outL + (size_t)(rbase + 8) * N + cbase) = l23;
            } else {
                if (bias) {
                    const float b0 = bias[cbase], b1 = bias[cbase + 1];
                    v0 += b0; v1 += b1; v2 += b0; v3 += b1;
                }
                float2 w0 = make_float2(v0, v1), w1 = make_float2(v2, v3);
                *reinterpret_cast<float2*>(C + (size_t)rbase * N + cbase) = w0;
                *reinterpret_cast<float2*>(C + (size_t)(rbase + 8) * N + cbase) = w1;
            }
        }
    }
}

// ---------------------------------------------------------------------------
// Tensor-core flash attention (bf16 split, mma.sync) — exact R5 structure.
// ---------------------------------------------------------------------------
#define FBQ 128
#define FBK 64
#define FROWB 144
#define FQ_TILE (FBQ * FROWB)             // 18432 B
#define FKV_TILE (FBK * FROWB)            // 9216 B
#define F_ST (2 * FQ_TILE)                // 36864
#define F_STAGE (4 * FKV_TILE)            // 36864
#define FLASH_SMEM (F_ST + 2 * F_STAGE)   // 110592 B

__global__ __launch_bounds__(256, 2) void flash_mma_kernel(
    const float* __restrict__ mask,
    const __nv_bfloat16* __restrict__ Qh, const __nv_bfloat16* __restrict__ Ql,
    const __nv_bfloat16* __restrict__ Kh, const __nv_bfloat16* __restrict__ Kl,
    const __nv_bfloat16* __restrict__ Vh, const __nv_bfloat16* __restrict__ Vl,
    __nv_bfloat16* __restrict__ Oh, __nv_bfloat16* __restrict__ Ol)
{
    extern __shared__ char smem[];
    const uint32_t sb = smem_u32(smem);

    const int tid  = threadIdx.x;
    const int wid  = tid >> 5;
    const int lane = tid & 31;
    const int q0 = blockIdx.x * FBQ;
    const int h  = blockIdx.y;
    const int b  = blockIdx.z;

    const size_t headoff = (size_t)b * Tq * INNERq + (size_t)h * DHq;
    const __nv_bfloat16* gQh = Qh + headoff;
    const __nv_bfloat16* gQl = Ql + headoff;
    const __nv_bfloat16* gKh = Kh + headoff;
    const __nv_bfloat16* gKl = Kl + headoff;
    const __nv_bfloat16* gVh = Vh + headoff;
    const __nv_bfloat16* gVl = Vl + headoff;
    const float* Mg = mask + (size_t)b * Tq * Tq;

    // ---- prologue: Q tiles (hi/lo) + KV stage 0 via cp.async ----
    {
#pragma unroll
        for (int t = 0; t < 8; ++t) {
            const int id = t * 256 + tid;
            const int tile = id >> 10;
            const int rem = id & 1023;
            const int row = rem >> 3;
            const int seg = rem & 7;
            const uint32_t s = sb + tile * FQ_TILE + row * FROWB + seg * 16;
            const __nv_bfloat16* g = (tile ? gQl : gQh) + (size_t)(q0 + row) * INNERq + seg * 8;
            CP_ASYNC16(s, g);
        }
#pragma unroll
        for (int t = 0; t < 8; ++t) {
            const int id = t * 256 + tid;
            const int tile = id >> 9;           // 0=Kh,1=Kl,2=Vh,3=Vl
            const int rem = id & 511;
            const int row = rem >> 3;
            const int seg = rem & 7;
            const uint32_t s = sb + F_ST + tile * FKV_TILE + row * FROWB + seg * 16;
            const __nv_bfloat16* base = (tile == 0) ? gKh : (tile == 1) ? gKl
                                       : (tile == 2) ? gVh : gVl;
            CP_ASYNC16(s, base + (size_t)row * INNERq + seg * 8);
        }
        CP_COMMIT();
    }

    float o[8][4];
#pragma unroll
    for (int t = 0; t < 8; ++t)
#pragma unroll
        for (int j = 0; j < 4; ++j) o[t][j] = 0.0f;
    float m0 = -1e30f, m1 = -1e30f, l0 = 0.0f, l1 = 0.0f;

    const int r0g = q0 + wid * 16 + (lane >> 2);
    const int quadcol = (lane & 3) * 2;

    const int chunks = Tq / FBK;   // 32
    for (int c = 0; c < chunks; ++c) {
        const int j0 = c * FBK;
        if (c + 1 < chunks) {
            const int jn = j0 + FBK;
            const uint32_t stn = sb + F_ST + ((c + 1) & 1) * F_STAGE;
#pragma unroll
            for (int t = 0; t < 8; ++t) {
                const int id = t * 256 + tid;
                const int tile = id >> 9;
                const int rem = id & 511;
                const int row = rem >> 3;
                const int seg = rem & 7;
                const uint32_t s = stn + tile * FKV_TILE + row * FROWB + seg * 16;
                const __nv_bfloat16* base = (tile == 0) ? gKh : (tile == 1) ? gKl
                                           : (tile == 2) ? gVh : gVl;
                CP_ASYNC16(s, base + (size_t)(jn + row) * INNERq + seg * 8);
            }
            CP_COMMIT();
            CP_WAIT1();
        } else {
            CP_WAIT0();
        }
        __syncthreads();

        const uint32_t st = sb + F_ST + (c & 1) * F_STAGE;
        const uint32_t kH = st;
        const uint32_t kL = st + FKV_TILE;
        const uint32_t vH = st + 2 * FKV_TILE;
        const uint32_t vL = st + 3 * FKV_TILE;

        // ---- S = Q K^T (split, 3 passes) ----
        float s[8][4];
#pragma unroll
        for (int t = 0; t < 8; ++t)
#pragma unroll
            for (int j = 0; j < 4; ++j) s[t][j] = 0.0f;

        const int brow_in = (lane & 7) + ((lane >> 4) << 3);
#pragma unroll
        for (int kk = 0; kk < 4; ++kk) {
            uint32_t qh4[4], ql4[4];
            const uint32_t qa = sb + (wid * 16 + (lane & 15)) * FROWB
                              + kk * 32 + (lane >> 4) * 16;
            LDSM_X4(qh4[0], qh4[1], qh4[2], qh4[3], qa);
            LDSM_X4(ql4[0], ql4[1], ql4[2], ql4[3], qa + FQ_TILE);

            const int bkb = kk * 32 + ((lane >> 3) & 1) * 16;
#pragma unroll
            for (int p = 0; p < 4; ++p) {
                uint32_t bh[2][2], bl[2][2];
                const uint32_t ba = (p * 16 + brow_in) * FROWB + bkb;
                LDSM_X4(bh[0][0], bh[0][1], bh[1][0], bh[1][1], kH + ba);
                LDSM_X4(bl[0][0], bl[0][1], bl[1][0], bl[1][1], kL + ba);
#pragma unroll
                for (int u = 0; u < 2; ++u) {
                    float* cc = s[2 * p + u];
                    MMA_BF16(cc[0], cc[1], cc[2], cc[3],
                             qh4[0], qh4[1], qh4[2], qh4[3], bh[u][0], bh[u][1]);
                    MMA_BF16(cc[0], cc[1], cc[2], cc[3],
                             ql4[0], ql4[1], ql4[2], ql4[3], bh[u][0], bh[u][1]);
                    MMA_BF16(cc[0], cc[1], cc[2], cc[3],
                             qh4[0], qh4[1], qh4[2], qh4[3], bl[u][0], bl[u][1]);
                }
            }
        }

        // ---- mask + online softmax ----
        const float* m0p = Mg + (size_t)r0g * Tq + j0 + quadcol;
        const float* m1p = m0p + 8 * Tq;
#pragma unroll
        for (int t = 0; t < 8; ++t) {
            float2 mv0 = *reinterpret_cast<const float2*>(m0p + t * 8);
            float2 mv1 = *reinterpret_cast<const float2*>(m1p + t * 8);
            s[t][0] += mv0.x; s[t][1] += mv0.y;
            s[t][2] += mv1.x; s[t][3] += mv1.y;
        }

        float mx0 = -1e30f, mx1 = -1e30f;
#pragma unroll
        for (int t = 0; t < 8; ++t) {
            mx0 = fmaxf(mx0, fmaxf(s[t][0], s[t][1]));
            mx1 = fmaxf(mx1, fmaxf(s[t][2], s[t][3]));
        }
        mx0 = fmaxf(mx0, __shfl_xor_sync(0xffffffffu, mx0, 1));
        mx0 = fmaxf(mx0, __shfl_xor_sync(0xffffffffu, mx0, 2));
        mx1 = fmaxf(mx1, __shfl_xor_sync(0xffffffffu, mx1, 1));
        mx1 = fmaxf(mx1, __shfl_xor_sync(0xffffffffu, mx1, 2));

        const float mn0 = fmaxf(m0, mx0);
        const float mn1 = fmaxf(m1, mx1);
        const float a0 = __expf(m0 - mn0);
        const float a1 = __expf(m1 - mn1);
        m0 = mn0; m1 = mn1;

        float sum0 = 0.0f, sum1 = 0.0f;
#pragma unroll
        for (int t = 0; t < 8; ++t) {
            s[t][0] = __expf(s[t][0] - mn0);
            s[t][1] = __expf(s[t][1] - mn0);
            s[t][2] = __expf(s[t][2] - mn1);
            s[t][3] = __expf(s[t][3] - mn1);
            sum0 += s[t][0] + s[t][1];
            sum1 += s[t][2] + s[t][3];
        }
        sum0 += __shfl_xor_sync(0xffffffffu, sum0, 1);
        sum0 += __shfl_xor_sync(0xffffffffu, sum0, 2);
        sum1 += __shfl_xor_sync(0xffffffffu, sum1, 1);
        sum1 += __shfl_xor_sync(0xffffffffu, sum1, 2);
        l0 = l0 * a0 + sum0;
        l1 = l1 * a1 + sum1;

#pragma unroll
        for (int t = 0; t < 8; ++t) {
            o[t][0] *= a0; o[t][1] *= a0;
            o[t][2] *= a1; o[t][3] *= a1;
        }

        // ---- P fragments (hi/lo) from S registers ----
        uint32_t pH[4][4], pL[4][4];
#pragma unroll
        for (int j = 0; j < 4; ++j) {
#pragma unroll
            for (int u = 0; u < 2; ++u) {
#pragma unroll
                for (int w = 0; w < 2; ++w) {
                    const float e0 = s[2 * j + w][2 * u + 0];
                    const float e1 = s[2 * j + w][2 * u + 1];
                    __nv_bfloat162 hh = __float22bfloat162_rn(make_float2(e0, e1));
                    float2 hf = __bfloat1622float2(hh);
                    __nv_bfloat162 ll = __float22bfloat162_rn(
                        make_float2(e0 - hf.x, e1 - hf.y));
                    pH[j][2 * w + u] = *reinterpret_cast<uint32_t*>(&hh);
                    pL[j][2 * w + u] = *reinterpret_cast<uint32_t*>(&ll);
                }
            }
        }

        // ---- O += P V (split, 3 passes) ----
#pragma unroll
        for (int j = 0; j < 4; ++j) {
#pragma unroll
            for (int p = 0; p < 4; ++p) {
                uint32_t vh4[2][2], vl4[2][2];
                const uint32_t va = (j * 16 + (lane & 15)) * FROWB
                                  + p * 32 + (lane >> 4) * 16;
                LDSM_X4_T(vh4[0][0], vh4[0][1], vh4[1][0], vh4[1][1], vH + va);
                LDSM_X4_T(vl4[0][0], vl4[0][1], vl4[1][0], vl4[1][1], vL + va);
#pragma unroll
                for (int u = 0; u < 2; ++u) {
                    float* cc = o[2 * p + u];
                    MMA_BF16(cc[0], cc[1], cc[2], cc[3],
                             pH[j][0], pH[j][1], pH[j][2], pH[j][3],
                             vh4[u][0], vh4[u][1]);
                    MMA_BF16(cc[0], cc[1], cc[2], cc[3],
                             pL[j][0], pL[j][1], pL[j][2], pL[j][3],
                             vh4[u][0], vh4[u][1]);
                    MMA_BF16(cc[0], cc[1], cc[2], cc[3],
                             pH[j][0], pH[j][1], pH[j][2], pH[j][3],
                             vl4[u][0], vl4[u][1]);
                }
            }
        }
        __syncthreads();
    }

    // ---- epilogue: normalize, split to bf16 hi/lo, store ----
    const float inv0 = 1.0f / l0;
    const float inv1 = 1.0f / l1;
    const size_t row0o = ((size_t)b * Tq + r0g) * INNERq + (size_t)h * DHq;
    const size_t row1o = row0o + 8 * INNERq;
#pragma unroll
    for (int t = 0; t < 8; ++t) {
        const int col = t * 8 + quadcol;
        float v0 = o[t][0] * inv0, v1 = o[t][1] * inv0;
        float v2 = o[t][2] * inv1, v3 = o[t][3] * inv1;
        __nv_bfloat162 h01 = __float22bfloat162_rn(make_float2(v0, v1));
        __nv_bfloat162 h23 = __float22bfloat162_rn(make_float2(v2, v3));
        float2 f01 = __bfloat1622float2(h01);
        float2 f23 = __bfloat1622float2(h23);
        __nv_bfloat162 l01 = __float22bfloat162_rn(make_float2(v0 - f01.x, v1 - f01.y));
        __nv_bfloat162 l23 = __float22bfloat162_rn(make_float2(v2 - f23.x, v3 - f23.y));
        *reinterpret_cast<__nv_bfloat162*>(Oh + row0o + col) = h01;
        *reinterpret_cast<__nv_bfloat162*>(Ol + row0o + col) = l01;
        *reinterpret_cast<__nv_bfloat162*>(Oh + row1o + col) = h23;
        *reinterpret_cast<__nv_bfloat162*>(Ol + row1o + col) = l23;
    }
}

// ---------------------------------------------------------------------------
// kernel_launch
// Inputs: x, attention_mask, Wq, Wk, Wv, Wo, bo
// ---------------------------------------------------------------------------
extern "C" void kernel_launch(void* const* d_in, const int* in_sizes, int n_in,
                              void* d_out, int out_size)
{
    (void)in_sizes; (void)n_in; (void)out_size;
    const float* x    = (const float*)d_in[0];
    const float* mask = (const float*)d_in[1];
    const float* Wq   = (const float*)d_in[2];
    const float* Wk   = (const float*)d_in[3];
    const float* Wv   = (const float*)d_in[4];
    const float* Wo   = (const float*)d_in[5];
    const float* bo   = (const float*)d_in[6];
    float* out = (float*)d_out;

    __nv_bfloat16 *xh, *xl, *ah, *al, *qkv, *w8;
    cudaGetSymbolAddress((void**)&xh, s_xh);
    cudaGetSymbolAddress((void**)&xl, s_xl);
    cudaGetSymbolAddress((void**)&ah, s_ah);
    cudaGetSymbolAddress((void**)&al, s_al);
    cudaGetSymbolAddress((void**)&qkv, s_qkv);
    cudaGetSymbolAddress((void**)&w8, s_w8);

    const int M = Bq * Tq;     // 8192
    const int N = INNERq;      // 1024
    const int K = Dq;          // 1024
    const int nx = M * K;

    // conversions
    split_kernel<<<nx / (256 * 4), 256>>>(x, xh, xl, nx);
    dim3 tGrid(N / 32, K / 32), tBlk(32, 8);
    tsplit_kernel<<<tGrid, tBlk>>>(Wq, w8 + 0 * WPLANE, w8 + 1 * WPLANE, K, N);
    tsplit_kernel<<<tGrid, tBlk>>>(Wk, w8 + 2 * WPLANE, w8 + 3 * WPLANE, K, N);
    tsplit_kernel<<<tGrid, tBlk>>>(Wv, w8 + 4 * WPLANE, w8 + 5 * WPLANE, K, N);
    tsplit_kernel<<<tGrid, tBlk>>>(Wo, w8 + 6 * WPLANE, w8 + 7 * WPLANE, K, N);

    // Q,K,V projections in ONE launch (grid.z selects weight/output planes)
    cudaFuncSetAttribute(gemm_mma_kernel,
                         cudaFuncAttributeMaxDynamicSharedMemorySize, GEMM_SMEM);
    dim3 qkvGrid(N / GBN, M / GBM, 3);   // (8, 64, 3)
    gemm_mma_kernel<<<qkvGrid, 256, GEMM_SMEM>>>(xh, xl, w8, qkv,
        nullptr, nullptr, nullptr, nullptr, nullptr, nullptr, 1.0f, M, N, K);

    // flash attention (tensor cores) -> bf16 hi/lo
    cudaFuncSetAttribute(flash_mma_kernel,
                         cudaFuncAttributeMaxDynamicSharedMemorySize, FLASH_SMEM);
    dim3 fGrid(Tq / FBQ, Hq, Bq);   // (16, 16, 4)
    flash_mma_kernel<<<fGrid, 256, FLASH_SMEM>>>(mask,
        qkv + 0 * KVPLANE, qkv + 1 * KVPLANE,
        qkv + 2 * KVPLANE, qkv + 3 * KVPLANE,
        qkv + 4 * KVPLANE, qkv + 5 * KVPLANE, ah, al);

    // output projection (fp32 + bias)
    dim3 oGrid(N / GBN, M / GBM, 1);
    gemm_mma_kernel<<<oGrid, 256, GEMM_SMEM>>>(ah, al, nullptr, nullptr,
        w8 + 6 * WPLANE, w8 + 7 * WPLANE, out, bo, nullptr, nullptr, 1.0f, M, Dq, INNERq);
}

// round 8
// speedup vs baseline: 1.4026x; 1.2445x over previous
#include <cuda_runtime.h>
#include <cuda_bf16.h>
#include <cstdint>
#include <cstddef>

// ---------------------------------------------------------------------------
// Problem constants
// ---------------------------------------------------------------------------
#define Bq   4
#define Tq   2048
#define Dq   1024
#define Hq   16
#define DHq  64
#define INNERq 1024
#define SCALEq 0.125f     // 64^-0.5

// Blocked-layout sizes
#define KCq 32                                   // K chunks (1024/32)
#define ABLK 20480                               // one (128x32) hi|lo pair block
#define WPAIR_BYTES ((size_t)8 * 32 * ABLK)      // one weight, blocked
#define XPAIR_BYTES ((size_t)64 * 32 * ABLK)     // x / attn-out, blocked
#define QBLK 36864                               // Q (128x64) hi|lo block
#define KVBLK 18432                              // K or V (64x64) hi|lo block
#define QB_BYTES ((size_t)Bq * Hq * 16 * QBLK)
#define KP_BYTES ((size_t)Bq * Hq * 32 * KVBLK)
#define MBLK 16384                               // permuted bf16 mask tile (128x64)
#define MP_BYTES ((size_t)Bq * 16 * 32 * MBLK)

// ---------------------------------------------------------------------------
// Scratch (device globals; allocation is forbidden)
// ---------------------------------------------------------------------------
__device__ __align__(128) unsigned char g_xpair[XPAIR_BYTES];
__device__ __align__(128) unsigned char g_apair[XPAIR_BYTES];
__device__ __align__(128) unsigned char g_w[4 * WPAIR_BYTES];
__device__ __align__(128) unsigned char g_qb[QB_BYTES];
__device__ __align__(128) unsigned char g_kp[KP_BYTES];
__device__ __align__(128) unsigned char g_vp[KP_BYTES];
__device__ __align__(128) unsigned char g_maskp[MP_BYTES];

// ---------------------------------------------------------------------------
// PTX helpers
// ---------------------------------------------------------------------------
__device__ __forceinline__ uint32_t smem_u32(const void* p) {
    uint32_t a;
    asm("{ .reg .u64 t; cvta.to.shared.u64 t, %1; cvt.u32.u64 %0, t; }" : "=r"(a) : "l"(p));
    return a;
}

#define MBAR_INIT(mbar, cnt) \
    asm volatile("mbarrier.init.shared.b64 [%0], %1;" :: "r"((uint32_t)(mbar)), "r"((uint32_t)(cnt)) : "memory")
#define MBAR_EXPECT_TX(mbar, bytes) \
    asm volatile("mbarrier.arrive.expect_tx.shared.b64 _, [%0], %1;" \
                 :: "r"((uint32_t)(mbar)), "r"((uint32_t)(bytes)) : "memory")
#define CP_BULK(smem_dst, gsrc, bytes, mbar) \
    asm volatile("cp.async.bulk.shared::cluster.global.mbarrier::complete_tx::bytes [%0], [%1], %2, [%3];" \
                 :: "r"((uint32_t)(smem_dst)), "l"(gsrc), "r"((uint32_t)(bytes)), \
                    "r"((uint32_t)(mbar)) : "memory")

__device__ __forceinline__ void mbar_wait(uint32_t mbar, uint32_t parity) {
    asm volatile(
        "{\n\t.reg .pred P;\n\t"
        "WAIT_%=:\n\t"
        "mbarrier.try_wait.parity.acquire.cta.shared::cta.b64 P, [%0], %1, 0x989680;\n\t"
        "@P bra DONE_%=;\n\t"
        "bra WAIT_%=;\n\t"
        "DONE_%=:\n\t}"
        :: "r"(mbar), "r"(parity) : "memory");
}

#define LDSM_X4(r0, r1, r2, r3, addr) \
    asm volatile("ldmatrix.sync.aligned.m8n8.x4.shared.b16 {%0,%1,%2,%3}, [%4];" \
                 : "=r"(r0), "=r"(r1), "=r"(r2), "=r"(r3) : "r"(addr))

#define LDSM_X4_T(r0, r1, r2, r3, addr) \
    asm volatile("ldmatrix.sync.aligned.m8n8.x4.trans.shared.b16 {%0,%1,%2,%3}, [%4];" \
                 : "=r"(r0), "=r"(r1), "=r"(r2), "=r"(r3) : "r"(addr))

#define MMA_BF16(c0, c1, c2, c3, a0, a1, a2, a3, b0, b1) \
    asm volatile("mma.sync.aligned.m16n8k16.row.col.f32.bf16.bf16.f32 " \
                 "{%0,%1,%2,%3}, {%4,%5,%6,%7}, {%8,%9}, {%0,%1,%2,%3};" \
                 : "+f"(c0), "+f"(c1), "+f"(c2), "+f"(c3) \
                 : "r"(a0), "r"(a1), "r"(a2), "r"(a3), "r"(b0), "r"(b1))

// split fp32 pair -> bf16 hi (4B) + lo (4B) at byte pointers
__device__ __forceinline__ void store_split_pair(unsigned char* hi, unsigned char* lo,
                                                 float v0, float v1) {
    __nv_bfloat162 hh = __float22bfloat162_rn(make_float2(v0, v1));
    float2 hf = __bfloat1622float2(hh);
    __nv_bfloat162 ll = __float22bfloat162_rn(make_float2(v0 - hf.x, v1 - hf.y));
    *reinterpret_cast<uint32_t*>(hi) = *reinterpret_cast<uint32_t*>(&hh);
    *reinterpret_cast<uint32_t*>(lo) = *reinterpret_cast<uint32_t*>(&ll);
}

// ---------------------------------------------------------------------------
// x[8192,1024] fp32 -> blocked hi/lo pair layout
// block (row>>7, col>>5): 20480B = [hi 128x80B | lo 128x80B]
// ---------------------------------------------------------------------------
__global__ __launch_bounds__(256) void split_kernel(
    const float* __restrict__ in, unsigned char* __restrict__ out)
{
    const int i = (blockIdx.x * 256 + threadIdx.x) * 4;
    float4 v = *reinterpret_cast<const float4*>(in + i);
    const int row = i >> 10, col = i & 1023;
    unsigned char* base = out + ((size_t)((row >> 7) * KCq + (col >> 5))) * ABLK
                        + (row & 127) * 80 + (col & 31) * 2;
    __nv_bfloat16 h0 = __float2bfloat16(v.x), h1 = __float2bfloat16(v.y);
    __nv_bfloat16 h2 = __float2bfloat16(v.z), h3 = __float2bfloat16(v.w);
    __nv_bfloat162 H0; H0.x = h0; H0.y = h1;
    __nv_bfloat162 H1; H1.x = h2; H1.y = h3;
    uint2 hw = make_uint2(*reinterpret_cast<uint32_t*>(&H0), *reinterpret_cast<uint32_t*>(&H1));
    *reinterpret_cast<uint2*>(base) = hw;
    __nv_bfloat162 L0, L1;
    L0.x = __float2bfloat16(v.x - __bfloat162float(h0));
    L0.y = __float2bfloat16(v.y - __bfloat162float(h1));
    L1.x = __float2bfloat16(v.z - __bfloat162float(h2));
    L1.y = __float2bfloat16(v.w - __bfloat162float(h3));
    uint2 lw = make_uint2(*reinterpret_cast<uint32_t*>(&L0), *reinterpret_cast<uint32_t*>(&L1));
    *reinterpret_cast<uint2*>(base + 10240) = lw;
}

// ---------------------------------------------------------------------------
// W[K,N] fp32 -> transposed blocked hi/lo pair layout (Wt[n][k])
// ---------------------------------------------------------------------------
__global__ __launch_bounds__(256) void tsplit_kernel(
    const float* __restrict__ W, unsigned char* __restrict__ out, int K, int N)
{
    __shared__ float t[32][33];
    const int tx = threadIdx.x, ty = threadIdx.y;
    const int bx = blockIdx.x, by = blockIdx.y;
#pragma unroll
    for (int j = 0; j < 32; j += 8)
        t[ty + j][tx] = W[(size_t)(by * 32 + ty + j) * N + bx * 32 + tx];
    __syncthreads();
#pragma unroll
    for (int j = 0; j < 32; j += 8) {
        float v = t[tx][ty + j];
        const int n = bx * 32 + ty + j;
        const int k = by * 32 + tx;
        unsigned char* base = out + ((size_t)((n >> 7) * KCq + (k >> 5))) * ABLK
                            + (n & 127) * 80 + (k & 31) * 2;
        __nv_bfloat16 h = __float2bfloat16(v);
        *reinterpret_cast<__nv_bfloat16*>(base) = h;
        *reinterpret_cast<__nv_bfloat16*>(base + 10240) =
            __float2bfloat16(v - __bfloat162float(h));
    }
}

// ---------------------------------------------------------------------------
// Mask permute: fp32 [B,1,T,T] -> bf16, consumer-ordered per (b,qtile,chunk,tid)
// ---------------------------------------------------------------------------
__global__ __launch_bounds__(256) void mask_permute(
    const float* __restrict__ mask, unsigned char* __restrict__ out)
{
    __shared__ float tile[128 * 64];
    const int b = blockIdx.z, qt = blockIdx.y, ch = blockIdx.x;
    const int tid = threadIdx.x;
    const float* src = mask + ((size_t)b * Tq + qt * 128) * Tq + ch * 64;
    for (int i = tid; i < 2048; i += 256) {
        const int row = i >> 4, c4 = (i & 15) * 4;
        float4 v = *reinterpret_cast<const float4*>(src + (size_t)row * Tq + c4);
        tile[row * 64 + c4 + 0] = v.x;
        tile[row * 64 + c4 + 1] = v.y;
        tile[row * 64 + c4 + 2] = v.z;
        tile[row * 64 + c4 + 3] = v.w;
    }
    __syncthreads();
    const int wid = tid >> 5, lane = tid & 31;
    const int r0 = wid * 16 + (lane >> 2);
    const int cb = (lane & 3) * 2;
    uint32_t outv[16];
#pragma unroll
    for (int t = 0; t < 8; ++t)
#pragma unroll
        for (int u = 0; u < 2; ++u) {
            const int row = r0 + u * 8;
            const int c = t * 8 + cb;
            __nv_bfloat162 p = __float22bfloat162_rn(
                make_float2(tile[row * 64 + c], tile[row * 64 + c + 1]));
            outv[t * 2 + u] = *reinterpret_cast<uint32_t*>(&p);
        }
    uint4* dst = reinterpret_cast<uint4*>(
        out + ((size_t)((b * 16 + qt) * 32 + ch)) * MBLK + tid * 64);
#pragma unroll
    for (int i = 0; i < 4; ++i)
        dst[i] = make_uint4(outv[4 * i], outv[4 * i + 1], outv[4 * i + 2], outv[4 * i + 3]);
}

// ---------------------------------------------------------------------------
// bulk-copy GEMM: C = (Ah+Al) @ (Bh+Bl)^T over blocked pair layouts.
// QKV mode (C==null): z=blockIdx.z picks weight; epilogue -> blocked Q/K/V.
// O mode: fp32 C + bias.
// ---------------------------------------------------------------------------
#define GBM 128
#define GBN 128
#define GBK 32
#define TILEB 10240
#define STAGEB (4 * TILEB)           // Ah Al Bh Bl
#define GEMM_SMEM (2 * STAGEB + 16)  // + 2 mbarriers

__device__ __forceinline__ void store_qkv(unsigned char* dst, int z, int row, int col,
                                          float v0, float v1) {
    const int b = row >> 11, tok = row & 2047;
    const int h = col >> 6, dh = col & 63;
    size_t off, lostride;
    if (z == 0) {
        off = ((size_t)((b * Hq + h) * 16 + (tok >> 7))) * QBLK
            + (size_t)(tok & 127) * 144 + dh * 2;
        lostride = 18432;
    } else {
        off = ((size_t)((b * Hq + h) * 32 + (tok >> 6))) * KVBLK
            + (size_t)(tok & 63) * 144 + dh * 2;
        lostride = 9216;
    }
    store_split_pair(dst + off, dst + off + lostride, v0, v1);
}

__global__ __launch_bounds__(256, 2) void gemm_bulk_kernel(
    const unsigned char* __restrict__ Apair, const unsigned char* __restrict__ Wb,
    unsigned char* __restrict__ qb, unsigned char* __restrict__ kp,
    unsigned char* __restrict__ vp,
    float* __restrict__ C, const float* __restrict__ bias,
    int M, int N, int K)
{
    extern __shared__ char smem[];
    const uint32_t sb = smem_u32(smem);
    const uint32_t mb0 = sb + 2 * STAGEB;
    const uint32_t mb1 = mb0 + 8;

    const int tid = threadIdx.x;
    const int wid = tid >> 5;
    const int lane = tid & 31;
    const int warp_m = wid >> 1;
    const int warp_n = wid & 1;
    const int row0 = blockIdx.y * GBM;
    const int col0 = blockIdx.x * GBN;
    const int z = blockIdx.z;
    const int KC = K / GBK;

    const unsigned char* Asrc = Apair + ((size_t)blockIdx.y * KC) * ABLK;
    const unsigned char* Bsrc = (C == nullptr ? Wb + (size_t)z * WPAIR_BYTES : Wb)
                              + ((size_t)blockIdx.x * KC) * ABLK;

    if (tid == 0) { MBAR_INIT(mb0, 1); MBAR_INIT(mb1, 1); }
    __syncthreads();

    if (tid == 0) {
        MBAR_EXPECT_TX(mb0, STAGEB);
        CP_BULK(sb, Asrc, 2 * TILEB, mb0);
        CP_BULK(sb + 2 * TILEB, Bsrc, 2 * TILEB, mb0);
    }

    float acc[2][8][4];
#pragma unroll
    for (int i = 0; i < 2; ++i)
#pragma unroll
        for (int j = 0; j < 8; ++j)
#pragma unroll
            for (int q = 0; q < 4; ++q) acc[i][j][q] = 0.0f;

    for (int c = 0; c < KC; ++c) {
        if (c + 1 < KC && tid == 0) {
            const uint32_t stn = sb + ((c + 1) & 1) * STAGEB;
            const uint32_t mbn = ((c + 1) & 1) ? mb1 : mb0;
            MBAR_EXPECT_TX(mbn, STAGEB);
            CP_BULK(stn, Asrc + (size_t)(c + 1) * ABLK, 2 * TILEB, mbn);
            CP_BULK(stn + 2 * TILEB, Bsrc + (size_t)(c + 1) * ABLK, 2 * TILEB, mbn);
        }
        mbar_wait((c & 1) ? mb1 : mb0, (c >> 1) & 1);

        const uint32_t st = sb + (c & 1) * STAGEB;
        const uint32_t aH = st;
        const uint32_t aL = st + TILEB;
        const uint32_t bH = st + 2 * TILEB;
        const uint32_t bL = st + 3 * TILEB;

#pragma unroll
        for (int kst = 0; kst < 2; ++kst) {
            const int kb = kst * 32 + (lane >> 4) * 16;

            uint32_t ah[2][4], al[2][4];
#pragma unroll
            for (int mt = 0; mt < 2; ++mt) {
                const int arow = warp_m * 32 + mt * 16 + (lane & 15);
                LDSM_X4(ah[mt][0], ah[mt][1], ah[mt][2], ah[mt][3], aH + arow * 80 + kb);
                LDSM_X4(al[mt][0], al[mt][1], al[mt][2], al[mt][3], aL + arow * 80 + kb);
            }

#pragma unroll
            for (int g = 0; g < 2; ++g) {
                uint32_t bh[4][2], bl[4][2];
                const int brow_in = (lane & 7) + ((lane >> 4) << 3);
                const int bkb = kst * 32 + ((lane >> 3) & 1) * 16;
#pragma unroll
                for (int p = 0; p < 2; ++p) {
                    const int nb = warp_n * 64 + g * 32 + p * 16;
                    const uint32_t ba = (nb + brow_in) * 80 + bkb;
                    LDSM_X4(bh[2 * p][0], bh[2 * p][1], bh[2 * p + 1][0], bh[2 * p + 1][1],
                            bH + ba);
                    LDSM_X4(bl[2 * p][0], bl[2 * p][1], bl[2 * p + 1][0], bl[2 * p + 1][1],
                            bL + ba);
                }
#pragma unroll
                for (int mt = 0; mt < 2; ++mt)
#pragma unroll
                    for (int nt = 0; nt < 4; ++nt) {
                        float* cc = acc[mt][g * 4 + nt];
                        MMA_BF16(cc[0], cc[1], cc[2], cc[3],
                                 ah[mt][0], ah[mt][1], ah[mt][2], ah[mt][3],
                                 bh[nt][0], bh[nt][1]);
                        MMA_BF16(cc[0], cc[1], cc[2], cc[3],
                                 ah[mt][0], ah[mt][1], ah[mt][2], ah[mt][3],
                                 bl[nt][0], bl[nt][1]);
                        MMA_BF16(cc[0], cc[1], cc[2], cc[3],
                                 al[mt][0], al[mt][1], al[mt][2], al[mt][3],
                                 bh[nt][0], bh[nt][1]);
                    }
            }
        }
        __syncthreads();
    }

    // epilogue
    if (C != nullptr) {
#pragma unroll
        for (int mt = 0; mt < 2; ++mt) {
            const int rbase = row0 + warp_m * 32 + mt * 16 + (lane >> 2);
#pragma unroll
            for (int nt = 0; nt < 8; ++nt) {
                const int cbase = col0 + warp_n * 64 + nt * 8 + (lane & 3) * 2;
                float v0 = acc[mt][nt][0], v1 = acc[mt][nt][1];
                float v2 = acc[mt][nt][2], v3 = acc[mt][nt][3];
                const float b0 = bias[cbase], b1 = bias[cbase + 1];
                v0 += b0; v1 += b1; v2 += b0; v3 += b1;
                *reinterpret_cast<float2*>(C + (size_t)rbase * N + cbase) = make_float2(v0, v1);
                *reinterpret_cast<float2*>(C + (size_t)(rbase + 8) * N + cbase) = make_float2(v2, v3);
            }
        }
    } else {
        const float scale = (z == 0) ? SCALEq : 1.0f;
        unsigned char* dst = (z == 0) ? qb : (z == 1) ? kp : vp;
#pragma unroll
        for (int mt = 0; mt < 2; ++mt) {
            const int rbase = row0 + warp_m * 32 + mt * 16 + (lane >> 2);
#pragma unroll
            for (int nt = 0; nt < 8; ++nt) {
                const int cbase = col0 + warp_n * 64 + nt * 8 + (lane & 3) * 2;
                store_qkv(dst, z, rbase, cbase,
                          acc[mt][nt][0] * scale, acc[mt][nt][1] * scale);
                store_qkv(dst, z, rbase + 8, cbase,
                          acc[mt][nt][2] * scale, acc[mt][nt][3] * scale);
            }
        }
    }
}

// ---------------------------------------------------------------------------
// Tensor-core flash attention, bulk-copy fed.
// ---------------------------------------------------------------------------
#define FBQ 128
#define FBK 64
#define FROWB 144
#define FQ_TILE (FBQ * FROWB)               // 18432
#define FKV_TILE (FBK * FROWB)              // 9216
#define F_ST (2 * FQ_TILE)                  // 36864
#define F_STAGE (4 * FKV_TILE)              // 36864
#define FLASH_SMEM (F_ST + 2 * F_STAGE + 32)

__global__ __launch_bounds__(256, 2) void flash_mma_kernel(
    const unsigned char* __restrict__ maskp,
    const unsigned char* __restrict__ qb,
    const unsigned char* __restrict__ kp,
    const unsigned char* __restrict__ vp,
    unsigned char* __restrict__ apair)
{
    extern __shared__ char smem[];
    const uint32_t sb = smem_u32(smem);
    const uint32_t mbQ = sb + F_ST + 2 * F_STAGE;
    const uint32_t mbK0 = mbQ + 8;
    const uint32_t mbK1 = mbQ + 16;

    const int tid  = threadIdx.x;
    const int wid  = tid >> 5;
    const int lane = tid & 31;
    const int qt = blockIdx.x;
    const int h  = blockIdx.y;
    const int b  = blockIdx.z;

    const unsigned char* qsrc = qb + ((size_t)((b * Hq + h) * 16 + qt)) * QBLK;
    const unsigned char* kbase = kp + ((size_t)((b * Hq + h) * 32)) * KVBLK;
    const unsigned char* vbase = vp + ((size_t)((b * Hq + h) * 32)) * KVBLK;
    const unsigned char* mbase = maskp + ((size_t)((b * 16 + qt) * 32)) * MBLK + tid * 64;

    if (tid == 0) { MBAR_INIT(mbQ, 1); MBAR_INIT(mbK0, 1); MBAR_INIT(mbK1, 1); }
    __syncthreads();

    if (tid == 0) {
        MBAR_EXPECT_TX(mbQ, 2 * FQ_TILE);
        CP_BULK(sb, qsrc, 2 * FQ_TILE, mbQ);
        MBAR_EXPECT_TX(mbK0, F_STAGE);
        CP_BULK(sb + F_ST, kbase, KVBLK, mbK0);
        CP_BULK(sb + F_ST + KVBLK, vbase, KVBLK, mbK0);
    }

    float o[8][4];
#pragma unroll
    for (int t = 0; t < 8; ++t)
#pragma unroll
        for (int j = 0; j < 4; ++j) o[t][j] = 0.0f;
    float m0 = -1e30f, m1 = -1e30f, l0 = 0.0f, l1 = 0.0f;

    const int r0g = qt * FBQ + wid * 16 + (lane >> 2);
    const int quadcol = (lane & 3) * 2;

    mbar_wait(mbQ, 0);

    const int chunks = Tq / FBK;   // 32
    for (int c = 0; c < chunks; ++c) {
        if (c + 1 < chunks && tid == 0) {
            const uint32_t stn = sb + F_ST + ((c + 1) & 1) * F_STAGE;
            const uint32_t mbn = ((c + 1) & 1) ? mbK1 : mbK0;
            MBAR_EXPECT_TX(mbn, F_STAGE);
            CP_BULK(stn, kbase + (size_t)(c + 1) * KVBLK, KVBLK, mbn);
            CP_BULK(stn + KVBLK, vbase + (size_t)(c + 1) * KVBLK, KVBLK, mbn);
        }
        mbar_wait((c & 1) ? mbK1 : mbK0, (c >> 1) & 1);

        const uint32_t st = sb + F_ST + (c & 1) * F_STAGE;
        const uint32_t kH = st;
        const uint32_t kL = st + FKV_TILE;
        const uint32_t vH = st + 2 * FKV_TILE;
        const uint32_t vL = st + 3 * FKV_TILE;

        // ---- S = Q K^T (split, 3 passes) ----
        float s[8][4];
#pragma unroll
        for (int t = 0; t < 8; ++t)
#pragma unroll
            for (int j = 0; j < 4; ++j) s[t][j] = 0.0f;

        const int brow_in = (lane & 7) + ((lane >> 4) << 3);
#pragma unroll
        for (int kk = 0; kk < 4; ++kk) {
            uint32_t qh4[4], ql4[4];
            const uint32_t qa = sb + (wid * 16 + (lane & 15)) * FROWB
                              + kk * 32 + (lane >> 4) * 16;
            LDSM_X4(qh4[0], qh4[1], qh4[2], qh4[3], qa);
            LDSM_X4(ql4[0], ql4[1], ql4[2], ql4[3], qa + FQ_TILE);

            const int bkb = kk * 32 + ((lane >> 3) & 1) * 16;
#pragma unroll
            for (int p = 0; p < 4; ++p) {
                uint32_t bh[2][2], bl[2][2];
                const uint32_t ba = (p * 16 + brow_in) * FROWB + bkb;
                LDSM_X4(bh[0][0], bh[0][1], bh[1][0], bh[1][1], kH + ba);
                LDSM_X4(bl[0][0], bl[0][1], bl[1][0], bl[1][1], kL + ba);
#pragma unroll
                for (int u = 0; u < 2; ++u) {
                    float* cc = s[2 * p + u];
                    MMA_BF16(cc[0], cc[1], cc[2], cc[3],
                             qh4[0], qh4[1], qh4[2], qh4[3], bh[u][0], bh[u][1]);
                    MMA_BF16(cc[0], cc[1], cc[2], cc[3],
                             ql4[0], ql4[1], ql4[2], ql4[3], bh[u][0], bh[u][1]);
                    MMA_BF16(cc[0], cc[1], cc[2], cc[3],
                             qh4[0], qh4[1], qh4[2], qh4[3], bl[u][0], bl[u][1]);
                }
            }
        }

        // ---- mask (permuted bf16, 4x LDG.128) + online softmax ----
        {
            const uint4* mp = reinterpret_cast<const uint4*>(mbase + (size_t)c * MBLK);
            uint32_t mu[16];
#pragma unroll
            for (int i = 0; i < 4; ++i) {
                uint4 q = mp[i];
                mu[4 * i + 0] = q.x; mu[4 * i + 1] = q.y;
                mu[4 * i + 2] = q.z; mu[4 * i + 3] = q.w;
            }
#pragma unroll
            for (int t = 0; t < 8; ++t) {
                float2 lo2 = __bfloat1622float2(
                    *reinterpret_cast<__nv_bfloat162*>(&mu[2 * t]));
                float2 hi2 = __bfloat1622float2(
                    *reinterpret_cast<__nv_bfloat162*>(&mu[2 * t + 1]));
                s[t][0] += lo2.x; s[t][1] += lo2.y;
                s[t][2] += hi2.x; s[t][3] += hi2.y;
            }
        }

        float mx0 = -1e30f, mx1 = -1e30f;
#pragma unroll
        for (int t = 0; t < 8; ++t) {
            mx0 = fmaxf(mx0, fmaxf(s[t][0], s[t][1]));
            mx1 = fmaxf(mx1, fmaxf(s[t][2], s[t][3]));
        }
        mx0 = fmaxf(mx0, __shfl_xor_sync(0xffffffffu, mx0, 1));
        mx0 = fmaxf(mx0, __shfl_xor_sync(0xffffffffu, mx0, 2));
        mx1 = fmaxf(mx1, __shfl_xor_sync(0xffffffffu, mx1, 1));
        mx1 = fmaxf(mx1, __shfl_xor_sync(0xffffffffu, mx1, 2));

        const float mn0 = fmaxf(m0, mx0);
        const float mn1 = fmaxf(m1, mx1);
        const float a0 = __expf(m0 - mn0);
        const float a1 = __expf(m1 - mn1);
        m0 = mn0; m1 = mn1;

        float sum0 = 0.0f, sum1 = 0.0f;
#pragma unroll
        for (int t = 0; t < 8; ++t) {
            s[t][0] = __expf(s[t][0] - mn0);
            s[t][1] = __expf(s[t][1] - mn0);
            s[t][2] = __expf(s[t][2] - mn1);
            s[t][3] = __expf(s[t][3] - mn1);
            sum0 += s[t][0] + s[t][1];
            sum1 += s[t][2] + s[t][3];
        }
        sum0 += __shfl_xor_sync(0xffffffffu, sum0, 1);
        sum0 += __shfl_xor_sync(0xffffffffu, sum0, 2);
        sum1 += __shfl_xor_sync(0xffffffffu, sum1, 1);
        sum1 += __shfl_xor_sync(0xffffffffu, sum1, 2);
        l0 = l0 * a0 + sum0;
        l1 = l1 * a1 + sum1;

#pragma unroll
        for (int t = 0; t < 8; ++t) {
            o[t][0] *= a0; o[t][1] *= a0;
            o[t][2] *= a1; o[t][3] *= a1;
        }

        // ---- P fragments (hi/lo) from S registers ----
        uint32_t pH[4][4], pL[4][4];
#pragma unroll
        for (int j = 0; j < 4; ++j) {
#pragma unroll
            for (int u = 0; u < 2; ++u) {
#pragma unroll
                for (int w = 0; w < 2; ++w) {
                    const float e0 = s[2 * j + w][2 * u + 0];
                    const float e1 = s[2 * j + w][2 * u + 1];
                    __nv_bfloat162 hh = __float22bfloat162_rn(make_float2(e0, e1));
                    float2 hf = __bfloat1622float2(hh);
                    __nv_bfloat162 ll = __float22bfloat162_rn(
                        make_float2(e0 - hf.x, e1 - hf.y));
                    pH[j][2 * w + u] = *reinterpret_cast<uint32_t*>(&hh);
                    pL[j][2 * w + u] = *reinterpret_cast<uint32_t*>(&ll);
                }
            }
        }

        // ---- O += P V (split, 3 passes) ----
#pragma unroll
        for (int j = 0; j < 4; ++j) {
#pragma unroll
            for (int p = 0; p < 4; ++p) {
                uint32_t vh4[2][2], vl4[2][2];
                const uint32_t va = (j * 16 + (lane & 15)) * FROWB
                                  + p * 32 + (lane >> 4) * 16;
                LDSM_X4_T(vh4[0][0], vh4[0][1], vh4[1][0], vh4[1][1], vH + va);
                LDSM_X4_T(vl4[0][0], vl4[0][1], vl4[1][0], vl4[1][1], vL + va);
#pragma unroll
                for (int u = 0; u < 2; ++u) {
                    float* cc = o[2 * p + u];
                    MMA_BF16(cc[0], cc[1], cc[2], cc[3],
                             pH[j][0], pH[j][1], pH[j][2], pH[j][3],
                             vh4[u][0], vh4[u][1]);
                    MMA_BF16(cc[0], cc[1], cc[2], cc[3],
                             pL[j][0], pL[j][1], pL[j][2], pL[j][3],
                             vh4[u][0], vh4[u][1]);
                    MMA_BF16(cc[0], cc[1], cc[2], cc[3],
                             pH[j][0], pH[j][1], pH[j][2], pH[j][3],
                             vl4[u][0], vl4[u][1]);
                }
            }
        }
        __syncthreads();
    }

    // ---- epilogue: normalize, write GEMM-blocked hi/lo A for O-projection ----
    const float inv0 = 1.0f / l0;
    const float inv1 = 1.0f / l1;
    const int grow = b * Tq + r0g;
#pragma unroll
    for (int t = 0; t < 8; ++t) {
        const int col = h * DHq + t * 8 + quadcol;
        {
            unsigned char* base = apair
                + ((size_t)((grow >> 7) * KCq + (col >> 5))) * ABLK
                + (grow & 127) * 80 + (col & 31) * 2;
            store_split_pair(base, base + 10240, o[t][0] * inv0, o[t][1] * inv0);
        }
        {
            const int grow2 = grow + 8;
            unsigned char* base = apair
                + ((size_t)((grow2 >> 7) * KCq + (col >> 5))) * ABLK
                + (grow2 & 127) * 80 + (col & 31) * 2;
            store_split_pair(base, base + 10240, o[t][2] * inv1, o[t][3] * inv1);
        }
    }
}

// ---------------------------------------------------------------------------
// kernel_launch
// Inputs: x, attention_mask, Wq, Wk, Wv, Wo, bo
// ---------------------------------------------------------------------------
extern "C" void kernel_launch(void* const* d_in, const int* in_sizes, int n_in,
                              void* d_out, int out_size)
{
    (void)in_sizes; (void)n_in; (void)out_size;
    const float* x    = (const float*)d_in[0];
    const float* mask = (const float*)d_in[1];
    const float* Wq   = (const float*)d_in[2];
    const float* Wk   = (const float*)d_in[3];
    const float* Wv   = (const float*)d_in[4];
    const float* Wo   = (const float*)d_in[5];
    const float* bo   = (const float*)d_in[6];
    float* out = (float*)d_out;

    unsigned char *xpair, *apair, *w, *qb, *kpb, *vpb, *maskp;
    cudaGetSymbolAddress((void**)&xpair, g_xpair);
    cudaGetSymbolAddress((void**)&apair, g_apair);
    cudaGetSymbolAddress((void**)&w, g_w);
    cudaGetSymbolAddress((void**)&qb, g_qb);
    cudaGetSymbolAddress((void**)&kpb, g_kp);
    cudaGetSymbolAddress((void**)&vpb, g_vp);
    cudaGetSymbolAddress((void**)&maskp, g_maskp);

    const int M = Bq * Tq;     // 8192
    const int N = INNERq;      // 1024
    const int K = Dq;          // 1024
    const int nx = M * K;

    // conversions -> blocked layouts
    split_kernel<<<nx / (256 * 4), 256>>>(x, xpair);
    dim3 tGrid(N / 32, K / 32), tBlk(32, 8);
    tsplit_kernel<<<tGrid, tBlk>>>(Wq, w + 0 * WPAIR_BYTES, K, N);
    tsplit_kernel<<<tGrid, tBlk>>>(Wk, w + 1 * WPAIR_BYTES, K, N);
    tsplit_kernel<<<tGrid, tBlk>>>(Wv, w + 2 * WPAIR_BYTES, K, N);
    tsplit_kernel<<<tGrid, tBlk>>>(Wo, w + 3 * WPAIR_BYTES, K, N);
    dim3 mGrid(32, 16, Bq);
    mask_permute<<<mGrid, 256>>>(mask, maskp);

    // Q,K,V projections (one launch, bulk-fed) -> blocked Q / K / V
    cudaFuncSetAttribute(gemm_bulk_kernel,
                         cudaFuncAttributeMaxDynamicSharedMemorySize, GEMM_SMEM);
    dim3 qkvGrid(N / GBN, M / GBM, 3);
    gemm_bulk_kernel<<<qkvGrid, 256, GEMM_SMEM>>>(xpair, w, qb, kpb, vpb,
                                                  nullptr, nullptr, M, N, K);

    // flash attention (bulk-fed) -> blocked A pair
    cudaFuncSetAttribute(flash_mma_kernel,
                         cudaFuncAttributeMaxDynamicSharedMemorySize, FLASH_SMEM);
    dim3 fGrid(Tq / FBQ, Hq, Bq);
    flash_mma_kernel<<<fGrid, 256, FLASH_SMEM>>>(maskp, qb, kpb, vpb, apair);

    // output projection (fp32 + bias)
    dim3 oGrid(N / GBN, M / GBM, 1);
    gemm_bulk_kernel<<<oGrid, 256, GEMM_SMEM>>>(apair, w + 3 * WPAIR_BYTES,
                                                nullptr, nullptr, nullptr,
                                                out, bo, M, Dq, INNERq);
}

// round 9
// speedup vs baseline: 1.5562x; 1.1095x over previous
#include <cuda_runtime.h>
#include <cuda_bf16.h>
#include <cuda_fp16.h>
#include <cstdint>
#include <cstddef>

// ---------------------------------------------------------------------------
// Problem constants
// ---------------------------------------------------------------------------
#define Bq   4
#define Tq   2048
#define Dq   1024
#define Hq   16
#define DHq  64
#define INNERq 1024
#define SCALEq 0.125f     // 64^-0.5

// Blocked-layout sizes
#define KCq 32                                   // K chunks (1024/32)
#define ABLK 20480                               // one (128x32) hi|lo pair block
#define WPAIR_BYTES ((size_t)8 * 32 * ABLK)      // one weight, blocked
#define XPAIR_BYTES ((size_t)64 * 32 * ABLK)     // x / attn-out, blocked
#define QBLK 18432                               // Q (128x64) single fp16 plane
#define KVBLK 18432                              // K or V (64x64) fp16 hi|lo block
#define QB_BYTES ((size_t)Bq * Hq * 16 * QBLK)
#define KP_BYTES ((size_t)Bq * Hq * 32 * KVBLK)
#define MBLK 16384                               // permuted bf16 mask tile (128x64)
#define MP_BYTES ((size_t)Bq * 16 * 32 * MBLK)

// ---------------------------------------------------------------------------
// Scratch (device globals; allocation is forbidden)
// ---------------------------------------------------------------------------
__device__ __align__(128) unsigned char g_xpair[XPAIR_BYTES];
__device__ __align__(128) unsigned char g_apair[XPAIR_BYTES];
__device__ __align__(128) unsigned char g_w[4 * WPAIR_BYTES];
__device__ __align__(128) unsigned char g_qb[QB_BYTES];
__device__ __align__(128) unsigned char g_kp[KP_BYTES];
__device__ __align__(128) unsigned char g_vp[KP_BYTES];
__device__ __align__(128) unsigned char g_maskp[MP_BYTES];

// ---------------------------------------------------------------------------
// PTX helpers
// ---------------------------------------------------------------------------
__device__ __forceinline__ uint32_t smem_u32(const void* p) {
    uint32_t a;
    asm("{ .reg .u64 t; cvta.to.shared.u64 t, %1; cvt.u32.u64 %0, t; }" : "=r"(a) : "l"(p));
    return a;
}

#define MBAR_INIT(mbar, cnt) \
    asm volatile("mbarrier.init.shared.b64 [%0], %1;" :: "r"((uint32_t)(mbar)), "r"((uint32_t)(cnt)) : "memory")
#define MBAR_EXPECT_TX(mbar, bytes) \
    asm volatile("mbarrier.arrive.expect_tx.shared.b64 _, [%0], %1;" \
                 :: "r"((uint32_t)(mbar)), "r"((uint32_t)(bytes)) : "memory")
#define CP_BULK(smem_dst, gsrc, bytes, mbar) \
    asm volatile("cp.async.bulk.shared::cluster.global.mbarrier::complete_tx::bytes [%0], [%1], %2, [%3];" \
                 :: "r"((uint32_t)(smem_dst)), "l"(gsrc), "r"((uint32_t)(bytes)), \
                    "r"((uint32_t)(mbar)) : "memory")

__device__ __forceinline__ void mbar_wait(uint32_t mbar, uint32_t parity) {
    asm volatile(
        "{\n\t.reg .pred P;\n\t"
        "WAIT_%=:\n\t"
        "mbarrier.try_wait.parity.acquire.cta.shared::cta.b64 P, [%0], %1, 0x989680;\n\t"
        "@P bra DONE_%=;\n\t"
        "bra WAIT_%=;\n\t"
        "DONE_%=:\n\t}"
        :: "r"(mbar), "r"(parity) : "memory");
}

#define LDSM_X4(r0, r1, r2, r3, addr) \
    asm volatile("ldmatrix.sync.aligned.m8n8.x4.shared.b16 {%0,%1,%2,%3}, [%4];" \
                 : "=r"(r0), "=r"(r1), "=r"(r2), "=r"(r3) : "r"(addr))

#define LDSM_X4_T(r0, r1, r2, r3, addr) \
    asm volatile("ldmatrix.sync.aligned.m8n8.x4.trans.shared.b16 {%0,%1,%2,%3}, [%4];" \
                 : "=r"(r0), "=r"(r1), "=r"(r2), "=r"(r3) : "r"(addr))

#define MMA_BF16(c0, c1, c2, c3, a0, a1, a2, a3, b0, b1) \
    asm volatile("mma.sync.aligned.m16n8k16.row.col.f32.bf16.bf16.f32 " \
                 "{%0,%1,%2,%3}, {%4,%5,%6,%7}, {%8,%9}, {%0,%1,%2,%3};" \
                 : "+f"(c0), "+f"(c1), "+f"(c2), "+f"(c3) \
                 : "r"(a0), "r"(a1), "r"(a2), "r"(a3), "r"(b0), "r"(b1))

#define MMA_FP16(c0, c1, c2, c3, a0, a1, a2, a3, b0, b1) \
    asm volatile("mma.sync.aligned.m16n8k16.row.col.f32.f16.f16.f32 " \
                 "{%0,%1,%2,%3}, {%4,%5,%6,%7}, {%8,%9}, {%0,%1,%2,%3};" \
                 : "+f"(c0), "+f"(c1), "+f"(c2), "+f"(c3) \
                 : "r"(a0), "r"(a1), "r"(a2), "r"(a3), "r"(b0), "r"(b1))

// split fp32 pair -> bf16 hi (4B) + lo (4B) at byte pointers
__device__ __forceinline__ void store_split_pair(unsigned char* hi, unsigned char* lo,
                                                 float v0, float v1) {
    __nv_bfloat162 hh = __float22bfloat162_rn(make_float2(v0, v1));
    float2 hf = __bfloat1622float2(hh);
    __nv_bfloat162 ll = __float22bfloat162_rn(make_float2(v0 - hf.x, v1 - hf.y));
    *reinterpret_cast<uint32_t*>(hi) = *reinterpret_cast<uint32_t*>(&hh);
    *reinterpret_cast<uint32_t*>(lo) = *reinterpret_cast<uint32_t*>(&ll);
}

// ---------------------------------------------------------------------------
// x[8192,1024] fp32 -> blocked bf16 hi/lo pair layout
// ---------------------------------------------------------------------------
__global__ __launch_bounds__(256) void split_kernel(
    const float* __restrict__ in, unsigned char* __restrict__ out)
{
    const int i = (blockIdx.x * 256 + threadIdx.x) * 4;
    float4 v = *reinterpret_cast<const float4*>(in + i);
    const int row = i >> 10, col = i & 1023;
    unsigned char* base = out + ((size_t)((row >> 7) * KCq + (col >> 5))) * ABLK
                        + (row & 127) * 80 + (col & 31) * 2;
    __nv_bfloat16 h0 = __float2bfloat16(v.x), h1 = __float2bfloat16(v.y);
    __nv_bfloat16 h2 = __float2bfloat16(v.z), h3 = __float2bfloat16(v.w);
    __nv_bfloat162 H0; H0.x = h0; H0.y = h1;
    __nv_bfloat162 H1; H1.x = h2; H1.y = h3;
    uint2 hw = make_uint2(*reinterpret_cast<uint32_t*>(&H0), *reinterpret_cast<uint32_t*>(&H1));
    *reinterpret_cast<uint2*>(base) = hw;
    __nv_bfloat162 L0, L1;
    L0.x = __float2bfloat16(v.x - __bfloat162float(h0));
    L0.y = __float2bfloat16(v.y - __bfloat162float(h1));
    L1.x = __float2bfloat16(v.z - __bfloat162float(h2));
    L1.y = __float2bfloat16(v.w - __bfloat162float(h3));
    uint2 lw = make_uint2(*reinterpret_cast<uint32_t*>(&L0), *reinterpret_cast<uint32_t*>(&L1));
    *reinterpret_cast<uint2*>(base + 10240) = lw;
}

// ---------------------------------------------------------------------------
// W[K,N] fp32 -> transposed blocked bf16 hi/lo pair layout (Wt[n][k])
// ---------------------------------------------------------------------------
__global__ __launch_bounds__(256) void tsplit_kernel(
    const float* __restrict__ W, unsigned char* __restrict__ out, int K, int N)
{
    __shared__ float t[32][33];
    const int tx = threadIdx.x, ty = threadIdx.y;
    const int bx = blockIdx.x, by = blockIdx.y;
#pragma unroll
    for (int j = 0; j < 32; j += 8)
        t[ty + j][tx] = W[(size_t)(by * 32 + ty + j) * N + bx * 32 + tx];
    __syncthreads();
#pragma unroll
    for (int j = 0; j < 32; j += 8) {
        float v = t[tx][ty + j];
        const int n = bx * 32 + ty + j;
        const int k = by * 32 + tx;
        unsigned char* base = out + ((size_t)((n >> 7) * KCq + (k >> 5))) * ABLK
                            + (n & 127) * 80 + (k & 31) * 2;
        __nv_bfloat16 h = __float2bfloat16(v);
        *reinterpret_cast<__nv_bfloat16*>(base) = h;
        *reinterpret_cast<__nv_bfloat16*>(base + 10240) =
            __float2bfloat16(v - __bfloat162float(h));
    }
}

// ---------------------------------------------------------------------------
// Mask permute: fp32 [B,1,T,T] -> bf16, consumer-ordered per (b,qtile,chunk,tid)
// ---------------------------------------------------------------------------
__global__ __launch_bounds__(256) void mask_permute(
    const float* __restrict__ mask, unsigned char* __restrict__ out)
{
    __shared__ float tile[128 * 64];
    const int b = blockIdx.z, qt = blockIdx.y, ch = blockIdx.x;
    const int tid = threadIdx.x;
    const float* src = mask + ((size_t)b * Tq + qt * 128) * Tq + ch * 64;
    for (int i = tid; i < 2048; i += 256) {
        const int row = i >> 4, c4 = (i & 15) * 4;
        float4 v = *reinterpret_cast<const float4*>(src + (size_t)row * Tq + c4);
        tile[row * 64 + c4 + 0] = v.x;
        tile[row * 64 + c4 + 1] = v.y;
        tile[row * 64 + c4 + 2] = v.z;
        tile[row * 64 + c4 + 3] = v.w;
    }
    __syncthreads();
    const int wid = tid >> 5, lane = tid & 31;
    const int r0 = wid * 16 + (lane >> 2);
    const int cb = (lane & 3) * 2;
    uint32_t outv[16];
#pragma unroll
    for (int t = 0; t < 8; ++t)
#pragma unroll
        for (int u = 0; u < 2; ++u) {
            const int row = r0 + u * 8;
            const int c = t * 8 + cb;
            __nv_bfloat162 p = __float22bfloat162_rn(
                make_float2(tile[row * 64 + c], tile[row * 64 + c + 1]));
            outv[t * 2 + u] = *reinterpret_cast<uint32_t*>(&p);
        }
    uint4* dst = reinterpret_cast<uint4*>(
        out + ((size_t)((b * 16 + qt) * 32 + ch)) * MBLK + tid * 64);
#pragma unroll
    for (int i = 0; i < 4; ++i)
        dst[i] = make_uint4(outv[4 * i], outv[4 * i + 1], outv[4 * i + 2], outv[4 * i + 3]);
}

// ---------------------------------------------------------------------------
// bulk-copy GEMM: C = (Ah+Al) @ (Bh+Bl)^T over blocked bf16 pair layouts.
// QKV mode (C==null): z picks weight; epilogue -> fp16 blocked Q (1 plane) /
// K,V (hi|lo). O mode: fp32 C + bias.
// ---------------------------------------------------------------------------
#define GBM 128
#define GBN 128
#define GBK 32
#define TILEB 10240
#define STAGEB (4 * TILEB)
#define GEMM_SMEM (2 * STAGEB + 16)

__device__ __forceinline__ void store_qkv(unsigned char* dst, int z, int row, int col,
                                          float v0, float v1) {
    const int b = row >> 11, tok = row & 2047;
    const int h = col >> 6, dh = col & 63;
    if (z == 0) {
        const size_t off = ((size_t)((b * Hq + h) * 16 + (tok >> 7))) * QBLK
                         + (size_t)(tok & 127) * 144 + dh * 2;
        __half2 hh = __float22half2_rn(make_float2(v0, v1));
        *reinterpret_cast<uint32_t*>(dst + off) = *reinterpret_cast<uint32_t*>(&hh);
    } else {
        const size_t off = ((size_t)((b * Hq + h) * 32 + (tok >> 6))) * KVBLK
                         + (size_t)(tok & 63) * 144 + dh * 2;
        __half2 hh = __float22half2_rn(make_float2(v0, v1));
        float2 hf = __half22float2(hh);
        __half2 ll = __float22half2_rn(make_float2(v0 - hf.x, v1 - hf.y));
        *reinterpret_cast<uint32_t*>(dst + off) = *reinterpret_cast<uint32_t*>(&hh);
        *reinterpret_cast<uint32_t*>(dst + off + 9216) = *reinterpret_cast<uint32_t*>(&ll);
    }
}

__global__ __launch_bounds__(256, 2) void gemm_bulk_kernel(
    const unsigned char* __restrict__ Apair, const unsigned char* __restrict__ Wb,
    unsigned char* __restrict__ qb, unsigned char* __restrict__ kp,
    unsigned char* __restrict__ vp,
    float* __restrict__ C, const float* __restrict__ bias,
    int M, int N, int K)
{
    extern __shared__ char smem[];
    const uint32_t sb = smem_u32(smem);
    const uint32_t mb0 = sb + 2 * STAGEB;
    const uint32_t mb1 = mb0 + 8;

    const int tid = threadIdx.x;
    const int wid = tid >> 5;
    const int lane = tid & 31;
    const int warp_m = wid >> 1;
    const int warp_n = wid & 1;
    const int row0 = blockIdx.y * GBM;
    const int col0 = blockIdx.x * GBN;
    const int z = blockIdx.z;
    const int KC = K / GBK;

    const unsigned char* Asrc = Apair + ((size_t)blockIdx.y * KC) * ABLK;
    const unsigned char* Bsrc = (C == nullptr ? Wb + (size_t)z * WPAIR_BYTES : Wb)
                              + ((size_t)blockIdx.x * KC) * ABLK;

    if (tid == 0) { MBAR_INIT(mb0, 1); MBAR_INIT(mb1, 1); }
    __syncthreads();

    if (tid == 0) {
        MBAR_EXPECT_TX(mb0, STAGEB);
        CP_BULK(sb, Asrc, 2 * TILEB, mb0);
        CP_BULK(sb + 2 * TILEB, Bsrc, 2 * TILEB, mb0);
    }

    float acc[2][8][4];
#pragma unroll
    for (int i = 0; i < 2; ++i)
#pragma unroll
        for (int j = 0; j < 8; ++j)
#pragma unroll
            for (int q = 0; q < 4; ++q) acc[i][j][q] = 0.0f;

    for (int c = 0; c < KC; ++c) {
        if (c + 1 < KC && tid == 0) {
            const uint32_t stn = sb + ((c + 1) & 1) * STAGEB;
            const uint32_t mbn = ((c + 1) & 1) ? mb1 : mb0;
            MBAR_EXPECT_TX(mbn, STAGEB);
            CP_BULK(stn, Asrc + (size_t)(c + 1) * ABLK, 2 * TILEB, mbn);
            CP_BULK(stn + 2 * TILEB, Bsrc + (size_t)(c + 1) * ABLK, 2 * TILEB, mbn);
        }
        mbar_wait((c & 1) ? mb1 : mb0, (c >> 1) & 1);

        const uint32_t st = sb + (c & 1) * STAGEB;
        const uint32_t aH = st;
        const uint32_t aL = st + TILEB;
        const uint32_t bH = st + 2 * TILEB;
        const uint32_t bL = st + 3 * TILEB;

#pragma unroll
        for (int kst = 0; kst < 2; ++kst) {
            const int kb = kst * 32 + (lane >> 4) * 16;

            uint32_t ah[2][4], al[2][4];
#pragma unroll
            for (int mt = 0; mt < 2; ++mt) {
                const int arow = warp_m * 32 + mt * 16 + (lane & 15);
                LDSM_X4(ah[mt][0], ah[mt][1], ah[mt][2], ah[mt][3], aH + arow * 80 + kb);
                LDSM_X4(al[mt][0], al[mt][1], al[mt][2], al[mt][3], aL + arow * 80 + kb);
            }

#pragma unroll
            for (int g = 0; g < 2; ++g) {
                uint32_t bh[4][2], bl[4][2];
                const int brow_in = (lane & 7) + ((lane >> 4) << 3);
                const int bkb = kst * 32 + ((lane >> 3) & 1) * 16;
#pragma unroll
                for (int p = 0; p < 2; ++p) {
                    const int nb = warp_n * 64 + g * 32 + p * 16;
                    const uint32_t ba = (nb + brow_in) * 80 + bkb;
                    LDSM_X4(bh[2 * p][0], bh[2 * p][1], bh[2 * p + 1][0], bh[2 * p + 1][1],
                            bH + ba);
                    LDSM_X4(bl[2 * p][0], bl[2 * p][1], bl[2 * p + 1][0], bl[2 * p + 1][1],
                            bL + ba);
                }
#pragma unroll
                for (int mt = 0; mt < 2; ++mt)
#pragma unroll
                    for (int nt = 0; nt < 4; ++nt) {
                        float* cc = acc[mt][g * 4 + nt];
                        MMA_BF16(cc[0], cc[1], cc[2], cc[3],
                                 ah[mt][0], ah[mt][1], ah[mt][2], ah[mt][3],
                                 bh[nt][0], bh[nt][1]);
                        MMA_BF16(cc[0], cc[1], cc[2], cc[3],
                                 ah[mt][0], ah[mt][1], ah[mt][2], ah[mt][3],
                                 bl[nt][0], bl[nt][1]);
                        MMA_BF16(cc[0], cc[1], cc[2], cc[3],
                                 al[mt][0], al[mt][1], al[mt][2], al[mt][3],
                                 bh[nt][0], bh[nt][1]);
                    }
            }
        }
        __syncthreads();
    }

    // epilogue
    if (C != nullptr) {
#pragma unroll
        for (int mt = 0; mt < 2; ++mt) {
            const int rbase = row0 + warp_m * 32 + mt * 16 + (lane >> 2);
#pragma unroll
            for (int nt = 0; nt < 8; ++nt) {
                const int cbase = col0 + warp_n * 64 + nt * 8 + (lane & 3) * 2;
                float v0 = acc[mt][nt][0], v1 = acc[mt][nt][1];
                float v2 = acc[mt][nt][2], v3 = acc[mt][nt][3];
                const float b0 = bias[cbase], b1 = bias[cbase + 1];
                v0 += b0; v1 += b1; v2 += b0; v3 += b1;
                *reinterpret_cast<float2*>(C + (size_t)rbase * N + cbase) = make_float2(v0, v1);
                *reinterpret_cast<float2*>(C + (size_t)(rbase + 8) * N + cbase) = make_float2(v2, v3);
            }
        }
    } else {
        const float scale = (z == 0) ? SCALEq : 1.0f;
        unsigned char* dst = (z == 0) ? qb : (z == 1) ? kp : vp;
#pragma unroll
        for (int mt = 0; mt < 2; ++mt) {
            const int rbase = row0 + warp_m * 32 + mt * 16 + (lane >> 2);
#pragma unroll
            for (int nt = 0; nt < 8; ++nt) {
                const int cbase = col0 + warp_n * 64 + nt * 8 + (lane & 3) * 2;
                store_qkv(dst, z, rbase, cbase,
                          acc[mt][nt][0] * scale, acc[mt][nt][1] * scale);
                store_qkv(dst, z, rbase + 8, cbase,
                          acc[mt][nt][2] * scale, acc[mt][nt][3] * scale);
            }
        }
    }
}

// ---------------------------------------------------------------------------
// Tensor-core flash attention, fp16 2-pass, bulk-copy fed.
// S = Qh(fp16) @ (Kh+Kl);  O += Ph(fp16) @ (Vh+Vl).  128 MMA/warp/chunk.
// ---------------------------------------------------------------------------
#define FBQ 128
#define FBK 64
#define FROWB 144
#define FQ_TILE (FBQ * FROWB)               // 18432 (single fp16 plane)
#define FKV_TILE (FBK * FROWB)              // 9216
#define F_ST FQ_TILE                        // 18432
#define F_STAGE (4 * FKV_TILE)              // 36864 (Kh Kl Vh Vl)
#define FLASH_SMEM (F_ST + 2 * F_STAGE + 32)

__global__ __launch_bounds__(256, 2) void flash_mma_kernel(
    const unsigned char* __restrict__ maskp,
    const unsigned char* __restrict__ qb,
    const unsigned char* __restrict__ kp,
    const unsigned char* __restrict__ vp,
    unsigned char* __restrict__ apair)
{
    extern __shared__ char smem[];
    const uint32_t sb = smem_u32(smem);
    const uint32_t mbQ = sb + F_ST + 2 * F_STAGE;
    const uint32_t mbK0 = mbQ + 8;
    const uint32_t mbK1 = mbQ + 16;

    const int tid  = threadIdx.x;
    const int wid  = tid >> 5;
    const int lane = tid & 31;
    const int qt = blockIdx.x;
    const int h  = blockIdx.y;
    const int b  = blockIdx.z;

    const unsigned char* qsrc = qb + ((size_t)((b * Hq + h) * 16 + qt)) * QBLK;
    const unsigned char* kbase = kp + ((size_t)((b * Hq + h) * 32)) * KVBLK;
    const unsigned char* vbase = vp + ((size_t)((b * Hq + h) * 32)) * KVBLK;
    const unsigned char* mbase = maskp + ((size_t)((b * 16 + qt) * 32)) * MBLK + tid * 64;

    if (tid == 0) { MBAR_INIT(mbQ, 1); MBAR_INIT(mbK0, 1); MBAR_INIT(mbK1, 1); }
    __syncthreads();

    if (tid == 0) {
        MBAR_EXPECT_TX(mbQ, FQ_TILE);
        CP_BULK(sb, qsrc, FQ_TILE, mbQ);
        MBAR_EXPECT_TX(mbK0, F_STAGE);
        CP_BULK(sb + F_ST, kbase, KVBLK, mbK0);
        CP_BULK(sb + F_ST + KVBLK, vbase, KVBLK, mbK0);
    }

    float o[8][4];
#pragma unroll
    for (int t = 0; t < 8; ++t)
#pragma unroll
        for (int j = 0; j < 4; ++j) o[t][j] = 0.0f;
    float m0 = -1e30f, m1 = -1e30f, l0 = 0.0f, l1 = 0.0f;

    const int r0g = qt * FBQ + wid * 16 + (lane >> 2);
    const int quadcol = (lane & 3) * 2;

    mbar_wait(mbQ, 0);

    const int chunks = Tq / FBK;   // 32
    for (int c = 0; c < chunks; ++c) {
        if (c + 1 < chunks && tid == 0) {
            const uint32_t stn = sb + F_ST + ((c + 1) & 1) * F_STAGE;
            const uint32_t mbn = ((c + 1) & 1) ? mbK1 : mbK0;
            MBAR_EXPECT_TX(mbn, F_STAGE);
            CP_BULK(stn, kbase + (size_t)(c + 1) * KVBLK, KVBLK, mbn);
            CP_BULK(stn + KVBLK, vbase + (size_t)(c + 1) * KVBLK, KVBLK, mbn);
        }
        mbar_wait((c & 1) ? mbK1 : mbK0, (c >> 1) & 1);

        const uint32_t st = sb + F_ST + (c & 1) * F_STAGE;
        const uint32_t kH = st;
        const uint32_t kL = st + FKV_TILE;
        const uint32_t vH = st + 2 * FKV_TILE;
        const uint32_t vL = st + 3 * FKV_TILE;

        // ---- S = Qh (Kh + Kl)  (fp16, 2 passes) ----
        float s[8][4];
#pragma unroll
        for (int t = 0; t < 8; ++t)
#pragma unroll
            for (int j = 0; j < 4; ++j) s[t][j] = 0.0f;

        const int brow_in = (lane & 7) + ((lane >> 4) << 3);
#pragma unroll
        for (int kk = 0; kk < 4; ++kk) {
            uint32_t q4[4];
            const uint32_t qa = sb + (wid * 16 + (lane & 15)) * FROWB
                              + kk * 32 + (lane >> 4) * 16;
            LDSM_X4(q4[0], q4[1], q4[2], q4[3], qa);

            const int bkb = kk * 32 + ((lane >> 3) & 1) * 16;
#pragma unroll
            for (int p = 0; p < 4; ++p) {
                uint32_t bh[2][2], bl[2][2];
                const uint32_t ba = (p * 16 + brow_in) * FROWB + bkb;
                LDSM_X4(bh[0][0], bh[0][1], bh[1][0], bh[1][1], kH + ba);
                LDSM_X4(bl[0][0], bl[0][1], bl[1][0], bl[1][1], kL + ba);
#pragma unroll
                for (int u = 0; u < 2; ++u) {
                    float* cc = s[2 * p + u];
                    MMA_FP16(cc[0], cc[1], cc[2], cc[3],
                             q4[0], q4[1], q4[2], q4[3], bh[u][0], bh[u][1]);
                    MMA_FP16(cc[0], cc[1], cc[2], cc[3],
                             q4[0], q4[1], q4[2], q4[3], bl[u][0], bl[u][1]);
                }
            }
        }

        // ---- mask (permuted bf16) + online softmax ----
        {
            const uint4* mp = reinterpret_cast<const uint4*>(mbase + (size_t)c * MBLK);
            uint32_t mu[16];
#pragma unroll
            for (int i = 0; i < 4; ++i) {
                uint4 q = mp[i];
                mu[4 * i + 0] = q.x; mu[4 * i + 1] = q.y;
                mu[4 * i + 2] = q.z; mu[4 * i + 3] = q.w;
            }
#pragma unroll
            for (int t = 0; t < 8; ++t) {
                float2 lo2 = __bfloat1622float2(
                    *reinterpret_cast<__nv_bfloat162*>(&mu[2 * t]));
                float2 hi2 = __bfloat1622float2(
                    *reinterpret_cast<__nv_bfloat162*>(&mu[2 * t + 1]));
                s[t][0] += lo2.x; s[t][1] += lo2.y;
                s[t][2] += hi2.x; s[t][3] += hi2.y;
            }
        }

        float mx0 = -1e30f, mx1 = -1e30f;
#pragma unroll
        for (int t = 0; t < 8; ++t) {
            mx0 = fmaxf(mx0, fmaxf(s[t][0], s[t][1]));
            mx1 = fmaxf(mx1, fmaxf(s[t][2], s[t][3]));
        }
        mx0 = fmaxf(mx0, __shfl_xor_sync(0xffffffffu, mx0, 1));
        mx0 = fmaxf(mx0, __shfl_xor_sync(0xffffffffu, mx0, 2));
        mx1 = fmaxf(mx1, __shfl_xor_sync(0xffffffffu, mx1, 1));
        mx1 = fmaxf(mx1, __shfl_xor_sync(0xffffffffu, mx1, 2));

        const float mn0 = fmaxf(m0, mx0);
        const float mn1 = fmaxf(m1, mx1);
        const float a0 = __expf(m0 - mn0);
        const float a1 = __expf(m1 - mn1);
        m0 = mn0; m1 = mn1;

        float sum0 = 0.0f, sum1 = 0.0f;
#pragma unroll
        for (int t = 0; t < 8; ++t) {
            s[t][0] = __expf(s[t][0] - mn0);
            s[t][1] = __expf(s[t][1] - mn0);
            s[t][2] = __expf(s[t][2] - mn1);
            s[t][3] = __expf(s[t][3] - mn1);
            sum0 += s[t][0] + s[t][1];
            sum1 += s[t][2] + s[t][3];
        }
        sum0 += __shfl_xor_sync(0xffffffffu, sum0, 1);
        sum0 += __shfl_xor_sync(0xffffffffu, sum0, 2);
        sum1 += __shfl_xor_sync(0xffffffffu, sum1, 1);
        sum1 += __shfl_xor_sync(0xffffffffu, sum1, 2);
        l0 = l0 * a0 + sum0;
        l1 = l1 * a1 + sum1;

#pragma unroll
        for (int t = 0; t < 8; ++t) {
            o[t][0] *= a0; o[t][1] *= a0;
            o[t][2] *= a1; o[t][3] *= a1;
        }

        // ---- P fragments (fp16, single plane) ----
        uint32_t pH[4][4];
#pragma unroll
        for (int j = 0; j < 4; ++j) {
#pragma unroll
            for (int u = 0; u < 2; ++u) {
#pragma unroll
                for (int w = 0; w < 2; ++w) {
                    __half2 hh = __float22half2_rn(make_float2(
                        s[2 * j + w][2 * u + 0], s[2 * j + w][2 * u + 1]));
                    pH[j][2 * w + u] = *reinterpret_cast<uint32_t*>(&hh);
                }
            }
        }

        // ---- O += Ph (Vh + Vl)  (fp16, 2 passes) ----
#pragma unroll
        for (int j = 0; j < 4; ++j) {
#pragma unroll
            for (int p = 0; p < 4; ++p) {
                uint32_t vh4[2][2], vl4[2][2];
                const uint32_t va = (j * 16 + (lane & 15)) * FROWB
                                  + p * 32 + (lane >> 4) * 16;
                LDSM_X4_T(vh4[0][0], vh4[0][1], vh4[1][0], vh4[1][1], vH + va);
                LDSM_X4_T(vl4[0][0], vl4[0][1], vl4[1][0], vl4[1][1], vL + va);
#pragma unroll
                for (int u = 0; u < 2; ++u) {
                    float* cc = o[2 * p + u];
                    MMA_FP16(cc[0], cc[1], cc[2], cc[3],
                             pH[j][0], pH[j][1], pH[j][2], pH[j][3],
                             vh4[u][0], vh4[u][1]);
                    MMA_FP16(cc[0], cc[1], cc[2], cc[3],
                             pH[j][0], pH[j][1], pH[j][2], pH[j][3],
                             vl4[u][0], vl4[u][1]);
                }
            }
        }
        __syncthreads();
    }

    // ---- epilogue: normalize, write GEMM-blocked bf16 hi/lo A ----
    const float inv0 = 1.0f / l0;
    const float inv1 = 1.0f / l1;
    const int grow = b * Tq + r0g;
#pragma unroll
    for (int t = 0; t < 8; ++t) {
        const int col = h * DHq + t * 8 + quadcol;
        {
            unsigned char* base = apair
                + ((size_t)((grow >> 7) * KCq + (col >> 5))) * ABLK
                + (grow & 127) * 80 + (col & 31) * 2;
            store_split_pair(base, base + 10240, o[t][0] * inv0, o[t][1] * inv0);
        }
        {
            const int grow2 = grow + 8;
            unsigned char* base = apair
                + ((size_t)((grow2 >> 7) * KCq + (col >> 5))) * ABLK
                + (grow2 & 127) * 80 + (col & 31) * 2;
            store_split_pair(base, base + 10240, o[t][2] * inv1, o[t][3] * inv1);
        }
    }
}

// ---------------------------------------------------------------------------
// kernel_launch
// Inputs: x, attention_mask, Wq, Wk, Wv, Wo, bo
// ---------------------------------------------------------------------------
extern "C" void kernel_launch(void* const* d_in, const int* in_sizes, int n_in,
                              void* d_out, int out_size)
{
    (void)in_sizes; (void)n_in; (void)out_size;
    const float* x    = (const float*)d_in[0];
    const float* mask = (const float*)d_in[1];
    const float* Wq   = (const float*)d_in[2];
    const float* Wk   = (const float*)d_in[3];
    const float* Wv   = (const float*)d_in[4];
    const float* Wo   = (const float*)d_in[5];
    const float* bo   = (const float*)d_in[6];
    float* out = (float*)d_out;

    unsigned char *xpair, *apair, *w, *qb, *kpb, *vpb, *maskp;
    cudaGetSymbolAddress((void**)&xpair, g_xpair);
    cudaGetSymbolAddress((void**)&apair, g_apair);
    cudaGetSymbolAddress((void**)&w, g_w);
    cudaGetSymbolAddress((void**)&qb, g_qb);
    cudaGetSymbolAddress((void**)&kpb, g_kp);
    cudaGetSymbolAddress((void**)&vpb, g_vp);
    cudaGetSymbolAddress((void**)&maskp, g_maskp);

    const int M = Bq * Tq;     // 8192
    const int N = INNERq;      // 1024
    const int K = Dq;          // 1024
    const int nx = M * K;

    // conversions -> blocked layouts
    split_kernel<<<nx / (256 * 4), 256>>>(x, xpair);
    dim3 tGrid(N / 32, K / 32), tBlk(32, 8);
    tsplit_kernel<<<tGrid, tBlk>>>(Wq, w + 0 * WPAIR_BYTES, K, N);
    tsplit_kernel<<<tGrid, tBlk>>>(Wk, w + 1 * WPAIR_BYTES, K, N);
    tsplit_kernel<<<tGrid, tBlk>>>(Wv, w + 2 * WPAIR_BYTES, K, N);
    tsplit_kernel<<<tGrid, tBlk>>>(Wo, w + 3 * WPAIR_BYTES, K, N);
    dim3 mGrid(32, 16, Bq);
    mask_permute<<<mGrid, 256>>>(mask, maskp);

    // Q,K,V projections (one launch, bulk-fed) -> fp16 blocked Q / K / V
    cudaFuncSetAttribute(gemm_bulk_kernel,
                         cudaFuncAttributeMaxDynamicSharedMemorySize, GEMM_SMEM);
    dim3 qkvGrid(N / GBN, M / GBM, 3);
    gemm_bulk_kernel<<<qkvGrid, 256, GEMM_SMEM>>>(xpair, w, qb, kpb, vpb,
                                                  nullptr, nullptr, M, N, K);

    // flash attention (fp16 2-pass, bulk-fed) -> blocked A pair
    cudaFuncSetAttribute(flash_mma_kernel,
                         cudaFuncAttributeMaxDynamicSharedMemorySize, FLASH_SMEM);
    dim3 fGrid(Tq / FBQ, Hq, Bq);
    flash_mma_kernel<<<fGrid, 256, FLASH_SMEM>>>(maskp, qb, kpb, vpb, apair);

    // output projection (fp32 + bias)
    dim3 oGrid(N / GBN, M / GBM, 1);
    gemm_bulk_kernel<<<oGrid, 256, GEMM_SMEM>>>(apair, w + 3 * WPAIR_BYTES,
                                                nullptr, nullptr, nullptr,
                                                out, bo, M, Dq, INNERq);
}

// round 10
// speedup vs baseline: 1.8362x; 1.1799x over previous
#include <cuda_runtime.h>
#include <cuda_bf16.h>
#include <cuda_fp16.h>
#include <cstdint>
#include <cstddef>

// ---------------------------------------------------------------------------
// Problem constants
// ---------------------------------------------------------------------------
#define Bq   4
#define Tq   2048
#define Dq   1024
#define Hq   16
#define DHq  64
#define INNERq 1024
#define SCALEq 0.125f     // 64^-0.5

// Blocked-layout sizes
#define KCq 32                                   // K chunks (1024/32)
#define XBLK 10240                               // activation (128x32) single fp16 plane
#define WBLK 20480                               // weight (128x32) fp16 hi|lo pair
#define WPAIR_BYTES ((size_t)8 * 32 * WBLK)      // one weight, blocked
#define XPLANE_BYTES ((size_t)64 * 32 * XBLK)    // x / attn-out, blocked single plane
#define QBLK 18432                               // Q (128x64) single fp16 plane
#define KVBLK 18432                              // K or V (64x64) fp16 hi|lo block
#define QB_BYTES ((size_t)Bq * Hq * 16 * QBLK)
#define KP_BYTES ((size_t)Bq * Hq * 32 * KVBLK)
#define MBLK 16384                               // permuted bf16 mask tile (128x64)
#define MP_BYTES ((size_t)Bq * 16 * 32 * MBLK)

// ---------------------------------------------------------------------------
// Scratch (device globals; allocation is forbidden)
// ---------------------------------------------------------------------------
__device__ __align__(128) unsigned char g_xp[XPLANE_BYTES];
__device__ __align__(128) unsigned char g_ap[XPLANE_BYTES];
__device__ __align__(128) unsigned char g_w[4 * WPAIR_BYTES];
__device__ __align__(128) unsigned char g_qb[QB_BYTES];
__device__ __align__(128) unsigned char g_kp[KP_BYTES];
__device__ __align__(128) unsigned char g_vp[KP_BYTES];
__device__ __align__(128) unsigned char g_maskp[MP_BYTES];

// ---------------------------------------------------------------------------
// PTX helpers
// ---------------------------------------------------------------------------
__device__ __forceinline__ uint32_t smem_u32(const void* p) {
    uint32_t a;
    asm("{ .reg .u64 t; cvta.to.shared.u64 t, %1; cvt.u32.u64 %0, t; }" : "=r"(a) : "l"(p));
    return a;
}

#define MBAR_INIT(mbar, cnt) \
    asm volatile("mbarrier.init.shared.b64 [%0], %1;" :: "r"((uint32_t)(mbar)), "r"((uint32_t)(cnt)) : "memory")
#define MBAR_EXPECT_TX(mbar, bytes) \
    asm volatile("mbarrier.arrive.expect_tx.shared.b64 _, [%0], %1;" \
                 :: "r"((uint32_t)(mbar)), "r"((uint32_t)(bytes)) : "memory")
#define CP_BULK(smem_dst, gsrc, bytes, mbar) \
    asm volatile("cp.async.bulk.shared::cluster.global.mbarrier::complete_tx::bytes [%0], [%1], %2, [%3];" \
                 :: "r"((uint32_t)(smem_dst)), "l"(gsrc), "r"((uint32_t)(bytes)), \
                    "r"((uint32_t)(mbar)) : "memory")

__device__ __forceinline__ void mbar_wait(uint32_t mbar, uint32_t parity) {
    asm volatile(
        "{\n\t.reg .pred P;\n\t"
        "WAIT_%=:\n\t"
        "mbarrier.try_wait.parity.acquire.cta.shared::cta.b64 P, [%0], %1, 0x989680;\n\t"
        "@P bra DONE_%=;\n\t"
        "bra WAIT_%=;\n\t"
        "DONE_%=:\n\t}"
        :: "r"(mbar), "r"(parity) : "memory");
}

#define LDSM_X4(r0, r1, r2, r3, addr) \
    asm volatile("ldmatrix.sync.aligned.m8n8.x4.shared.b16 {%0,%1,%2,%3}, [%4];" \
                 : "=r"(r0), "=r"(r1), "=r"(r2), "=r"(r3) : "r"(addr))

#define LDSM_X4_T(r0, r1, r2, r3, addr) \
    asm volatile("ldmatrix.sync.aligned.m8n8.x4.trans.shared.b16 {%0,%1,%2,%3}, [%4];" \
                 : "=r"(r0), "=r"(r1), "=r"(r2), "=r"(r3) : "r"(addr))

#define MMA_FP16(c0, c1, c2, c3, a0, a1, a2, a3, b0, b1) \
    asm volatile("mma.sync.aligned.m16n8k16.row.col.f32.f16.f16.f32 " \
                 "{%0,%1,%2,%3}, {%4,%5,%6,%7}, {%8,%9}, {%0,%1,%2,%3};" \
                 : "+f"(c0), "+f"(c1), "+f"(c2), "+f"(c3) \
                 : "r"(a0), "r"(a1), "r"(a2), "r"(a3), "r"(b0), "r"(b1))

// ---------------------------------------------------------------------------
// x[8192,1024] fp32 -> blocked single fp16 plane
// ---------------------------------------------------------------------------
__global__ __launch_bounds__(256) void split_kernel(
    const float* __restrict__ in, unsigned char* __restrict__ out)
{
    const int i = (blockIdx.x * 256 + threadIdx.x) * 4;
    float4 v = *reinterpret_cast<const float4*>(in + i);
    const int row = i >> 10, col = i & 1023;
    unsigned char* base = out + ((size_t)((row >> 7) * KCq + (col >> 5))) * XBLK
                        + (row & 127) * 80 + (col & 31) * 2;
    __half2 h01 = __float22half2_rn(make_float2(v.x, v.y));
    __half2 h23 = __float22half2_rn(make_float2(v.z, v.w));
    *reinterpret_cast<uint2*>(base) = make_uint2(
        *reinterpret_cast<uint32_t*>(&h01), *reinterpret_cast<uint32_t*>(&h23));
}

// ---------------------------------------------------------------------------
// W[K,N] fp32 -> transposed blocked fp16 hi/lo pair (Wt[n][k])
// ---------------------------------------------------------------------------
__global__ __launch_bounds__(256) void tsplit_kernel(
    const float* __restrict__ W, unsigned char* __restrict__ out, int K, int N)
{
    __shared__ float t[32][33];
    const int tx = threadIdx.x, ty = threadIdx.y;
    const int bx = blockIdx.x, by = blockIdx.y;
#pragma unroll
    for (int j = 0; j < 32; j += 8)
        t[ty + j][tx] = W[(size_t)(by * 32 + ty + j) * N + bx * 32 + tx];
    __syncthreads();
#pragma unroll
    for (int j = 0; j < 32; j += 8) {
        float v = t[tx][ty + j];
        const int n = bx * 32 + ty + j;
        const int k = by * 32 + tx;
        unsigned char* base = out + ((size_t)((n >> 7) * KCq + (k >> 5))) * WBLK
                            + (n & 127) * 80 + (k & 31) * 2;
        __half h = __float2half_rn(v);
        *reinterpret_cast<__half*>(base) = h;
        *reinterpret_cast<__half*>(base + 10240) = __float2half_rn(v - __half2float(h));
    }
}

// ---------------------------------------------------------------------------
// Mask permute: fp32 [B,1,T,T] -> bf16, consumer-ordered per (b,qtile,chunk,tid)
// ---------------------------------------------------------------------------
__global__ __launch_bounds__(256) void mask_permute(
    const float* __restrict__ mask, unsigned char* __restrict__ out)
{
    __shared__ float tile[128 * 64];
    const int b = blockIdx.z, qt = blockIdx.y, ch = blockIdx.x;
    const int tid = threadIdx.x;
    const float* src = mask + ((size_t)b * Tq + qt * 128) * Tq + ch * 64;
    for (int i = tid; i < 2048; i += 256) {
        const int row = i >> 4, c4 = (i & 15) * 4;
        float4 v = *reinterpret_cast<const float4*>(src + (size_t)row * Tq + c4);
        tile[row * 64 + c4 + 0] = v.x;
        tile[row * 64 + c4 + 1] = v.y;
        tile[row * 64 + c4 + 2] = v.z;
        tile[row * 64 + c4 + 3] = v.w;
    }
    __syncthreads();
    const int wid = tid >> 5, lane = tid & 31;
    const int r0 = wid * 16 + (lane >> 2);
    const int cb = (lane & 3) * 2;
    uint32_t outv[16];
#pragma unroll
    for (int t = 0; t < 8; ++t)
#pragma unroll
        for (int u = 0; u < 2; ++u) {
            const int row = r0 + u * 8;
            const int c = t * 8 + cb;
            __nv_bfloat162 p = __float22bfloat162_rn(
                make_float2(tile[row * 64 + c], tile[row * 64 + c + 1]));
            outv[t * 2 + u] = *reinterpret_cast<uint32_t*>(&p);
        }
    uint4* dst = reinterpret_cast<uint4*>(
        out + ((size_t)((b * 16 + qt) * 32 + ch)) * MBLK + tid * 64);
#pragma unroll
    for (int i = 0; i < 4; ++i)
        dst[i] = make_uint4(outv[4 * i], outv[4 * i + 1], outv[4 * i + 2], outv[4 * i + 3]);
}

// ---------------------------------------------------------------------------
// bulk-copy GEMM (fp16 one-sided split): C = Ah @ (Bh+Bl)^T.
// A: blocked single fp16 plane. B: blocked fp16 hi|lo pair.
// QKV mode (C==null): z picks weight; epilogue -> fp16 blocked Q/K/V.
// O mode: fp32 C + bias.
// ---------------------------------------------------------------------------
#define GBM 128
#define GBN 128
#define GBK 32
#define STAGEB (XBLK + WBLK)          // 30720: A | Bh | Bl
#define GEMM_SMEM (2 * STAGEB + 16)

__device__ __forceinline__ void store_qkv(unsigned char* dst, int z, int row, int col,
                                          float v0, float v1) {
    const int b = row >> 11, tok = row & 2047;
    const int h = col >> 6, dh = col & 63;
    if (z == 0) {
        const size_t off = ((size_t)((b * Hq + h) * 16 + (tok >> 7))) * QBLK
                         + (size_t)(tok & 127) * 144 + dh * 2;
        __half2 hh = __float22half2_rn(make_float2(v0, v1));
        *reinterpret_cast<uint32_t*>(dst + off) = *reinterpret_cast<uint32_t*>(&hh);
    } else {
        const size_t off = ((size_t)((b * Hq + h) * 32 + (tok >> 6))) * KVBLK
                         + (size_t)(tok & 63) * 144 + dh * 2;
        __half2 hh = __float22half2_rn(make_float2(v0, v1));
        float2 hf = __half22float2(hh);
        __half2 ll = __float22half2_rn(make_float2(v0 - hf.x, v1 - hf.y));
        *reinterpret_cast<uint32_t*>(dst + off) = *reinterpret_cast<uint32_t*>(&hh);
        *reinterpret_cast<uint32_t*>(dst + off + 9216) = *reinterpret_cast<uint32_t*>(&ll);
    }
}

__global__ __launch_bounds__(256, 2) void gemm_bulk_kernel(
    const unsigned char* __restrict__ Aplane, const unsigned char* __restrict__ Wb,
    unsigned char* __restrict__ qb, unsigned char* __restrict__ kp,
    unsigned char* __restrict__ vp,
    float* __restrict__ C, const float* __restrict__ bias,
    int M, int N, int K)
{
    extern __shared__ char smem[];
    const uint32_t sb = smem_u32(smem);
    const uint32_t mb0 = sb + 2 * STAGEB;
    const uint32_t mb1 = mb0 + 8;

    const int tid = threadIdx.x;
    const int wid = tid >> 5;
    const int lane = tid & 31;
    const int warp_m = wid >> 1;
    const int warp_n = wid & 1;
    const int row0 = blockIdx.y * GBM;
    const int col0 = blockIdx.x * GBN;
    const int z = blockIdx.z;
    const int KC = K / GBK;

    const unsigned char* Asrc = Aplane + ((size_t)blockIdx.y * KC) * XBLK;
    const unsigned char* Bsrc = (C == nullptr ? Wb + (size_t)z * WPAIR_BYTES : Wb)
                              + ((size_t)blockIdx.x * KC) * WBLK;

    if (tid == 0) { MBAR_INIT(mb0, 1); MBAR_INIT(mb1, 1); }
    __syncthreads();

    if (tid == 0) {
        MBAR_EXPECT_TX(mb0, STAGEB);
        CP_BULK(sb, Asrc, XBLK, mb0);
        CP_BULK(sb + XBLK, Bsrc, WBLK, mb0);
    }

    float acc[2][8][4];
#pragma unroll
    for (int i = 0; i < 2; ++i)
#pragma unroll
        for (int j = 0; j < 8; ++j)
#pragma unroll
            for (int q = 0; q < 4; ++q) acc[i][j][q] = 0.0f;

    for (int c = 0; c < KC; ++c) {
        if (c + 1 < KC && tid == 0) {
            const uint32_t stn = sb + ((c + 1) & 1) * STAGEB;
            const uint32_t mbn = ((c + 1) & 1) ? mb1 : mb0;
            MBAR_EXPECT_TX(mbn, STAGEB);
            CP_BULK(stn, Asrc + (size_t)(c + 1) * XBLK, XBLK, mbn);
            CP_BULK(stn + XBLK, Bsrc + (size_t)(c + 1) * WBLK, WBLK, mbn);
        }
        mbar_wait((c & 1) ? mb1 : mb0, (c >> 1) & 1);

        const uint32_t st = sb + (c & 1) * STAGEB;
        const uint32_t aP = st;
        const uint32_t bH = st + XBLK;
        const uint32_t bL = st + XBLK + 10240;

#pragma unroll
        for (int kst = 0; kst < 2; ++kst) {
            const int kb = kst * 32 + (lane >> 4) * 16;

            uint32_t a4[2][4];
#pragma unroll
            for (int mt = 0; mt < 2; ++mt) {
                const int arow = warp_m * 32 + mt * 16 + (lane & 15);
                LDSM_X4(a4[mt][0], a4[mt][1], a4[mt][2], a4[mt][3], aP + arow * 80 + kb);
            }

#pragma unroll
            for (int g = 0; g < 2; ++g) {
                uint32_t bh[4][2], bl[4][2];
                const int brow_in = (lane & 7) + ((lane >> 4) << 3);
                const int bkb = kst * 32 + ((lane >> 3) & 1) * 16;
#pragma unroll
                for (int p = 0; p < 2; ++p) {
                    const int nb = warp_n * 64 + g * 32 + p * 16;
                    const uint32_t ba = (nb + brow_in) * 80 + bkb;
                    LDSM_X4(bh[2 * p][0], bh[2 * p][1], bh[2 * p + 1][0], bh[2 * p + 1][1],
                            bH + ba);
                    LDSM_X4(bl[2 * p][0], bl[2 * p][1], bl[2 * p + 1][0], bl[2 * p + 1][1],
                            bL + ba);
                }
#pragma unroll
                for (int mt = 0; mt < 2; ++mt)
#pragma unroll
                    for (int nt = 0; nt < 4; ++nt) {
                        float* cc = acc[mt][g * 4 + nt];
                        MMA_FP16(cc[0], cc[1], cc[2], cc[3],
                                 a4[mt][0], a4[mt][1], a4[mt][2], a4[mt][3],
                                 bh[nt][0], bh[nt][1]);
                        MMA_FP16(cc[0], cc[1], cc[2], cc[3],
                                 a4[mt][0], a4[mt][1], a4[mt][2], a4[mt][3],
                                 bl[nt][0], bl[nt][1]);
                    }
            }
        }
        __syncthreads();
    }

    // epilogue
    if (C != nullptr) {
#pragma unroll
        for (int mt = 0; mt < 2; ++mt) {
            const int rbase = row0 + warp_m * 32 + mt * 16 + (lane >> 2);
#pragma unroll
            for (int nt = 0; nt < 8; ++nt) {
                const int cbase = col0 + warp_n * 64 + nt * 8 + (lane & 3) * 2;
                float v0 = acc[mt][nt][0], v1 = acc[mt][nt][1];
                float v2 = acc[mt][nt][2], v3 = acc[mt][nt][3];
                const float b0 = bias[cbase], b1 = bias[cbase + 1];
                v0 += b0; v1 += b1; v2 += b0; v3 += b1;
                *reinterpret_cast<float2*>(C + (size_t)rbase * N + cbase) = make_float2(v0, v1);
                *reinterpret_cast<float2*>(C + (size_t)(rbase + 8) * N + cbase) = make_float2(v2, v3);
            }
        }
    } else {
        const float scale = (z == 0) ? SCALEq : 1.0f;
        unsigned char* dst = (z == 0) ? qb : (z == 1) ? kp : vp;
#pragma unroll
        for (int mt = 0; mt < 2; ++mt) {
            const int rbase = row0 + warp_m * 32 + mt * 16 + (lane >> 2);
#pragma unroll
            for (int nt = 0; nt < 8; ++nt) {
                const int cbase = col0 + warp_n * 64 + nt * 8 + (lane & 3) * 2;
                store_qkv(dst, z, rbase, cbase,
                          acc[mt][nt][0] * scale, acc[mt][nt][1] * scale);
                store_qkv(dst, z, rbase + 8, cbase,
                          acc[mt][nt][2] * scale, acc[mt][nt][3] * scale);
            }
        }
    }
}

// ---------------------------------------------------------------------------
// Tensor-core flash attention, fp16 2-pass, bulk-copy fed.
// S = Qh(fp16) @ (Kh+Kl);  O += Ph(fp16) @ (Vh+Vl).
// ---------------------------------------------------------------------------
#define FBQ 128
#define FBK 64
#define FROWB 144
#define FQ_TILE (FBQ * FROWB)               // 18432 (single fp16 plane)
#define FKV_TILE (FBK * FROWB)              // 9216
#define F_ST FQ_TILE                        // 18432
#define F_STAGE (4 * FKV_TILE)              // 36864 (Kh Kl Vh Vl)
#define FLASH_SMEM (F_ST + 2 * F_STAGE + 32)

__global__ __launch_bounds__(256, 2) void flash_mma_kernel(
    const unsigned char* __restrict__ maskp,
    const unsigned char* __restrict__ qb,
    const unsigned char* __restrict__ kp,
    const unsigned char* __restrict__ vp,
    unsigned char* __restrict__ ap)
{
    extern __shared__ char smem[];
    const uint32_t sb = smem_u32(smem);
    const uint32_t mbQ = sb + F_ST + 2 * F_STAGE;
    const uint32_t mbK0 = mbQ + 8;
    const uint32_t mbK1 = mbQ + 16;

    const int tid  = threadIdx.x;
    const int wid  = tid >> 5;
    const int lane = tid & 31;
    const int qt = blockIdx.x;
    const int h  = blockIdx.y;
    const int b  = blockIdx.z;

    const unsigned char* qsrc = qb + ((size_t)((b * Hq + h) * 16 + qt)) * QBLK;
    const unsigned char* kbase = kp + ((size_t)((b * Hq + h) * 32)) * KVBLK;
    const unsigned char* vbase = vp + ((size_t)((b * Hq + h) * 32)) * KVBLK;
    const unsigned char* mbase = maskp + ((size_t)((b * 16 + qt) * 32)) * MBLK + tid * 64;

    if (tid == 0) { MBAR_INIT(mbQ, 1); MBAR_INIT(mbK0, 1); MBAR_INIT(mbK1, 1); }
    __syncthreads();

    if (tid == 0) {
        MBAR_EXPECT_TX(mbQ, FQ_TILE);
        CP_BULK(sb, qsrc, FQ_TILE, mbQ);
        MBAR_EXPECT_TX(mbK0, F_STAGE);
        CP_BULK(sb + F_ST, kbase, KVBLK, mbK0);
        CP_BULK(sb + F_ST + KVBLK, vbase, KVBLK, mbK0);
    }

    float o[8][4];
#pragma unroll
    for (int t = 0; t < 8; ++t)
#pragma unroll
        for (int j = 0; j < 4; ++j) o[t][j] = 0.0f;
    float m0 = -1e30f, m1 = -1e30f, l0 = 0.0f, l1 = 0.0f;

    const int r0g = qt * FBQ + wid * 16 + (lane >> 2);
    const int quadcol = (lane & 3) * 2;

    mbar_wait(mbQ, 0);

    const int chunks = Tq / FBK;   // 32
    for (int c = 0; c < chunks; ++c) {
        if (c + 1 < chunks && tid == 0) {
            const uint32_t stn = sb + F_ST + ((c + 1) & 1) * F_STAGE;
            const uint32_t mbn = ((c + 1) & 1) ? mbK1 : mbK0;
            MBAR_EXPECT_TX(mbn, F_STAGE);
            CP_BULK(stn, kbase + (size_t)(c + 1) * KVBLK, KVBLK, mbn);
            CP_BULK(stn + KVBLK, vbase + (size_t)(c + 1) * KVBLK, KVBLK, mbn);
        }
        mbar_wait((c & 1) ? mbK1 : mbK0, (c >> 1) & 1);

        const uint32_t st = sb + F_ST + (c & 1) * F_STAGE;
        const uint32_t kH = st;
        const uint32_t kL = st + FKV_TILE;
        const uint32_t vH = st + 2 * FKV_TILE;
        const uint32_t vL = st + 3 * FKV_TILE;

        // ---- S = Qh (Kh + Kl)  (fp16, 2 passes) ----
        float s[8][4];
#pragma unroll
        for (int t = 0; t < 8; ++t)
#pragma unroll
            for (int j = 0; j < 4; ++j) s[t][j] = 0.0f;

        const int brow_in = (lane & 7) + ((lane >> 4) << 3);
#pragma unroll
        for (int kk = 0; kk < 4; ++kk) {
            uint32_t q4[4];
            const uint32_t qa = sb + (wid * 16 + (lane & 15)) * FROWB
                              + kk * 32 + (lane >> 4) * 16;
            LDSM_X4(q4[0], q4[1], q4[2], q4[3], qa);

            const int bkb = kk * 32 + ((lane >> 3) & 1) * 16;
#pragma unroll
            for (int p = 0; p < 4; ++p) {
                uint32_t bh[2][2], bl[2][2];
                const uint32_t ba = (p * 16 + brow_in) * FROWB + bkb;
                LDSM_X4(bh[0][0], bh[0][1], bh[1][0], bh[1][1], kH + ba);
                LDSM_X4(bl[0][0], bl[0][1], bl[1][0], bl[1][1], kL + ba);
#pragma unroll
                for (int u = 0; u < 2; ++u) {
                    float* cc = s[2 * p + u];
                    MMA_FP16(cc[0], cc[1], cc[2], cc[3],
                             q4[0], q4[1], q4[2], q4[3], bh[u][0], bh[u][1]);
                    MMA_FP16(cc[0], cc[1], cc[2], cc[3],
                             q4[0], q4[1], q4[2], q4[3], bl[u][0], bl[u][1]);
                }
            }
        }

        // ---- mask (permuted bf16) + online softmax ----
        {
            const uint4* mp = reinterpret_cast<const uint4*>(mbase + (size_t)c * MBLK);
            uint32_t mu[16];
#pragma unroll
            for (int i = 0; i < 4; ++i) {
                uint4 q = mp[i];
                mu[4 * i + 0] = q.x; mu[4 * i + 1] = q.y;
                mu[4 * i + 2] = q.z; mu[4 * i + 3] = q.w;
            }
#pragma unroll
            for (int t = 0; t < 8; ++t) {
                float2 lo2 = __bfloat1622float2(
                    *reinterpret_cast<__nv_bfloat162*>(&mu[2 * t]));
                float2 hi2 = __bfloat1622float2(
                    *reinterpret_cast<__nv_bfloat162*>(&mu[2 * t + 1]));
                s[t][0] += lo2.x; s[t][1] += lo2.y;
                s[t][2] += hi2.x; s[t][3] += hi2.y;
            }
        }

        float mx0 = -1e30f, mx1 = -1e30f;
#pragma unroll
        for (int t = 0; t < 8; ++t) {
            mx0 = fmaxf(mx0, fmaxf(s[t][0], s[t][1]));
            mx1 = fmaxf(mx1, fmaxf(s[t][2], s[t][3]));
        }
        mx0 = fmaxf(mx0, __shfl_xor_sync(0xffffffffu, mx0, 1));
        mx0 = fmaxf(mx0, __shfl_xor_sync(0xffffffffu, mx0, 2));
        mx1 = fmaxf(mx1, __shfl_xor_sync(0xffffffffu, mx1, 1));
        mx1 = fmaxf(mx1, __shfl_xor_sync(0xffffffffu, mx1, 2));

        const float mn0 = fmaxf(m0, mx0);
        const float mn1 = fmaxf(m1, mx1);
        const float a0 = __expf(m0 - mn0);
        const float a1 = __expf(m1 - mn1);
        m0 = mn0; m1 = mn1;

        float sum0 = 0.0f, sum1 = 0.0f;
#pragma unroll
        for (int t = 0; t < 8; ++t) {
            s[t][0] = __expf(s[t][0] - mn0);
            s[t][1] = __expf(s[t][1] - mn0);
            s[t][2] = __expf(s[t][2] - mn1);
            s[t][3] = __expf(s[t][3] - mn1);
            sum0 += s[t][0] + s[t][1];
            sum1 += s[t][2] + s[t][3];
        }
        sum0 += __shfl_xor_sync(0xffffffffu, sum0, 1);
        sum0 += __shfl_xor_sync(0xffffffffu, sum0, 2);
        sum1 += __shfl_xor_sync(0xffffffffu, sum1, 1);
        sum1 += __shfl_xor_sync(0xffffffffu, sum1, 2);
        l0 = l0 * a0 + sum0;
        l1 = l1 * a1 + sum1;

#pragma unroll
        for (int t = 0; t < 8; ++t) {
            o[t][0] *= a0; o[t][1] *= a0;
            o[t][2] *= a1; o[t][3] *= a1;
        }

        // ---- P fragments (fp16, single plane) ----
        uint32_t pH[4][4];
#pragma unroll
        for (int j = 0; j < 4; ++j) {
#pragma unroll
            for (int u = 0; u < 2; ++u) {
#pragma unroll
                for (int w = 0; w < 2; ++w) {
                    __half2 hh = __float22half2_rn(make_float2(
                        s[2 * j + w][2 * u + 0], s[2 * j + w][2 * u + 1]));
                    pH[j][2 * w + u] = *reinterpret_cast<uint32_t*>(&hh);
                }
            }
        }

        // ---- O += Ph (Vh + Vl)  (fp16, 2 passes) ----
#pragma unroll
        for (int j = 0; j < 4; ++j) {
#pragma unroll
            for (int p = 0; p < 4; ++p) {
                uint32_t vh4[2][2], vl4[2][2];
                const uint32_t va = (j * 16 + (lane & 15)) * FROWB
                                  + p * 32 + (lane >> 4) * 16;
                LDSM_X4_T(vh4[0][0], vh4[0][1], vh4[1][0], vh4[1][1], vH + va);
                LDSM_X4_T(vl4[0][0], vl4[0][1], vl4[1][0], vl4[1][1], vL + va);
#pragma unroll
                for (int u = 0; u < 2; ++u) {
                    float* cc = o[2 * p + u];
                    MMA_FP16(cc[0], cc[1], cc[2], cc[3],
                             pH[j][0], pH[j][1], pH[j][2], pH[j][3],
                             vh4[u][0], vh4[u][1]);
                    MMA_FP16(cc[0], cc[1], cc[2], cc[3],
                             pH[j][0], pH[j][1], pH[j][2], pH[j][3],
                             vl4[u][0], vl4[u][1]);
                }
            }
        }
        __syncthreads();
    }

    // ---- epilogue: normalize, write blocked single fp16 plane A ----
    const float inv0 = 1.0f / l0;
    const float inv1 = 1.0f / l1;
    const int grow = b * Tq + r0g;
#pragma unroll
    for (int t = 0; t < 8; ++t) {
        const int col = h * DHq + t * 8 + quadcol;
        {
            unsigned char* base = ap
                + ((size_t)((grow >> 7) * KCq + (col >> 5))) * XBLK
                + (grow & 127) * 80 + (col & 31) * 2;
            __half2 hh = __float22half2_rn(make_float2(o[t][0] * inv0, o[t][1] * inv0));
            *reinterpret_cast<uint32_t*>(base) = *reinterpret_cast<uint32_t*>(&hh);
        }
        {
            const int grow2 = grow + 8;
            unsigned char* base = ap
                + ((size_t)((grow2 >> 7) * KCq + (col >> 5))) * XBLK
                + (grow2 & 127) * 80 + (col & 31) * 2;
            __half2 hh = __float22half2_rn(make_float2(o[t][2] * inv1, o[t][3] * inv1));
            *reinterpret_cast<uint32_t*>(base) = *reinterpret_cast<uint32_t*>(&hh);
        }
    }
}

// ---------------------------------------------------------------------------
// kernel_launch
// Inputs: x, attention_mask, Wq, Wk, Wv, Wo, bo
// ---------------------------------------------------------------------------
extern "C" void kernel_launch(void* const* d_in, const int* in_sizes, int n_in,
                              void* d_out, int out_size)
{
    (void)in_sizes; (void)n_in; (void)out_size;
    const float* x    = (const float*)d_in[0];
    const float* mask = (const float*)d_in[1];
    const float* Wq   = (const float*)d_in[2];
    const float* Wk   = (const float*)d_in[3];
    const float* Wv   = (const float*)d_in[4];
    const float* Wo   = (const float*)d_in[5];
    const float* bo   = (const float*)d_in[6];
    float* out = (float*)d_out;

    unsigned char *xp, *ap, *w, *qb, *kpb, *vpb, *maskp;
    cudaGetSymbolAddress((void**)&xp, g_xp);
    cudaGetSymbolAddress((void**)&ap, g_ap);
    cudaGetSymbolAddress((void**)&w, g_w);
    cudaGetSymbolAddress((void**)&qb, g_qb);
    cudaGetSymbolAddress((void**)&kpb, g_kp);
    cudaGetSymbolAddress((void**)&vpb, g_vp);
    cudaGetSymbolAddress((void**)&maskp, g_maskp);

    const int M = Bq * Tq;     // 8192
    const int N = INNERq;      // 1024
    const int K = Dq;          // 1024
    const int nx = M * K;

    // conversions -> blocked layouts
    split_kernel<<<nx / (256 * 4), 256>>>(x, xp);
    dim3 tGrid(N / 32, K / 32), tBlk(32, 8);
    tsplit_kernel<<<tGrid, tBlk>>>(Wq, w + 0 * WPAIR_BYTES, K, N);
    tsplit_kernel<<<tGrid, tBlk>>>(Wk, w + 1 * WPAIR_BYTES, K, N);
    tsplit_kernel<<<tGrid, tBlk>>>(Wv, w + 2 * WPAIR_BYTES, K, N);
    tsplit_kernel<<<tGrid, tBlk>>>(Wo, w + 3 * WPAIR_BYTES, K, N);
    dim3 mGrid(32, 16, Bq);
    mask_permute<<<mGrid, 256>>>(mask, maskp);

    // Q,K,V projections (one launch, bulk-fed, fp16 2-pass)
    cudaFuncSetAttribute(gemm_bulk_kernel,
                         cudaFuncAttributeMaxDynamicSharedMemorySize, GEMM_SMEM);
    dim3 qkvGrid(N / GBN, M / GBM, 3);
    gemm_bulk_kernel<<<qkvGrid, 256, GEMM_SMEM>>>(xp, w, qb, kpb, vpb,
                                                  nullptr, nullptr, M, N, K);

    // flash attention (fp16 2-pass, bulk-fed) -> blocked A plane
    cudaFuncSetAttribute(flash_mma_kernel,
                         cudaFuncAttributeMaxDynamicSharedMemorySize, FLASH_SMEM);
    dim3 fGrid(Tq / FBQ, Hq, Bq);
    flash_mma_kernel<<<fGrid, 256, FLASH_SMEM>>>(maskp, qb, kpb, vpb, ap);

    // output projection (fp32 + bias, fp16 2-pass)
    dim3 oGrid(N / GBN, M / GBM, 1);
    gemm_bulk_kernel<<<oGrid, 256, GEMM_SMEM>>>(ap, w + 3 * WPAIR_BYTES,
                                                nullptr, nullptr, nullptr,
                                                out, bo, M, Dq, INNERq);
}

// round 11
// speedup vs baseline: 2.6660x; 1.4519x over previous
#include <cuda_runtime.h>
#include <cuda_bf16.h>
#include <cuda_fp16.h>
#include <cstdint>
#include <cstddef>

// ---------------------------------------------------------------------------
// Problem constants
// ---------------------------------------------------------------------------
#define Bq   4
#define Tq   2048
#define Dq   1024
#define Hq   16
#define DHq  64
#define INNERq 1024
#define SCALEq 0.125f     // 64^-0.5

// Blocked-layout sizes (all single fp16 planes now)
#define KCq 32                                   // K chunks (1024/32)
#define XBLK 10240                               // activation (128x32) fp16 plane
#define WBLK 10240                               // weight (128x32) fp16 plane
#define WONE_BYTES ((size_t)8 * 32 * WBLK)       // one weight, blocked
#define XPLANE_BYTES ((size_t)64 * 32 * XBLK)    // x / attn-out, blocked
#define QBLK 18432                               // Q (128x64) fp16 plane
#define KVBLK 9216                               // K or V (64x64) fp16 plane
#define QB_BYTES ((size_t)Bq * Hq * 16 * QBLK)
#define KP_BYTES ((size_t)Bq * Hq * 32 * KVBLK)
#define MBLK 16384                               // permuted bf16 mask tile (128x64)
#define MP_BYTES ((size_t)Bq * 16 * 32 * MBLK)

// ---------------------------------------------------------------------------
// Scratch (device globals; allocation is forbidden)
// ---------------------------------------------------------------------------
__device__ __align__(128) unsigned char g_xp[XPLANE_BYTES];
__device__ __align__(128) unsigned char g_ap[XPLANE_BYTES];
__device__ __align__(128) unsigned char g_w[4 * WONE_BYTES];
__device__ __align__(128) unsigned char g_qb[QB_BYTES];
__device__ __align__(128) unsigned char g_kp[KP_BYTES];
__device__ __align__(128) unsigned char g_vp[KP_BYTES];
__device__ __align__(128) unsigned char g_maskp[MP_BYTES];

// ---------------------------------------------------------------------------
// PTX helpers
// ---------------------------------------------------------------------------
__device__ __forceinline__ uint32_t smem_u32(const void* p) {
    uint32_t a;
    asm("{ .reg .u64 t; cvta.to.shared.u64 t, %1; cvt.u32.u64 %0, t; }" : "=r"(a) : "l"(p));
    return a;
}

#define MBAR_INIT(mbar, cnt) \
    asm volatile("mbarrier.init.shared.b64 [%0], %1;" :: "r"((uint32_t)(mbar)), "r"((uint32_t)(cnt)) : "memory")
#define MBAR_EXPECT_TX(mbar, bytes) \
    asm volatile("mbarrier.arrive.expect_tx.shared.b64 _, [%0], %1;" \
                 :: "r"((uint32_t)(mbar)), "r"((uint32_t)(bytes)) : "memory")
#define CP_BULK(smem_dst, gsrc, bytes, mbar) \
    asm volatile("cp.async.bulk.shared::cluster.global.mbarrier::complete_tx::bytes [%0], [%1], %2, [%3];" \
                 :: "r"((uint32_t)(smem_dst)), "l"(gsrc), "r"((uint32_t)(bytes)), \
                    "r"((uint32_t)(mbar)) : "memory")

__device__ __forceinline__ void mbar_wait(uint32_t mbar, uint32_t parity) {
    asm volatile(
        "{\n\t.reg .pred P;\n\t"
        "WAIT_%=:\n\t"
        "mbarrier.try_wait.parity.acquire.cta.shared::cta.b64 P, [%0], %1, 0x989680;\n\t"
        "@P bra DONE_%=;\n\t"
        "bra WAIT_%=;\n\t"
        "DONE_%=:\n\t}"
        :: "r"(mbar), "r"(parity) : "memory");
}

#define LDSM_X4(r0, r1, r2, r3, addr) \
    asm volatile("ldmatrix.sync.aligned.m8n8.x4.shared.b16 {%0,%1,%2,%3}, [%4];" \
                 : "=r"(r0), "=r"(r1), "=r"(r2), "=r"(r3) : "r"(addr))

#define LDSM_X4_T(r0, r1, r2, r3, addr) \
    asm volatile("ldmatrix.sync.aligned.m8n8.x4.trans.shared.b16 {%0,%1,%2,%3}, [%4];" \
                 : "=r"(r0), "=r"(r1), "=r"(r2), "=r"(r3) : "r"(addr))

#define MMA_FP16(c0, c1, c2, c3, a0, a1, a2, a3, b0, b1) \
    asm volatile("mma.sync.aligned.m16n8k16.row.col.f32.f16.f16.f32 " \
                 "{%0,%1,%2,%3}, {%4,%5,%6,%7}, {%8,%9}, {%0,%1,%2,%3};" \
                 : "+f"(c0), "+f"(c1), "+f"(c2), "+f"(c3) \
                 : "r"(a0), "r"(a1), "r"(a2), "r"(a3), "r"(b0), "r"(b1))

// ---------------------------------------------------------------------------
// x[8192,1024] fp32 -> blocked single fp16 plane
// ---------------------------------------------------------------------------
__global__ __launch_bounds__(256) void split_kernel(
    const float* __restrict__ in, unsigned char* __restrict__ out)
{
    const int i = (blockIdx.x * 256 + threadIdx.x) * 4;
    float4 v = *reinterpret_cast<const float4*>(in + i);
    const int row = i >> 10, col = i & 1023;
    unsigned char* base = out + ((size_t)((row >> 7) * KCq + (col >> 5))) * XBLK
                        + (row & 127) * 80 + (col & 31) * 2;
    __half2 h01 = __float22half2_rn(make_float2(v.x, v.y));
    __half2 h23 = __float22half2_rn(make_float2(v.z, v.w));
    *reinterpret_cast<uint2*>(base) = make_uint2(
        *reinterpret_cast<uint32_t*>(&h01), *reinterpret_cast<uint32_t*>(&h23));
}

// ---------------------------------------------------------------------------
// W[K,N] fp32 -> transposed blocked single fp16 plane (Wt[n][k])
// ---------------------------------------------------------------------------
__global__ __launch_bounds__(256) void tsplit_kernel(
    const float* __restrict__ W, unsigned char* __restrict__ out, int K, int N)
{
    __shared__ float t[32][33];
    const int tx = threadIdx.x, ty = threadIdx.y;
    const int bx = blockIdx.x, by = blockIdx.y;
#pragma unroll
    for (int j = 0; j < 32; j += 8)
        t[ty + j][tx] = W[(size_t)(by * 32 + ty + j) * N + bx * 32 + tx];
    __syncthreads();
#pragma unroll
    for (int j = 0; j < 32; j += 8) {
        float v = t[tx][ty + j];
        const int n = bx * 32 + ty + j;
        const int k = by * 32 + tx;
        unsigned char* base = out + ((size_t)((n >> 7) * KCq + (k >> 5))) * WBLK
                            + (n & 127) * 80 + (k & 31) * 2;
        *reinterpret_cast<__half*>(base) = __float2half_rn(v);
    }
}

// ---------------------------------------------------------------------------
// Mask permute: fp32 [B,1,T,T] -> bf16, consumer-ordered per (b,qtile,chunk,tid)
// ---------------------------------------------------------------------------
__global__ __launch_bounds__(256) void mask_permute(
    const float* __restrict__ mask, unsigned char* __restrict__ out)
{
    __shared__ float tile[128 * 64];
    const int b = blockIdx.z, qt = blockIdx.y, ch = blockIdx.x;
    const int tid = threadIdx.x;
    const float* src = mask + ((size_t)b * Tq + qt * 128) * Tq + ch * 64;
    for (int i = tid; i < 2048; i += 256) {
        const int row = i >> 4, c4 = (i & 15) * 4;
        float4 v = *reinterpret_cast<const float4*>(src + (size_t)row * Tq + c4);
        tile[row * 64 + c4 + 0] = v.x;
        tile[row * 64 + c4 + 1] = v.y;
        tile[row * 64 + c4 + 2] = v.z;
        tile[row * 64 + c4 + 3] = v.w;
    }
    __syncthreads();
    const int wid = tid >> 5, lane = tid & 31;
    const int r0 = wid * 16 + (lane >> 2);
    const int cb = (lane & 3) * 2;
    uint32_t outv[16];
#pragma unroll
    for (int t = 0; t < 8; ++t)
#pragma unroll
        for (int u = 0; u < 2; ++u) {
            const int row = r0 + u * 8;
            const int c = t * 8 + cb;
            __nv_bfloat162 p = __float22bfloat162_rn(
                make_float2(tile[row * 64 + c], tile[row * 64 + c + 1]));
            outv[t * 2 + u] = *reinterpret_cast<uint32_t*>(&p);
        }
    uint4* dst = reinterpret_cast<uint4*>(
        out + ((size_t)((b * 16 + qt) * 32 + ch)) * MBLK + tid * 64);
#pragma unroll
    for (int i = 0; i < 4; ++i)
        dst[i] = make_uint4(outv[4 * i], outv[4 * i + 1], outv[4 * i + 2], outv[4 * i + 3]);
}

// ---------------------------------------------------------------------------
// bulk-copy GEMM (pure fp16): C = Ah @ Bh^T.
// A, B: blocked single fp16 planes.
// QKV mode (C==null): z picks weight; epilogue -> fp16 blocked Q/K/V.
// O mode: fp32 C + bias.
// ---------------------------------------------------------------------------
#define GBM 128
#define GBN 128
#define GBK 32
#define STAGEB (XBLK + WBLK)          // 20480: A | B
#define GEMM_SMEM (2 * STAGEB + 16)

__device__ __forceinline__ void store_qkv(unsigned char* dst, int z, int row, int col,
                                          float v0, float v1) {
    const int b = row >> 11, tok = row & 2047;
    const int h = col >> 6, dh = col & 63;
    size_t off;
    if (z == 0) {
        off = ((size_t)((b * Hq + h) * 16 + (tok >> 7))) * QBLK
            + (size_t)(tok & 127) * 144 + dh * 2;
    } else {
        off = ((size_t)((b * Hq + h) * 32 + (tok >> 6))) * KVBLK
            + (size_t)(tok & 63) * 144 + dh * 2;
    }
    __half2 hh = __float22half2_rn(make_float2(v0, v1));
    *reinterpret_cast<uint32_t*>(dst + off) = *reinterpret_cast<uint32_t*>(&hh);
}

__global__ __launch_bounds__(256, 2) void gemm_bulk_kernel(
    const unsigned char* __restrict__ Aplane, const unsigned char* __restrict__ Wb,
    unsigned char* __restrict__ qb, unsigned char* __restrict__ kp,
    unsigned char* __restrict__ vp,
    float* __restrict__ C, const float* __restrict__ bias,
    int M, int N, int K)
{
    extern __shared__ char smem[];
    const uint32_t sb = smem_u32(smem);
    const uint32_t mb0 = sb + 2 * STAGEB;
    const uint32_t mb1 = mb0 + 8;

    const int tid = threadIdx.x;
    const int wid = tid >> 5;
    const int lane = tid & 31;
    const int warp_m = wid >> 1;
    const int warp_n = wid & 1;
    const int row0 = blockIdx.y * GBM;
    const int col0 = blockIdx.x * GBN;
    const int z = blockIdx.z;
    const int KC = K / GBK;

    const unsigned char* Asrc = Aplane + ((size_t)blockIdx.y * KC) * XBLK;
    const unsigned char* Bsrc = (C == nullptr ? Wb + (size_t)z * WONE_BYTES : Wb)
                              + ((size_t)blockIdx.x * KC) * WBLK;

    if (tid == 0) { MBAR_INIT(mb0, 1); MBAR_INIT(mb1, 1); }
    __syncthreads();

    if (tid == 0) {
        MBAR_EXPECT_TX(mb0, STAGEB);
        CP_BULK(sb, Asrc, XBLK, mb0);
        CP_BULK(sb + XBLK, Bsrc, WBLK, mb0);
    }

    float acc[2][8][4];
#pragma unroll
    for (int i = 0; i < 2; ++i)
#pragma unroll
        for (int j = 0; j < 8; ++j)
#pragma unroll
            for (int q = 0; q < 4; ++q) acc[i][j][q] = 0.0f;

    for (int c = 0; c < KC; ++c) {
        if (c + 1 < KC && tid == 0) {
            const uint32_t stn = sb + ((c + 1) & 1) * STAGEB;
            const uint32_t mbn = ((c + 1) & 1) ? mb1 : mb0;
            MBAR_EXPECT_TX(mbn, STAGEB);
            CP_BULK(stn, Asrc + (size_t)(c + 1) * XBLK, XBLK, mbn);
            CP_BULK(stn + XBLK, Bsrc + (size_t)(c + 1) * WBLK, WBLK, mbn);
        }
        mbar_wait((c & 1) ? mb1 : mb0, (c >> 1) & 1);

        const uint32_t st = sb + (c & 1) * STAGEB;
        const uint32_t aP = st;
        const uint32_t bP = st + XBLK;

#pragma unroll
        for (int kst = 0; kst < 2; ++kst) {
            const int kb = kst * 32 + (lane >> 4) * 16;

            uint32_t a4[2][4];
#pragma unroll
            for (int mt = 0; mt < 2; ++mt) {
                const int arow = warp_m * 32 + mt * 16 + (lane & 15);
                LDSM_X4(a4[mt][0], a4[mt][1], a4[mt][2], a4[mt][3], aP + arow * 80 + kb);
            }

#pragma unroll
            for (int g = 0; g < 2; ++g) {
                uint32_t b4[4][2];
                const int brow_in = (lane & 7) + ((lane >> 4) << 3);
                const int bkb = kst * 32 + ((lane >> 3) & 1) * 16;
#pragma unroll
                for (int p = 0; p < 2; ++p) {
                    const int nb = warp_n * 64 + g * 32 + p * 16;
                    const uint32_t ba = (nb + brow_in) * 80 + bkb;
                    LDSM_X4(b4[2 * p][0], b4[2 * p][1], b4[2 * p + 1][0], b4[2 * p + 1][1],
                            bP + ba);
                }
#pragma unroll
                for (int mt = 0; mt < 2; ++mt)
#pragma unroll
                    for (int nt = 0; nt < 4; ++nt) {
                        float* cc = acc[mt][g * 4 + nt];
                        MMA_FP16(cc[0], cc[1], cc[2], cc[3],
                                 a4[mt][0], a4[mt][1], a4[mt][2], a4[mt][3],
                                 b4[nt][0], b4[nt][1]);
                    }
            }
        }
        __syncthreads();
    }

    // epilogue
    if (C != nullptr) {
#pragma unroll
        for (int mt = 0; mt < 2; ++mt) {
            const int rbase = row0 + warp_m * 32 + mt * 16 + (lane >> 2);
#pragma unroll
            for (int nt = 0; nt < 8; ++nt) {
                const int cbase = col0 + warp_n * 64 + nt * 8 + (lane & 3) * 2;
                float v0 = acc[mt][nt][0], v1 = acc[mt][nt][1];
                float v2 = acc[mt][nt][2], v3 = acc[mt][nt][3];
                const float b0 = bias[cbase], b1 = bias[cbase + 1];
                v0 += b0; v1 += b1; v2 += b0; v3 += b1;
                *reinterpret_cast<float2*>(C + (size_t)rbase * N + cbase) = make_float2(v0, v1);
                *reinterpret_cast<float2*>(C + (size_t)(rbase + 8) * N + cbase) = make_float2(v2, v3);
            }
        }
    } else {
        const float scale = (z == 0) ? SCALEq : 1.0f;
        unsigned char* dst = (z == 0) ? qb : (z == 1) ? kp : vp;
#pragma unroll
        for (int mt = 0; mt < 2; ++mt) {
            const int rbase = row0 + warp_m * 32 + mt * 16 + (lane >> 2);
#pragma unroll
            for (int nt = 0; nt < 8; ++nt) {
                const int cbase = col0 + warp_n * 64 + nt * 8 + (lane & 3) * 2;
                store_qkv(dst, z, rbase, cbase,
                          acc[mt][nt][0] * scale, acc[mt][nt][1] * scale);
                store_qkv(dst, z, rbase + 8, cbase,
                          acc[mt][nt][2] * scale, acc[mt][nt][3] * scale);
            }
        }
    }
}

// ---------------------------------------------------------------------------
// Tensor-core flash attention, pure fp16, bulk-copy fed.
// S = Q @ K;  O += P @ V.  64 MMA/warp/chunk.
// ---------------------------------------------------------------------------
#define FBQ 128
#define FBK 64
#define FROWB 144
#define FQ_TILE (FBQ * FROWB)               // 18432
#define FKV_TILE (FBK * FROWB)              // 9216
#define F_ST FQ_TILE                        // 18432
#define F_STAGE (2 * FKV_TILE)              // 18432 (K | V)
#define FLASH_SMEM (F_ST + 2 * F_STAGE + 32)

__global__ __launch_bounds__(256, 2) void flash_mma_kernel(
    const unsigned char* __restrict__ maskp,
    const unsigned char* __restrict__ qb,
    const unsigned char* __restrict__ kp,
    const unsigned char* __restrict__ vp,
    unsigned char* __restrict__ ap)
{
    extern __shared__ char smem[];
    const uint32_t sb = smem_u32(smem);
    const uint32_t mbQ = sb + F_ST + 2 * F_STAGE;
    const uint32_t mbK0 = mbQ + 8;
    const uint32_t mbK1 = mbQ + 16;

    const int tid  = threadIdx.x;
    const int wid  = tid >> 5;
    const int lane = tid & 31;
    const int qt = blockIdx.x;
    const int h  = blockIdx.y;
    const int b  = blockIdx.z;

    const unsigned char* qsrc = qb + ((size_t)((b * Hq + h) * 16 + qt)) * QBLK;
    const unsigned char* kbase = kp + ((size_t)((b * Hq + h) * 32)) * KVBLK;
    const unsigned char* vbase = vp + ((size_t)((b * Hq + h) * 32)) * KVBLK;
    const unsigned char* mbase = maskp + ((size_t)((b * 16 + qt) * 32)) * MBLK + tid * 64;

    if (tid == 0) { MBAR_INIT(mbQ, 1); MBAR_INIT(mbK0, 1); MBAR_INIT(mbK1, 1); }
    __syncthreads();

    if (tid == 0) {
        MBAR_EXPECT_TX(mbQ, FQ_TILE);
        CP_BULK(sb, qsrc, FQ_TILE, mbQ);
        MBAR_EXPECT_TX(mbK0, F_STAGE);
        CP_BULK(sb + F_ST, kbase, KVBLK, mbK0);
        CP_BULK(sb + F_ST + KVBLK, vbase, KVBLK, mbK0);
    }

    float o[8][4];
#pragma unroll
    for (int t = 0; t < 8; ++t)
#pragma unroll
        for (int j = 0; j < 4; ++j) o[t][j] = 0.0f;
    float m0 = -1e30f, m1 = -1e30f, l0 = 0.0f, l1 = 0.0f;

    const int r0g = qt * FBQ + wid * 16 + (lane >> 2);
    const int quadcol = (lane & 3) * 2;

    mbar_wait(mbQ, 0);

    const int chunks = Tq / FBK;   // 32
    for (int c = 0; c < chunks; ++c) {
        if (c + 1 < chunks && tid == 0) {
            const uint32_t stn = sb + F_ST + ((c + 1) & 1) * F_STAGE;
            const uint32_t mbn = ((c + 1) & 1) ? mbK1 : mbK0;
            MBAR_EXPECT_TX(mbn, F_STAGE);
            CP_BULK(stn, kbase + (size_t)(c + 1) * KVBLK, KVBLK, mbn);
            CP_BULK(stn + KVBLK, vbase + (size_t)(c + 1) * KVBLK, KVBLK, mbn);
        }
        mbar_wait((c & 1) ? mbK1 : mbK0, (c >> 1) & 1);

        const uint32_t st = sb + F_ST + (c & 1) * F_STAGE;
        const uint32_t kP = st;
        const uint32_t vP = st + FKV_TILE;

        // ---- S = Q @ K^T (fp16, 1 pass) ----
        float s[8][4];
#pragma unroll
        for (int t = 0; t < 8; ++t)
#pragma unroll
            for (int j = 0; j < 4; ++j) s[t][j] = 0.0f;

        const int brow_in = (lane & 7) + ((lane >> 4) << 3);
#pragma unroll
        for (int kk = 0; kk < 4; ++kk) {
            uint32_t q4[4];
            const uint32_t qa = sb + (wid * 16 + (lane & 15)) * FROWB
                              + kk * 32 + (lane >> 4) * 16;
            LDSM_X4(q4[0], q4[1], q4[2], q4[3], qa);

            const int bkb = kk * 32 + ((lane >> 3) & 1) * 16;
#pragma unroll
            for (int p = 0; p < 4; ++p) {
                uint32_t b4[2][2];
                const uint32_t ba = (p * 16 + brow_in) * FROWB + bkb;
                LDSM_X4(b4[0][0], b4[0][1], b4[1][0], b4[1][1], kP + ba);
#pragma unroll
                for (int u = 0; u < 2; ++u) {
                    float* cc = s[2 * p + u];
                    MMA_FP16(cc[0], cc[1], cc[2], cc[3],
                             q4[0], q4[1], q4[2], q4[3], b4[u][0], b4[u][1]);
                }
            }
        }

        // ---- mask (permuted bf16) + online softmax ----
        {
            const uint4* mp = reinterpret_cast<const uint4*>(mbase + (size_t)c * MBLK);
            uint32_t mu[16];
#pragma unroll
            for (int i = 0; i < 4; ++i) {
                uint4 q = mp[i];
                mu[4 * i + 0] = q.x; mu[4 * i + 1] = q.y;
                mu[4 * i + 2] = q.z; mu[4 * i + 3] = q.w;
            }
#pragma unroll
            for (int t = 0; t < 8; ++t) {
                float2 lo2 = __bfloat1622float2(
                    *reinterpret_cast<__nv_bfloat162*>(&mu[2 * t]));
                float2 hi2 = __bfloat1622float2(
                    *reinterpret_cast<__nv_bfloat162*>(&mu[2 * t + 1]));
                s[t][0] += lo2.x; s[t][1] += lo2.y;
                s[t][2] += hi2.x; s[t][3] += hi2.y;
            }
        }

        float mx0 = -1e30f, mx1 = -1e30f;
#pragma unroll
        for (int t = 0; t < 8; ++t) {
            mx0 = fmaxf(mx0, fmaxf(s[t][0], s[t][1]));
            mx1 = fmaxf(mx1, fmaxf(s[t][2], s[t][3]));
        }
        mx0 = fmaxf(mx0, __shfl_xor_sync(0xffffffffu, mx0, 1));
        mx0 = fmaxf(mx0, __shfl_xor_sync(0xffffffffu, mx0, 2));
        mx1 = fmaxf(mx1, __shfl_xor_sync(0xffffffffu, mx1, 1));
        mx1 = fmaxf(mx1, __shfl_xor_sync(0xffffffffu, mx1, 2));

        const float mn0 = fmaxf(m0, mx0);
        const float mn1 = fmaxf(m1, mx1);
        const float a0 = __expf(m0 - mn0);
        const float a1 = __expf(m1 - mn1);
        m0 = mn0; m1 = mn1;

        float sum0 = 0.0f, sum1 = 0.0f;
#pragma unroll
        for (int t = 0; t < 8; ++t) {
            s[t][0] = __expf(s[t][0] - mn0);
            s[t][1] = __expf(s[t][1] - mn0);
            s[t][2] = __expf(s[t][2] - mn1);
            s[t][3] = __expf(s[t][3] - mn1);
            sum0 += s[t][0] + s[t][1];
            sum1 += s[t][2] + s[t][3];
        }
        sum0 += __shfl_xor_sync(0xffffffffu, sum0, 1);
        sum0 += __shfl_xor_sync(0xffffffffu, sum0, 2);
        sum1 += __shfl_xor_sync(0xffffffffu, sum1, 1);
        sum1 += __shfl_xor_sync(0xffffffffu, sum1, 2);
        l0 = l0 * a0 + sum0;
        l1 = l1 * a1 + sum1;

#pragma unroll
        for (int t = 0; t < 8; ++t) {
            o[t][0] *= a0; o[t][1] *= a0;
            o[t][2] *= a1; o[t][3] *= a1;
        }

        // ---- P fragments (fp16) ----
        uint32_t pH[4][4];
#pragma unroll
        for (int j = 0; j < 4; ++j) {
#pragma unroll
            for (int u = 0; u < 2; ++u) {
#pragma unroll
                for (int w = 0; w < 2; ++w) {
                    __half2 hh = __float22half2_rn(make_float2(
                        s[2 * j + w][2 * u + 0], s[2 * j + w][2 * u + 1]));
                    pH[j][2 * w + u] = *reinterpret_cast<uint32_t*>(&hh);
                }
            }
        }

        // ---- O += P @ V (fp16, 1 pass) ----
#pragma unroll
        for (int j = 0; j < 4; ++j) {
#pragma unroll
            for (int p = 0; p < 4; ++p) {
                uint32_t v4[2][2];
                const uint32_t va = (j * 16 + (lane & 15)) * FROWB
                                  + p * 32 + (lane >> 4) * 16;
                LDSM_X4_T(v4[0][0], v4[0][1], v4[1][0], v4[1][1], vP + va);
#pragma unroll
                for (int u = 0; u < 2; ++u) {
                    float* cc = o[2 * p + u];
                    MMA_FP16(cc[0], cc[1], cc[2], cc[3],
                             pH[j][0], pH[j][1], pH[j][2], pH[j][3],
                             v4[u][0], v4[u][1]);
                }
            }
        }
        __syncthreads();
    }

    // ---- epilogue: normalize, write blocked single fp16 plane A ----
    const float inv0 = 1.0f / l0;
    const float inv1 = 1.0f / l1;
    const int grow = b * Tq + r0g;
#pragma unroll
    for (int t = 0; t < 8; ++t) {
        const int col = h * DHq + t * 8 + quadcol;
        {
            unsigned char* base = ap
                + ((size_t)((grow >> 7) * KCq + (col >> 5))) * XBLK
                + (grow & 127) * 80 + (col & 31) * 2;
            __half2 hh = __float22half2_rn(make_float2(o[t][0] * inv0, o[t][1] * inv0));
            *reinterpret_cast<uint32_t*>(base) = *reinterpret_cast<uint32_t*>(&hh);
        }
        {
            const int grow2 = grow + 8;
            unsigned char* base = ap
                + ((size_t)((grow2 >> 7) * KCq + (col >> 5))) * XBLK
                + (grow2 & 127) * 80 + (col & 31) * 2;
            __half2 hh = __float22half2_rn(make_float2(o[t][2] * inv1, o[t][3] * inv1));
            *reinterpret_cast<uint32_t*>(base) = *reinterpret_cast<uint32_t*>(&hh);
        }
    }
}

// ---------------------------------------------------------------------------
// kernel_launch
// Inputs: x, attention_mask, Wq, Wk, Wv, Wo, bo
// ---------------------------------------------------------------------------
extern "C" void kernel_launch(void* const* d_in, const int* in_sizes, int n_in,
                              void* d_out, int out_size)
{
    (void)in_sizes; (void)n_in; (void)out_size;
    const float* x    = (const float*)d_in[0];
    const float* mask = (const float*)d_in[1];
    const float* Wq   = (const float*)d_in[2];
    const float* Wk   = (const float*)d_in[3];
    const float* Wv   = (const float*)d_in[4];
    const float* Wo   = (const float*)d_in[5];
    const float* bo   = (const float*)d_in[6];
    float* out = (float*)d_out;

    unsigned char *xp, *ap, *w, *qb, *kpb, *vpb, *maskp;
    cudaGetSymbolAddress((void**)&xp, g_xp);
    cudaGetSymbolAddress((void**)&ap, g_ap);
    cudaGetSymbolAddress((void**)&w, g_w);
    cudaGetSymbolAddress((void**)&qb, g_qb);
    cudaGetSymbolAddress((void**)&kpb, g_kp);
    cudaGetSymbolAddress((void**)&vpb, g_vp);
    cudaGetSymbolAddress((void**)&maskp, g_maskp);

    const int M = Bq * Tq;     // 8192
    const int N = INNERq;      // 1024
    const int K = Dq;          // 1024
    const int nx = M * K;

    // conversions -> blocked layouts
    split_kernel<<<nx / (256 * 4), 256>>>(x, xp);
    dim3 tGrid(N / 32, K / 32), tBlk(32, 8);
    tsplit_kernel<<<tGrid, tBlk>>>(Wq, w + 0 * WONE_BYTES, K, N);
    tsplit_kernel<<<tGrid, tBlk>>>(Wk, w + 1 * WONE_BYTES, K, N);
    tsplit_kernel<<<tGrid, tBlk>>>(Wv, w + 2 * WONE_BYTES, K, N);
    tsplit_kernel<<<tGrid, tBlk>>>(Wo, w + 3 * WONE_BYTES, K, N);
    dim3 mGrid(32, 16, Bq);
    mask_permute<<<mGrid, 256>>>(mask, maskp);

    // Q,K,V projections (one launch, bulk-fed, pure fp16)
    cudaFuncSetAttribute(gemm_bulk_kernel,
                         cudaFuncAttributeMaxDynamicSharedMemorySize, GEMM_SMEM);
    dim3 qkvGrid(N / GBN, M / GBM, 3);
    gemm_bulk_kernel<<<qkvGrid, 256, GEMM_SMEM>>>(xp, w, qb, kpb, vpb,
                                                  nullptr, nullptr, M, N, K);

    // flash attention (pure fp16, bulk-fed) -> blocked A plane
    cudaFuncSetAttribute(flash_mma_kernel,
                         cudaFuncAttributeMaxDynamicSharedMemorySize, FLASH_SMEM);
    dim3 fGrid(Tq / FBQ, Hq, Bq);
    flash_mma_kernel<<<fGrid, 256, FLASH_SMEM>>>(maskp, qb, kpb, vpb, ap);

    // output projection (fp32 + bias, pure fp16)
    dim3 oGrid(N / GBN, M / GBM, 1);
    gemm_bulk_kernel<<<oGrid, 256, GEMM_SMEM>>>(ap, w + 3 * WONE_BYTES,
                                                nullptr, nullptr, nullptr,
                                                out, bo, M, Dq, INNERq);
}

// round 12
// speedup vs baseline: 2.7106x; 1.0167x over previous
#include <cuda_runtime.h>
#include <cuda_bf16.h>
#include <cuda_fp16.h>
#include <cstdint>
#include <cstddef>

// ---------------------------------------------------------------------------
// Problem constants
// ---------------------------------------------------------------------------
#define Bq   4
#define Tq   2048
#define Dq   1024
#define Hq   16
#define DHq  64
#define INNERq 1024
#define SCALEq 0.125f     // 64^-0.5

// Blocked-layout sizes (all single fp16 planes)
#define KCq 32                                   // 32-col blocks per 1024-K row panel
#define XBLK 10240                               // activation (128x32) fp16 plane
#define WBLK 10240                               // weight (128x32) fp16 plane
#define WONE_BYTES ((size_t)8 * 32 * WBLK)       // one weight, blocked
#define XPLANE_BYTES ((size_t)64 * 32 * XBLK)    // x / attn-out, blocked
#define QBLK 18432                               // Q (128x64) fp16 plane
#define KVBLK 9216                               // K or V (64x64) fp16 plane
#define QB_BYTES ((size_t)Bq * Hq * 16 * QBLK)
#define KP_BYTES ((size_t)Bq * Hq * 32 * KVBLK)
#define MBLK 16384                               // permuted bf16 mask tile (128x64)
#define MP_BYTES ((size_t)Bq * 16 * 32 * MBLK)

// ---------------------------------------------------------------------------
// Scratch (device globals; allocation is forbidden)
// ---------------------------------------------------------------------------
__device__ __align__(128) unsigned char g_xp[XPLANE_BYTES];
__device__ __align__(128) unsigned char g_ap[XPLANE_BYTES];
__device__ __align__(128) unsigned char g_w[4 * WONE_BYTES];
__device__ __align__(128) unsigned char g_qb[QB_BYTES];
__device__ __align__(128) unsigned char g_kp[KP_BYTES];
__device__ __align__(128) unsigned char g_vp[KP_BYTES];
__device__ __align__(128) unsigned char g_maskp[MP_BYTES];

// ---------------------------------------------------------------------------
// PTX helpers
// ---------------------------------------------------------------------------
__device__ __forceinline__ uint32_t smem_u32(const void* p) {
    uint32_t a;
    asm("{ .reg .u64 t; cvta.to.shared.u64 t, %1; cvt.u32.u64 %0, t; }" : "=r"(a) : "l"(p));
    return a;
}

#define MBAR_INIT(mbar, cnt) \
    asm volatile("mbarrier.init.shared.b64 [%0], %1;" :: "r"((uint32_t)(mbar)), "r"((uint32_t)(cnt)) : "memory")
#define MBAR_EXPECT_TX(mbar, bytes) \
    asm volatile("mbarrier.arrive.expect_tx.shared.b64 _, [%0], %1;" \
                 :: "r"((uint32_t)(mbar)), "r"((uint32_t)(bytes)) : "memory")
#define CP_BULK(smem_dst, gsrc, bytes, mbar) \
    asm volatile("cp.async.bulk.shared::cluster.global.mbarrier::complete_tx::bytes [%0], [%1], %2, [%3];" \
                 :: "r"((uint32_t)(smem_dst)), "l"(gsrc), "r"((uint32_t)(bytes)), \
                    "r"((uint32_t)(mbar)) : "memory")

__device__ __forceinline__ void mbar_wait(uint32_t mbar, uint32_t parity) {
    asm volatile(
        "{\n\t.reg .pred P;\n\t"
        "WAIT_%=:\n\t"
        "mbarrier.try_wait.parity.acquire.cta.shared::cta.b64 P, [%0], %1, 0x989680;\n\t"
        "@P bra DONE_%=;\n\t"
        "bra WAIT_%=;\n\t"
        "DONE_%=:\n\t}"
        :: "r"(mbar), "r"(parity) : "memory");
}

#define LDSM_X4(r0, r1, r2, r3, addr) \
    asm volatile("ldmatrix.sync.aligned.m8n8.x4.shared.b16 {%0,%1,%2,%3}, [%4];" \
                 : "=r"(r0), "=r"(r1), "=r"(r2), "=r"(r3) : "r"(addr))

#define LDSM_X4_T(r0, r1, r2, r3, addr) \
    asm volatile("ldmatrix.sync.aligned.m8n8.x4.trans.shared.b16 {%0,%1,%2,%3}, [%4];" \
                 : "=r"(r0), "=r"(r1), "=r"(r2), "=r"(r3) : "r"(addr))

#define MMA_FP16(c0, c1, c2, c3, a0, a1, a2, a3, b0, b1) \
    asm volatile("mma.sync.aligned.m16n8k16.row.col.f32.f16.f16.f32 " \
                 "{%0,%1,%2,%3}, {%4,%5,%6,%7}, {%8,%9}, {%0,%1,%2,%3};" \
                 : "+f"(c0), "+f"(c1), "+f"(c2), "+f"(c3) \
                 : "r"(a0), "r"(a1), "r"(a2), "r"(a3), "r"(b0), "r"(b1))

// ---------------------------------------------------------------------------
// x[8192,1024] fp32 -> blocked single fp16 plane
// ---------------------------------------------------------------------------
__global__ __launch_bounds__(256) void split_kernel(
    const float* __restrict__ in, unsigned char* __restrict__ out)
{
    const int i = (blockIdx.x * 256 + threadIdx.x) * 4;
    float4 v = *reinterpret_cast<const float4*>(in + i);
    const int row = i >> 10, col = i & 1023;
    unsigned char* base = out + ((size_t)((row >> 7) * KCq + (col >> 5))) * XBLK
                        + (row & 127) * 80 + (col & 31) * 2;
    __half2 h01 = __float22half2_rn(make_float2(v.x, v.y));
    __half2 h23 = __float22half2_rn(make_float2(v.z, v.w));
    *reinterpret_cast<uint2*>(base) = make_uint2(
        *reinterpret_cast<uint32_t*>(&h01), *reinterpret_cast<uint32_t*>(&h23));
}

// ---------------------------------------------------------------------------
// All 4 weights in ONE launch: W[K,N] fp32 -> transposed blocked fp16 plane.
// blockIdx.z selects which weight.
// ---------------------------------------------------------------------------
__global__ __launch_bounds__(256) void tsplit_kernel(
    const float* __restrict__ W0, const float* __restrict__ W1,
    const float* __restrict__ W2, const float* __restrict__ W3,
    unsigned char* __restrict__ outbase, int K, int N)
{
    __shared__ float t[32][33];
    const int tx = threadIdx.x, ty = threadIdx.y;
    const int bx = blockIdx.x, by = blockIdx.y, z = blockIdx.z;
    const float* W = (z == 0) ? W0 : (z == 1) ? W1 : (z == 2) ? W2 : W3;
    unsigned char* out = outbase + (size_t)z * WONE_BYTES;
#pragma unroll
    for (int j = 0; j < 32; j += 8)
        t[ty + j][tx] = W[(size_t)(by * 32 + ty + j) * N + bx * 32 + tx];
    __syncthreads();
#pragma unroll
    for (int j = 0; j < 32; j += 8) {
        float v = t[tx][ty + j];
        const int n = bx * 32 + ty + j;
        const int k = by * 32 + tx;
        unsigned char* base = out + ((size_t)((n >> 7) * KCq + (k >> 5))) * WBLK
                            + (n & 127) * 80 + (k & 31) * 2;
        *reinterpret_cast<__half*>(base) = __float2half_rn(v);
    }
}

// ---------------------------------------------------------------------------
// Mask permute: fp32 [B,1,T,T] -> bf16, consumer-ordered per (b,qtile,chunk,tid)
// ---------------------------------------------------------------------------
__global__ __launch_bounds__(256) void mask_permute(
    const float* __restrict__ mask, unsigned char* __restrict__ out)
{
    __shared__ float tile[128 * 64];
    const int b = blockIdx.z, qt = blockIdx.y, ch = blockIdx.x;
    const int tid = threadIdx.x;
    const float* src = mask + ((size_t)b * Tq + qt * 128) * Tq + ch * 64;
    for (int i = tid; i < 2048; i += 256) {
        const int row = i >> 4, c4 = (i & 15) * 4;
        float4 v = *reinterpret_cast<const float4*>(src + (size_t)row * Tq + c4);
        tile[row * 64 + c4 + 0] = v.x;
        tile[row * 64 + c4 + 1] = v.y;
        tile[row * 64 + c4 + 2] = v.z;
        tile[row * 64 + c4 + 3] = v.w;
    }
    __syncthreads();
    const int wid = tid >> 5, lane = tid & 31;
    const int r0 = wid * 16 + (lane >> 2);
    const int cb = (lane & 3) * 2;
    uint32_t outv[16];
#pragma unroll
    for (int t = 0; t < 8; ++t)
#pragma unroll
        for (int u = 0; u < 2; ++u) {
            const int row = r0 + u * 8;
            const int c = t * 8 + cb;
            __nv_bfloat162 p = __float22bfloat162_rn(
                make_float2(tile[row * 64 + c], tile[row * 64 + c + 1]));
            outv[t * 2 + u] = *reinterpret_cast<uint32_t*>(&p);
        }
    uint4* dst = reinterpret_cast<uint4*>(
        out + ((size_t)((b * 16 + qt) * 32 + ch)) * MBLK + tid * 64);
#pragma unroll
    for (int i = 0; i < 4; ++i)
        dst[i] = make_uint4(outv[4 * i], outv[4 * i + 1], outv[4 * i + 2], outv[4 * i + 3]);
}

// ---------------------------------------------------------------------------
// bulk-copy GEMM (pure fp16, K-chunks of 64): C = Ah @ Bh^T.
// A, B: blocked single fp16 planes (32-col blocks; chunk = 2 adjacent blocks).
// QKV mode (C==null): z picks weight; epilogue -> fp16 blocked Q/K/V.
// O mode: fp32 C + bias.
// ---------------------------------------------------------------------------
#define GBM 128
#define GBN 128
#define GBK 64
#define STAGEB (2 * XBLK + 2 * WBLK)   // 40960: A(2 blocks) | B(2 blocks)
#define GEMM_SMEM (2 * STAGEB + 16)

__device__ __forceinline__ void store_qkv(unsigned char* dst, int z, int row, int col,
                                          float v0, float v1) {
    const int b = row >> 11, tok = row & 2047;
    const int h = col >> 6, dh = col & 63;
    size_t off;
    if (z == 0) {
        off = ((size_t)((b * Hq + h) * 16 + (tok >> 7))) * QBLK
            + (size_t)(tok & 127) * 144 + dh * 2;
    } else {
        off = ((size_t)((b * Hq + h) * 32 + (tok >> 6))) * KVBLK
            + (size_t)(tok & 63) * 144 + dh * 2;
    }
    __half2 hh = __float22half2_rn(make_float2(v0, v1));
    *reinterpret_cast<uint32_t*>(dst + off) = *reinterpret_cast<uint32_t*>(&hh);
}

__global__ __launch_bounds__(256, 2) void gemm_bulk_kernel(
    const unsigned char* __restrict__ Aplane, const unsigned char* __restrict__ Wb,
    unsigned char* __restrict__ qb, unsigned char* __restrict__ kp,
    unsigned char* __restrict__ vp,
    float* __restrict__ C, const float* __restrict__ bias,
    int M, int N, int K)
{
    extern __shared__ char smem[];
    const uint32_t sb = smem_u32(smem);
    const uint32_t mb0 = sb + 2 * STAGEB;
    const uint32_t mb1 = mb0 + 8;

    const int tid = threadIdx.x;
    const int wid = tid >> 5;
    const int lane = tid & 31;
    const int warp_m = wid >> 1;
    const int warp_n = wid & 1;
    const int row0 = blockIdx.y * GBM;
    const int col0 = blockIdx.x * GBN;
    const int z = blockIdx.z;
    const int KC = K / GBK;            // 16

    const unsigned char* Asrc = Aplane + ((size_t)blockIdx.y * (K / 32)) * XBLK;
    const unsigned char* Bsrc = (C == nullptr ? Wb + (size_t)z * WONE_BYTES : Wb)
                              + ((size_t)blockIdx.x * (K / 32)) * WBLK;

    if (tid == 0) { MBAR_INIT(mb0, 1); MBAR_INIT(mb1, 1); }
    __syncthreads();

    if (tid == 0) {
        MBAR_EXPECT_TX(mb0, STAGEB);
        CP_BULK(sb, Asrc, 2 * XBLK, mb0);
        CP_BULK(sb + 2 * XBLK, Bsrc, 2 * WBLK, mb0);
    }

    float acc[2][8][4];
#pragma unroll
    for (int i = 0; i < 2; ++i)
#pragma unroll
        for (int j = 0; j < 8; ++j)
#pragma unroll
            for (int q = 0; q < 4; ++q) acc[i][j][q] = 0.0f;

    for (int c = 0; c < KC; ++c) {
        if (c + 1 < KC && tid == 0) {
            const uint32_t stn = sb + ((c + 1) & 1) * STAGEB;
            const uint32_t mbn = ((c + 1) & 1) ? mb1 : mb0;
            MBAR_EXPECT_TX(mbn, STAGEB);
            CP_BULK(stn, Asrc + (size_t)(c + 1) * 2 * XBLK, 2 * XBLK, mbn);
            CP_BULK(stn + 2 * XBLK, Bsrc + (size_t)(c + 1) * 2 * WBLK, 2 * WBLK, mbn);
        }
        mbar_wait((c & 1) ? mb1 : mb0, (c >> 1) & 1);

        const uint32_t st = sb + (c & 1) * STAGEB;

#pragma unroll
        for (int kst = 0; kst < 4; ++kst) {
            const int blk = kst >> 1;
            const uint32_t aBase = st + blk * XBLK;
            const uint32_t bBase = st + 2 * XBLK + blk * WBLK;
            const int kb = (kst & 1) * 32 + (lane >> 4) * 16;

            uint32_t a4[2][4];
#pragma unroll
            for (int mt = 0; mt < 2; ++mt) {
                const int arow = warp_m * 32 + mt * 16 + (lane & 15);
                LDSM_X4(a4[mt][0], a4[mt][1], a4[mt][2], a4[mt][3], aBase + arow * 80 + kb);
            }

#pragma unroll
            for (int g = 0; g < 2; ++g) {
                uint32_t b4[4][2];
                const int brow_in = (lane & 7) + ((lane >> 4) << 3);
                const int bkb = (kst & 1) * 32 + ((lane >> 3) & 1) * 16;
#pragma unroll
                for (int p = 0; p < 2; ++p) {
                    const int nb = warp_n * 64 + g * 32 + p * 16;
                    const uint32_t ba = (nb + brow_in) * 80 + bkb;
                    LDSM_X4(b4[2 * p][0], b4[2 * p][1], b4[2 * p + 1][0], b4[2 * p + 1][1],
                            bBase + ba);
                }
#pragma unroll
                for (int mt = 0; mt < 2; ++mt)
#pragma unroll
                    for (int nt = 0; nt < 4; ++nt) {
                        float* cc = acc[mt][g * 4 + nt];
                        MMA_FP16(cc[0], cc[1], cc[2], cc[3],
                                 a4[mt][0], a4[mt][1], a4[mt][2], a4[mt][3],
                                 b4[nt][0], b4[nt][1]);
                    }
            }
        }
        __syncthreads();
    }

    // epilogue
    if (C != nullptr) {
#pragma unroll
        for (int mt = 0; mt < 2; ++mt) {
            const int rbase = row0 + warp_m * 32 + mt * 16 + (lane >> 2);
#pragma unroll
            for (int nt = 0; nt < 8; ++nt) {
                const int cbase = col0 + warp_n * 64 + nt * 8 + (lane & 3) * 2;
                float v0 = acc[mt][nt][0], v1 = acc[mt][nt][1];
                float v2 = acc[mt][nt][2], v3 = acc[mt][nt][3];
                const float b0 = bias[cbase], b1 = bias[cbase + 1];
                v0 += b0; v1 += b1; v2 += b0; v3 += b1;
                *reinterpret_cast<float2*>(C + (size_t)rbase * N + cbase) = make_float2(v0, v1);
                *reinterpret_cast<float2*>(C + (size_t)(rbase + 8) * N + cbase) = make_float2(v2, v3);
            }
        }
    } else {
        const float scale = (z == 0) ? SCALEq : 1.0f;
        unsigned char* dst = (z == 0) ? qb : (z == 1) ? kp : vp;
#pragma unroll
        for (int mt = 0; mt < 2; ++mt) {
            const int rbase = row0 + warp_m * 32 + mt * 16 + (lane >> 2);
#pragma unroll
            for (int nt = 0; nt < 8; ++nt) {
                const int cbase = col0 + warp_n * 64 + nt * 8 + (lane & 3) * 2;
                store_qkv(dst, z, rbase, cbase,
                          acc[mt][nt][0] * scale, acc[mt][nt][1] * scale);
                store_qkv(dst, z, rbase + 8, cbase,
                          acc[mt][nt][2] * scale, acc[mt][nt][3] * scale);
            }
        }
    }
}

// ---------------------------------------------------------------------------
// Tensor-core flash attention, pure fp16, bulk-copy fed. (unchanged from R11)
// ---------------------------------------------------------------------------
#define FBQ 128
#define FBK 64
#define FROWB 144
#define FQ_TILE (FBQ * FROWB)               // 18432
#define FKV_TILE (FBK * FROWB)              // 9216
#define F_ST FQ_TILE                        // 18432
#define F_STAGE (2 * FKV_TILE)              // 18432 (K | V)
#define FLASH_SMEM (F_ST + 2 * F_STAGE + 32)

__global__ __launch_bounds__(256, 2) void flash_mma_kernel(
    const unsigned char* __restrict__ maskp,
    const unsigned char* __restrict__ qb,
    const unsigned char* __restrict__ kp,
    const unsigned char* __restrict__ vp,
    unsigned char* __restrict__ ap)
{
    extern __shared__ char smem[];
    const uint32_t sb = smem_u32(smem);
    const uint32_t mbQ = sb + F_ST + 2 * F_STAGE;
    const uint32_t mbK0 = mbQ + 8;
    const uint32_t mbK1 = mbQ + 16;

    const int tid  = threadIdx.x;
    const int wid  = tid >> 5;
    const int lane = tid & 31;
    const int qt = blockIdx.x;
    const int h  = blockIdx.y;
    const int b  = blockIdx.z;

    const unsigned char* qsrc = qb + ((size_t)((b * Hq + h) * 16 + qt)) * QBLK;
    const unsigned char* kbase = kp + ((size_t)((b * Hq + h) * 32)) * KVBLK;
    const unsigned char* vbase = vp + ((size_t)((b * Hq + h) * 32)) * KVBLK;
    const unsigned char* mbase = maskp + ((size_t)((b * 16 + qt) * 32)) * MBLK + tid * 64;

    if (tid == 0) { MBAR_INIT(mbQ, 1); MBAR_INIT(mbK0, 1); MBAR_INIT(mbK1, 1); }
    __syncthreads();

    if (tid == 0) {
        MBAR_EXPECT_TX(mbQ, FQ_TILE);
        CP_BULK(sb, qsrc, FQ_TILE, mbQ);
        MBAR_EXPECT_TX(mbK0, F_STAGE);
        CP_BULK(sb + F_ST, kbase, KVBLK, mbK0);
        CP_BULK(sb + F_ST + KVBLK, vbase, KVBLK, mbK0);
    }

    float o[8][4];
#pragma unroll
    for (int t = 0; t < 8; ++t)
#pragma unroll
        for (int j = 0; j < 4; ++j) o[t][j] = 0.0f;
    float m0 = -1e30f, m1 = -1e30f, l0 = 0.0f, l1 = 0.0f;

    const int r0g = qt * FBQ + wid * 16 + (lane >> 2);
    const int quadcol = (lane & 3) * 2;

    mbar_wait(mbQ, 0);

    const int chunks = Tq / FBK;   // 32
    for (int c = 0; c < chunks; ++c) {
        if (c + 1 < chunks && tid == 0) {
            const uint32_t stn = sb + F_ST + ((c + 1) & 1) * F_STAGE;
            const uint32_t mbn = ((c + 1) & 1) ? mbK1 : mbK0;
            MBAR_EXPECT_TX(mbn, F_STAGE);
            CP_BULK(stn, kbase + (size_t)(c + 1) * KVBLK, KVBLK, mbn);
            CP_BULK(stn + KVBLK, vbase + (size_t)(c + 1) * KVBLK, KVBLK, mbn);
        }
        mbar_wait((c & 1) ? mbK1 : mbK0, (c >> 1) & 1);

        const uint32_t st = sb + F_ST + (c & 1) * F_STAGE;
        const uint32_t kP = st;
        const uint32_t vP = st + FKV_TILE;

        // ---- S = Q @ K^T (fp16, 1 pass) ----
        float s[8][4];
#pragma unroll
        for (int t = 0; t < 8; ++t)
#pragma unroll
            for (int j = 0; j < 4; ++j) s[t][j] = 0.0f;

        const int brow_in = (lane & 7) + ((lane >> 4) << 3);
#pragma unroll
        for (int kk = 0; kk < 4; ++kk) {
            uint32_t q4[4];
            const uint32_t qa = sb + (wid * 16 + (lane & 15)) * FROWB
                              + kk * 32 + (lane >> 4) * 16;
            LDSM_X4(q4[0], q4[1], q4[2], q4[3], qa);

            const int bkb = kk * 32 + ((lane >> 3) & 1) * 16;
#pragma unroll
            for (int p = 0; p < 4; ++p) {
                uint32_t b4[2][2];
                const uint32_t ba = (p * 16 + brow_in) * FROWB + bkb;
                LDSM_X4(b4[0][0], b4[0][1], b4[1][0], b4[1][1], kP + ba);
#pragma unroll
                for (int u = 0; u < 2; ++u) {
                    float* cc = s[2 * p + u];
                    MMA_FP16(cc[0], cc[1], cc[2], cc[3],
                             q4[0], q4[1], q4[2], q4[3], b4[u][0], b4[u][1]);
                }
            }
        }

        // ---- mask (permuted bf16) + online softmax ----
        {
            const uint4* mp = reinterpret_cast<const uint4*>(mbase + (size_t)c * MBLK);
            uint32_t mu[16];
#pragma unroll
            for (int i = 0; i < 4; ++i) {
                uint4 q = mp[i];
                mu[4 * i + 0] = q.x; mu[4 * i + 1] = q.y;
                mu[4 * i + 2] = q.z; mu[4 * i + 3] = q.w;
            }
#pragma unroll
            for (int t = 0; t < 8; ++t) {
                float2 lo2 = __bfloat1622float2(
                    *reinterpret_cast<__nv_bfloat162*>(&mu[2 * t]));
                float2 hi2 = __bfloat1622float2(
                    *reinterpret_cast<__nv_bfloat162*>(&mu[2 * t + 1]));
                s[t][0] += lo2.x; s[t][1] += lo2.y;
                s[t][2] += hi2.x; s[t][3] += hi2.y;
            }
        }

        float mx0 = -1e30f, mx1 = -1e30f;
#pragma unroll
        for (int t = 0; t < 8; ++t) {
            mx0 = fmaxf(mx0, fmaxf(s[t][0], s[t][1]));
            mx1 = fmaxf(mx1, fmaxf(s[t][2], s[t][3]));
        }
        mx0 = fmaxf(mx0, __shfl_xor_sync(0xffffffffu, mx0, 1));
        mx0 = fmaxf(mx0, __shfl_xor_sync(0xffffffffu, mx0, 2));
        mx1 = fmaxf(mx1, __shfl_xor_sync(0xffffffffu, mx1, 1));
        mx1 = fmaxf(mx1, __shfl_xor_sync(0xffffffffu, mx1, 2));

        const float mn0 = fmaxf(m0, mx0);
        const float mn1 = fmaxf(m1, mx1);
        const float a0 = __expf(m0 - mn0);
        const float a1 = __expf(m1 - mn1);
        m0 = mn0; m1 = mn1;

        float sum0 = 0.0f, sum1 = 0.0f;
#pragma unroll
        for (int t = 0; t < 8; ++t) {
            s[t][0] = __expf(s[t][0] - mn0);
            s[t][1] = __expf(s[t][1] - mn0);
            s[t][2] = __expf(s[t][2] - mn1);
            s[t][3] = __expf(s[t][3] - mn1);
            sum0 += s[t][0] + s[t][1];
            sum1 += s[t][2] + s[t][3];
        }
        sum0 += __shfl_xor_sync(0xffffffffu, sum0, 1);
        sum0 += __shfl_xor_sync(0xffffffffu, sum0, 2);
        sum1 += __shfl_xor_sync(0xffffffffu, sum1, 1);
        sum1 += __shfl_xor_sync(0xffffffffu, sum1, 2);
        l0 = l0 * a0 + sum0;
        l1 = l1 * a1 + sum1;

#pragma unroll
        for (int t = 0; t < 8; ++t) {
            o[t][0] *= a0; o[t][1] *= a0;
            o[t][2] *= a1; o[t][3] *= a1;
        }

        // ---- P fragments (fp16) ----
        uint32_t pH[4][4];
#pragma unroll
        for (int j = 0; j < 4; ++j) {
#pragma unroll
            for (int u = 0; u < 2; ++u) {
#pragma unroll
                for (int w = 0; w < 2; ++w) {
                    __half2 hh = __float22half2_rn(make_float2(
                        s[2 * j + w][2 * u + 0], s[2 * j + w][2 * u + 1]));
                    pH[j][2 * w + u] = *reinterpret_cast<uint32_t*>(&hh);
                }
            }
        }

        // ---- O += P @ V (fp16, 1 pass) ----
#pragma unroll
        for (int j = 0; j < 4; ++j) {
#pragma unroll
            for (int p = 0; p < 4; ++p) {
                uint32_t v4[2][2];
                const uint32_t va = (j * 16 + (lane & 15)) * FROWB
                                  + p * 32 + (lane >> 4) * 16;
                LDSM_X4_T(v4[0][0], v4[0][1], v4[1][0], v4[1][1], vP + va);
#pragma unroll
                for (int u = 0; u < 2; ++u) {
                    float* cc = o[2 * p + u];
                    MMA_FP16(cc[0], cc[1], cc[2], cc[3],
                             pH[j][0], pH[j][1], pH[j][2], pH[j][3],
                             v4[u][0], v4[u][1]);
                }
            }
        }
        __syncthreads();
    }

    // ---- epilogue: normalize, write blocked single fp16 plane A ----
    const float inv0 = 1.0f / l0;
    const float inv1 = 1.0f / l1;
    const int grow = b * Tq + r0g;
#pragma unroll
    for (int t = 0; t < 8; ++t) {
        const int col = h * DHq + t * 8 + quadcol;
        {
            unsigned char* base = ap
                + ((size_t)((grow >> 7) * KCq + (col >> 5))) * XBLK
                + (grow & 127) * 80 + (col & 31) * 2;
            __half2 hh = __float22half2_rn(make_float2(o[t][0] * inv0, o[t][1] * inv0));
            *reinterpret_cast<uint32_t*>(base) = *reinterpret_cast<uint32_t*>(&hh);
        }
        {
            const int grow2 = grow + 8;
            unsigned char* base = ap
                + ((size_t)((grow2 >> 7) * KCq + (col >> 5))) * XBLK
                + (grow2 & 127) * 80 + (col & 31) * 2;
            __half2 hh = __float22half2_rn(make_float2(o[t][2] * inv1, o[t][3] * inv1));
            *reinterpret_cast<uint32_t*>(base) = *reinterpret_cast<uint32_t*>(&hh);
        }
    }
}

// ---------------------------------------------------------------------------
// kernel_launch
// Inputs: x, attention_mask, Wq, Wk, Wv, Wo, bo
// ---------------------------------------------------------------------------
extern "C" void kernel_launch(void* const* d_in, const int* in_sizes, int n_in,
                              void* d_out, int out_size)
{
    (void)in_sizes; (void)n_in; (void)out_size;
    const float* x    = (const float*)d_in[0];
    const float* mask = (const float*)d_in[1];
    const float* Wq   = (const float*)d_in[2];
    const float* Wk   = (const float*)d_in[3];
    const float* Wv   = (const float*)d_in[4];
    const float* Wo   = (const float*)d_in[5];
    const float* bo   = (const float*)d_in[6];
    float* out = (float*)d_out;

    unsigned char *xp, *ap, *w, *qb, *kpb, *vpb, *maskp;
    cudaGetSymbolAddress((void**)&xp, g_xp);
    cudaGetSymbolAddress((void**)&ap, g_ap);
    cudaGetSymbolAddress((void**)&w, g_w);
    cudaGetSymbolAddress((void**)&qb, g_qb);
    cudaGetSymbolAddress((void**)&kpb, g_kp);
    cudaGetSymbolAddress((void**)&vpb, g_vp);
    cudaGetSymbolAddress((void**)&maskp, g_maskp);

    const int M = Bq * Tq;     // 8192
    const int N = INNERq;      // 1024
    const int K = Dq;          // 1024
    const int nx = M * K;

    // Side stream for the mask permute (independent of the GEMM chain).
    // Created once on the first (non-captured) correctness call; the fork/join
    // event pattern below is graph-capturable.
    static cudaStream_t s2 = nullptr;
    static cudaEvent_t evFork = nullptr, evJoin = nullptr;
    if (s2 == nullptr) {
        cudaStreamCreateWithFlags(&s2, cudaStreamNonBlocking);
        cudaEventCreateWithFlags(&evFork, cudaEventDisableTiming);
        cudaEventCreateWithFlags(&evJoin, cudaEventDisableTiming);
    }

    // fork: mask permute runs concurrently with split/tsplit/QKV GEMM
    cudaEventRecord(evFork, 0);
    cudaStreamWaitEvent(s2, evFork, 0);
    dim3 mGrid(32, 16, Bq);
    mask_permute<<<mGrid, 256, 0, s2>>>(mask, maskp);
    cudaEventRecord(evJoin, s2);

    // main chain: conversions -> blocked layouts
    split_kernel<<<nx / (256 * 4), 256>>>(x, xp);
    dim3 tGrid(N / 32, K / 32, 4), tBlk(32, 8);
    tsplit_kernel<<<tGrid, tBlk>>>(Wq, Wk, Wv, Wo, w, K, N);

    // Q,K,V projections (one launch, bulk-fed, pure fp16)
    cudaFuncSetAttribute(gemm_bulk_kernel,
                         cudaFuncAttributeMaxDynamicSharedMemorySize, GEMM_SMEM);
    dim3 qkvGrid(N / GBN, M / GBM, 3);
    gemm_bulk_kernel<<<qkvGrid, 256, GEMM_SMEM>>>(xp, w, qb, kpb, vpb,
                                                  nullptr, nullptr, M, N, K);

    // join: flash needs the permuted mask
    cudaStreamWaitEvent(0, evJoin, 0);

    // flash attention (pure fp16, bulk-fed) -> blocked A plane
    cudaFuncSetAttribute(flash_mma_kernel,
                         cudaFuncAttributeMaxDynamicSharedMemorySize, FLASH_SMEM);
    dim3 fGrid(Tq / FBQ, Hq, Bq);
    flash_mma_kernel<<<fGrid, 256, FLASH_SMEM>>>(maskp, qb, kpb, vpb, ap);

    // output projection (fp32 + bias, pure fp16)
    dim3 oGrid(N / GBN, M / GBM, 1);
    gemm_bulk_kernel<<<oGrid, 256, GEMM_SMEM>>>(ap, w + 3 * WONE_BYTES,
                                                nullptr, nullptr, nullptr,
                                                out, bo, M, Dq, INNERq);
}

// round 13
// speedup vs baseline: 2.7964x; 1.0316x over previous
#include <cuda_runtime.h>
#include <cuda_bf16.h>
#include <cuda_fp16.h>
#include <cstdint>
#include <cstddef>

// ---------------------------------------------------------------------------
// Problem constants
// ---------------------------------------------------------------------------
#define Bq   4
#define Tq   2048
#define Dq   1024
#define Hq   16
#define DHq  64
#define INNERq 1024
#define SCALEq 0.125f     // 64^-0.5

// Blocked-layout sizes (all single fp16 planes)
#define KCq 32                                   // 32-col blocks per 1024-K row panel
#define XBLK 10240                               // activation (128x32) fp16 plane
#define WBLK 10240                               // weight (128x32) fp16 plane
#define WONE_BYTES ((size_t)8 * 32 * WBLK)       // one weight, blocked
#define XPLANE_BYTES ((size_t)64 * 32 * XBLK)    // x / attn-out, blocked
#define QBLK 18432                               // Q (128x64) fp16 plane
#define KVBLK 9216                               // K or V (64x64) fp16 plane
#define QB_BYTES ((size_t)Bq * Hq * 16 * QBLK)
#define KP_BYTES ((size_t)Bq * Hq * 32 * KVBLK)
#define MBLK 16384                               // permuted bf16 mask tile (128x64)
#define MP_BYTES ((size_t)Bq * 16 * 32 * MBLK)

// ---------------------------------------------------------------------------
// Scratch (device globals; allocation is forbidden)
// ---------------------------------------------------------------------------
__device__ __align__(128) unsigned char g_xp[XPLANE_BYTES];
__device__ __align__(128) unsigned char g_ap[XPLANE_BYTES];
__device__ __align__(128) unsigned char g_w[4 * WONE_BYTES];
__device__ __align__(128) unsigned char g_qb[QB_BYTES];
__device__ __align__(128) unsigned char g_kp[KP_BYTES];
__device__ __align__(128) unsigned char g_vp[KP_BYTES];
__device__ __align__(128) unsigned char g_maskp[MP_BYTES];

// ---------------------------------------------------------------------------
// PTX helpers
// ---------------------------------------------------------------------------
__device__ __forceinline__ uint32_t smem_u32(const void* p) {
    uint32_t a;
    asm("{ .reg .u64 t; cvta.to.shared.u64 t, %1; cvt.u32.u64 %0, t; }" : "=r"(a) : "l"(p));
    return a;
}

#define MBAR_INIT(mbar, cnt) \
    asm volatile("mbarrier.init.shared.b64 [%0], %1;" :: "r"((uint32_t)(mbar)), "r"((uint32_t)(cnt)) : "memory")
#define MBAR_EXPECT_TX(mbar, bytes) \
    asm volatile("mbarrier.arrive.expect_tx.shared.b64 _, [%0], %1;" \
                 :: "r"((uint32_t)(mbar)), "r"((uint32_t)(bytes)) : "memory")
#define CP_BULK(smem_dst, gsrc, bytes, mbar) \
    asm volatile("cp.async.bulk.shared::cluster.global.mbarrier::complete_tx::bytes [%0], [%1], %2, [%3];" \
                 :: "r"((uint32_t)(smem_dst)), "l"(gsrc), "r"((uint32_t)(bytes)), \
                    "r"((uint32_t)(mbar)) : "memory")

__device__ __forceinline__ void mbar_wait(uint32_t mbar, uint32_t parity) {
    asm volatile(
        "{\n\t.reg .pred P;\n\t"
        "WAIT_%=:\n\t"
        "mbarrier.try_wait.parity.acquire.cta.shared::cta.b64 P, [%0], %1, 0x989680;\n\t"
        "@P bra DONE_%=;\n\t"
        "bra WAIT_%=;\n\t"
        "DONE_%=:\n\t}"
        :: "r"(mbar), "r"(parity) : "memory");
}

#define LDSM_X4(r0, r1, r2, r3, addr) \
    asm volatile("ldmatrix.sync.aligned.m8n8.x4.shared.b16 {%0,%1,%2,%3}, [%4];" \
                 : "=r"(r0), "=r"(r1), "=r"(r2), "=r"(r3) : "r"(addr))

#define LDSM_X4_T(r0, r1, r2, r3, addr) \
    asm volatile("ldmatrix.sync.aligned.m8n8.x4.trans.shared.b16 {%0,%1,%2,%3}, [%4];" \
                 : "=r"(r0), "=r"(r1), "=r"(r2), "=r"(r3) : "r"(addr))

#define MMA_FP16(c0, c1, c2, c3, a0, a1, a2, a3, b0, b1) \
    asm volatile("mma.sync.aligned.m16n8k16.row.col.f32.f16.f16.f32 " \
                 "{%0,%1,%2,%3}, {%4,%5,%6,%7}, {%8,%9}, {%0,%1,%2,%3};" \
                 : "+f"(c0), "+f"(c1), "+f"(c2), "+f"(c3) \
                 : "r"(a0), "r"(a1), "r"(a2), "r"(a3), "r"(b0), "r"(b1))

// ---------------------------------------------------------------------------
// x[8192,1024] fp32 -> blocked single fp16 plane
// ---------------------------------------------------------------------------
__global__ __launch_bounds__(256) void split_kernel(
    const float* __restrict__ in, unsigned char* __restrict__ out)
{
    const int i = (blockIdx.x * 256 + threadIdx.x) * 4;
    float4 v = *reinterpret_cast<const float4*>(in + i);
    const int row = i >> 10, col = i & 1023;
    unsigned char* base = out + ((size_t)((row >> 7) * KCq + (col >> 5))) * XBLK
                        + (row & 127) * 80 + (col & 31) * 2;
    __half2 h01 = __float22half2_rn(make_float2(v.x, v.y));
    __half2 h23 = __float22half2_rn(make_float2(v.z, v.w));
    *reinterpret_cast<uint2*>(base) = make_uint2(
        *reinterpret_cast<uint32_t*>(&h01), *reinterpret_cast<uint32_t*>(&h23));
}

// ---------------------------------------------------------------------------
// All 4 weights in ONE launch: W[K,N] fp32 -> transposed blocked fp16 plane.
// ---------------------------------------------------------------------------
__global__ __launch_bounds__(256) void tsplit_kernel(
    const float* __restrict__ W0, const float* __restrict__ W1,
    const float* __restrict__ W2, const float* __restrict__ W3,
    unsigned char* __restrict__ outbase, int K, int N)
{
    __shared__ float t[32][33];
    const int tx = threadIdx.x, ty = threadIdx.y;
    const int bx = blockIdx.x, by = blockIdx.y, z = blockIdx.z;
    const float* W = (z == 0) ? W0 : (z == 1) ? W1 : (z == 2) ? W2 : W3;
    unsigned char* out = outbase + (size_t)z * WONE_BYTES;
#pragma unroll
    for (int j = 0; j < 32; j += 8)
        t[ty + j][tx] = W[(size_t)(by * 32 + ty + j) * N + bx * 32 + tx];
    __syncthreads();
#pragma unroll
    for (int j = 0; j < 32; j += 8) {
        float v = t[tx][ty + j];
        const int n = bx * 32 + ty + j;
        const int k = by * 32 + tx;
        unsigned char* base = out + ((size_t)((n >> 7) * KCq + (k >> 5))) * WBLK
                            + (n & 127) * 80 + (k & 31) * 2;
        *reinterpret_cast<__half*>(base) = __float2half_rn(v);
    }
}

// ---------------------------------------------------------------------------
// Mask permute: fp32 [B,1,T,T] -> bf16, consumer-ordered per (b,qtile,chunk,tid)
// ---------------------------------------------------------------------------
__global__ __launch_bounds__(256) void mask_permute(
    const float* __restrict__ mask, unsigned char* __restrict__ out)
{
    __shared__ float tile[128 * 64];
    const int b = blockIdx.z, qt = blockIdx.y, ch = blockIdx.x;
    const int tid = threadIdx.x;
    const float* src = mask + ((size_t)b * Tq + qt * 128) * Tq + ch * 64;
    for (int i = tid; i < 2048; i += 256) {
        const int row = i >> 4, c4 = (i & 15) * 4;
        float4 v = *reinterpret_cast<const float4*>(src + (size_t)row * Tq + c4);
        tile[row * 64 + c4 + 0] = v.x;
        tile[row * 64 + c4 + 1] = v.y;
        tile[row * 64 + c4 + 2] = v.z;
        tile[row * 64 + c4 + 3] = v.w;
    }
    __syncthreads();
    const int wid = tid >> 5, lane = tid & 31;
    const int r0 = wid * 16 + (lane >> 2);
    const int cb = (lane & 3) * 2;
    uint32_t outv[16];
#pragma unroll
    for (int t = 0; t < 8; ++t)
#pragma unroll
        for (int u = 0; u < 2; ++u) {
            const int row = r0 + u * 8;
            const int c = t * 8 + cb;
            __nv_bfloat162 p = __float22bfloat162_rn(
                make_float2(tile[row * 64 + c], tile[row * 64 + c + 1]));
            outv[t * 2 + u] = *reinterpret_cast<uint32_t*>(&p);
        }
    uint4* dst = reinterpret_cast<uint4*>(
        out + ((size_t)((b * 16 + qt) * 32 + ch)) * MBLK + tid * 64);
#pragma unroll
    for (int i = 0; i < 4; ++i)
        dst[i] = make_uint4(outv[4 * i], outv[4 * i + 1], outv[4 * i + 2], outv[4 * i + 3]);
}

// ---------------------------------------------------------------------------
// bulk-copy GEMM (pure fp16, 4-stage pipeline, GBK=32): C = Ah @ Bh^T.
// ---------------------------------------------------------------------------
#define GBM 128
#define GBN 128
#define GBK 32
#define STAGEB (XBLK + WBLK)              // 20480: A | B
#define GEMM_SMEM (4 * STAGEB + 32)       // 4 stages + 4 mbars

__device__ __forceinline__ void store_qkv(unsigned char* dst, int z, int row, int col,
                                          float v0, float v1) {
    const int b = row >> 11, tok = row & 2047;
    const int h = col >> 6, dh = col & 63;
    size_t off;
    if (z == 0) {
        off = ((size_t)((b * Hq + h) * 16 + (tok >> 7))) * QBLK
            + (size_t)(tok & 127) * 144 + dh * 2;
    } else {
        off = ((size_t)((b * Hq + h) * 32 + (tok >> 6))) * KVBLK
            + (size_t)(tok & 63) * 144 + dh * 2;
    }
    __half2 hh = __float22half2_rn(make_float2(v0, v1));
    *reinterpret_cast<uint32_t*>(dst + off) = *reinterpret_cast<uint32_t*>(&hh);
}

__global__ __launch_bounds__(256, 2) void gemm_bulk_kernel(
    const unsigned char* __restrict__ Aplane, const unsigned char* __restrict__ Wb,
    unsigned char* __restrict__ qb, unsigned char* __restrict__ kp,
    unsigned char* __restrict__ vp,
    float* __restrict__ C, const float* __restrict__ bias,
    int M, int N, int K)
{
    extern __shared__ char smem[];
    const uint32_t sb = smem_u32(smem);
    const uint32_t mbb = sb + 4 * STAGEB;     // 4 mbarriers, 8B apart

    const int tid = threadIdx.x;
    const int wid = tid >> 5;
    const int lane = tid & 31;
    const int warp_m = wid >> 1;
    const int warp_n = wid & 1;
    const int row0 = blockIdx.y * GBM;
    const int col0 = blockIdx.x * GBN;
    const int z = blockIdx.z;
    const int KC = K / GBK;                   // 32

    const unsigned char* Asrc = Aplane + ((size_t)blockIdx.y * KC) * XBLK;
    const unsigned char* Bsrc = (C == nullptr ? Wb + (size_t)z * WONE_BYTES : Wb)
                              + ((size_t)blockIdx.x * KC) * WBLK;

    if (tid == 0) {
#pragma unroll
        for (int s = 0; s < 4; ++s) MBAR_INIT(mbb + 8 * s, 1);
    }
    __syncthreads();

    // prologue: fill stages 0..2
    if (tid == 0) {
#pragma unroll
        for (int s = 0; s < 3; ++s) {
            MBAR_EXPECT_TX(mbb + 8 * s, STAGEB);
            CP_BULK(sb + s * STAGEB, Asrc + (size_t)s * XBLK, XBLK, mbb + 8 * s);
            CP_BULK(sb + s * STAGEB + XBLK, Bsrc + (size_t)s * WBLK, WBLK, mbb + 8 * s);
        }
    }

    float acc[2][8][4];
#pragma unroll
    for (int i = 0; i < 2; ++i)
#pragma unroll
        for (int j = 0; j < 8; ++j)
#pragma unroll
            for (int q = 0; q < 4; ++q) acc[i][j][q] = 0.0f;

    for (int c = 0; c < KC; ++c) {
        // prefetch 3 ahead (stage (c+3)&3 was last read at iteration c-1;
        // the __syncthreads at the end of iteration c-1 fences those reads)
        if (c + 3 < KC && tid == 0) {
            const int f = c + 3;
            const int s = f & 3;
            MBAR_EXPECT_TX(mbb + 8 * s, STAGEB);
            CP_BULK(sb + s * STAGEB, Asrc + (size_t)f * XBLK, XBLK, mbb + 8 * s);
            CP_BULK(sb + s * STAGEB + XBLK, Bsrc + (size_t)f * WBLK, WBLK, mbb + 8 * s);
        }
        mbar_wait(mbb + 8 * (c & 3), (c >> 2) & 1);

        const uint32_t st = sb + (c & 3) * STAGEB;
        const uint32_t aP = st;
        const uint32_t bP = st + XBLK;

#pragma unroll
        for (int kst = 0; kst < 2; ++kst) {
            const int kb = kst * 32 + (lane >> 4) * 16;

            uint32_t a4[2][4];
#pragma unroll
            for (int mt = 0; mt < 2; ++mt) {
                const int arow = warp_m * 32 + mt * 16 + (lane & 15);
                LDSM_X4(a4[mt][0], a4[mt][1], a4[mt][2], a4[mt][3], aP + arow * 80 + kb);
            }

#pragma unroll
            for (int g = 0; g < 2; ++g) {
                uint32_t b4[4][2];
                const int brow_in = (lane & 7) + ((lane >> 4) << 3);
                const int bkb = kst * 32 + ((lane >> 3) & 1) * 16;
#pragma unroll
                for (int p = 0; p < 2; ++p) {
                    const int nb = warp_n * 64 + g * 32 + p * 16;
                    const uint32_t ba = (nb + brow_in) * 80 + bkb;
                    LDSM_X4(b4[2 * p][0], b4[2 * p][1], b4[2 * p + 1][0], b4[2 * p + 1][1],
                            bP + ba);
                }
#pragma unroll
                for (int mt = 0; mt < 2; ++mt)
#pragma unroll
                    for (int nt = 0; nt < 4; ++nt) {
                        float* cc = acc[mt][g * 4 + nt];
                        MMA_FP16(cc[0], cc[1], cc[2], cc[3],
                                 a4[mt][0], a4[mt][1], a4[mt][2], a4[mt][3],
                                 b4[nt][0], b4[nt][1]);
                    }
            }
        }
        __syncthreads();
    }

    // epilogue
    if (C != nullptr) {
#pragma unroll
        for (int mt = 0; mt < 2; ++mt) {
            const int rbase = row0 + warp_m * 32 + mt * 16 + (lane >> 2);
#pragma unroll
            for (int nt = 0; nt < 8; ++nt) {
                const int cbase = col0 + warp_n * 64 + nt * 8 + (lane & 3) * 2;
                float v0 = acc[mt][nt][0], v1 = acc[mt][nt][1];
                float v2 = acc[mt][nt][2], v3 = acc[mt][nt][3];
                const float b0 = bias[cbase], b1 = bias[cbase + 1];
                v0 += b0; v1 += b1; v2 += b0; v3 += b1;
                *reinterpret_cast<float2*>(C + (size_t)rbase * N + cbase) = make_float2(v0, v1);
                *reinterpret_cast<float2*>(C + (size_t)(rbase + 8) * N + cbase) = make_float2(v2, v3);
            }
        }
    } else {
        const float scale = (z == 0) ? SCALEq : 1.0f;
        unsigned char* dst = (z == 0) ? qb : (z == 1) ? kp : vp;
#pragma unroll
        for (int mt = 0; mt < 2; ++mt) {
            const int rbase = row0 + warp_m * 32 + mt * 16 + (lane >> 2);
#pragma unroll
            for (int nt = 0; nt < 8; ++nt) {
                const int cbase = col0 + warp_n * 64 + nt * 8 + (lane & 3) * 2;
                store_qkv(dst, z, rbase, cbase,
                          acc[mt][nt][0] * scale, acc[mt][nt][1] * scale);
                store_qkv(dst, z, rbase + 8, cbase,
                          acc[mt][nt][2] * scale, acc[mt][nt][3] * scale);
            }
        }
    }
}

// ---------------------------------------------------------------------------
// Tensor-core flash attention, pure fp16, 4-stage KV pipeline.
// ---------------------------------------------------------------------------
#define FBQ 128
#define FBK 64
#define FROWB 144
#define FQ_TILE (FBQ * FROWB)               // 18432
#define FKV_TILE (FBK * FROWB)              // 9216
#define F_ST FQ_TILE                        // 18432
#define F_STAGE (2 * FKV_TILE)              // 18432 (K | V)
#define FLASH_SMEM (F_ST + 4 * F_STAGE + 64)

__global__ __launch_bounds__(256, 2) void flash_mma_kernel(
    const unsigned char* __restrict__ maskp,
    const unsigned char* __restrict__ qb,
    const unsigned char* __restrict__ kp,
    const unsigned char* __restrict__ vp,
    unsigned char* __restrict__ ap)
{
    extern __shared__ char smem[];
    const uint32_t sb = smem_u32(smem);
    const uint32_t mbQ = sb + F_ST + 4 * F_STAGE;
    const uint32_t mbb = mbQ + 8;            // 4 KV mbarriers

    const int tid  = threadIdx.x;
    const int wid  = tid >> 5;
    const int lane = tid & 31;
    const int qt = blockIdx.x;
    const int h  = blockIdx.y;
    const int b  = blockIdx.z;

    const unsigned char* qsrc = qb + ((size_t)((b * Hq + h) * 16 + qt)) * QBLK;
    const unsigned char* kbase = kp + ((size_t)((b * Hq + h) * 32)) * KVBLK;
    const unsigned char* vbase = vp + ((size_t)((b * Hq + h) * 32)) * KVBLK;
    const unsigned char* mbase = maskp + ((size_t)((b * 16 + qt) * 32)) * MBLK + tid * 64;

    if (tid == 0) {
        MBAR_INIT(mbQ, 1);
#pragma unroll
        for (int s = 0; s < 4; ++s) MBAR_INIT(mbb + 8 * s, 1);
    }
    __syncthreads();

    if (tid == 0) {
        MBAR_EXPECT_TX(mbQ, FQ_TILE);
        CP_BULK(sb, qsrc, FQ_TILE, mbQ);
#pragma unroll
        for (int s = 0; s < 3; ++s) {
            MBAR_EXPECT_TX(mbb + 8 * s, F_STAGE);
            CP_BULK(sb + F_ST + s * F_STAGE, kbase + (size_t)s * KVBLK, KVBLK, mbb + 8 * s);
            CP_BULK(sb + F_ST + s * F_STAGE + FKV_TILE, vbase + (size_t)s * KVBLK, KVBLK,
                    mbb + 8 * s);
        }
    }

    float o[8][4];
#pragma unroll
    for (int t = 0; t < 8; ++t)
#pragma unroll
        for (int j = 0; j < 4; ++j) o[t][j] = 0.0f;
    float m0 = -1e30f, m1 = -1e30f, l0 = 0.0f, l1 = 0.0f;

    const int r0g = qt * FBQ + wid * 16 + (lane >> 2);
    const int quadcol = (lane & 3) * 2;

    mbar_wait(mbQ, 0);

    const int chunks = Tq / FBK;   // 32
    for (int c = 0; c < chunks; ++c) {
        if (c + 3 < chunks && tid == 0) {
            const int f = c + 3;
            const int s = f & 3;
            MBAR_EXPECT_TX(mbb + 8 * s, F_STAGE);
            CP_BULK(sb + F_ST + s * F_STAGE, kbase + (size_t)f * KVBLK, KVBLK, mbb + 8 * s);
            CP_BULK(sb + F_ST + s * F_STAGE + FKV_TILE, vbase + (size_t)f * KVBLK, KVBLK,
                    mbb + 8 * s);
        }
        mbar_wait(mbb + 8 * (c & 3), (c >> 2) & 1);

        const uint32_t st = sb + F_ST + (c & 3) * F_STAGE;
        const uint32_t kP = st;
        const uint32_t vP = st + FKV_TILE;

        // ---- S = Q @ K^T (fp16, 1 pass) ----
        float s[8][4];
#pragma unroll
        for (int t = 0; t < 8; ++t)
#pragma unroll
            for (int j = 0; j < 4; ++j) s[t][j] = 0.0f;

        const int brow_in = (lane & 7) + ((lane >> 4) << 3);
#pragma unroll
        for (int kk = 0; kk < 4; ++kk) {
            uint32_t q4[4];
            const uint32_t qa = sb + (wid * 16 + (lane & 15)) * FROWB
                              + kk * 32 + (lane >> 4) * 16;
            LDSM_X4(q4[0], q4[1], q4[2], q4[3], qa);

            const int bkb = kk * 32 + ((lane >> 3) & 1) * 16;
#pragma unroll
            for (int p = 0; p < 4; ++p) {
                uint32_t b4[2][2];
                const uint32_t ba = (p * 16 + brow_in) * FROWB + bkb;
                LDSM_X4(b4[0][0], b4[0][1], b4[1][0], b4[1][1], kP + ba);
#pragma unroll
                for (int u = 0; u < 2; ++u) {
                    float* cc = s[2 * p + u];
                    MMA_FP16(cc[0], cc[1], cc[2], cc[3],
                             q4[0], q4[1], q4[2], q4[3], b4[u][0], b4[u][1]);
                }
            }
        }

        // ---- mask (permuted bf16) + online softmax ----
        {
            const uint4* mp = reinterpret_cast<const uint4*>(mbase + (size_t)c * MBLK);
            uint32_t mu[16];
#pragma unroll
            for (int i = 0; i < 4; ++i) {
                uint4 q = mp[i];
                mu[4 * i + 0] = q.x; mu[4 * i + 1] = q.y;
                mu[4 * i + 2] = q.z; mu[4 * i + 3] = q.w;
            }
#pragma unroll
            for (int t = 0; t < 8; ++t) {
                float2 lo2 = __bfloat1622float2(
                    *reinterpret_cast<__nv_bfloat162*>(&mu[2 * t]));
                float2 hi2 = __bfloat1622float2(
                    *reinterpret_cast<__nv_bfloat162*>(&mu[2 * t + 1]));
                s[t][0] += lo2.x; s[t][1] += lo2.y;
                s[t][2] += hi2.x; s[t][3] += hi2.y;
            }
        }

        float mx0 = -1e30f, mx1 = -1e30f;
#pragma unroll
        for (int t = 0; t < 8; ++t) {
            mx0 = fmaxf(mx0, fmaxf(s[t][0], s[t][1]));
            mx1 = fmaxf(mx1, fmaxf(s[t][2], s[t][3]));
        }
        mx0 = fmaxf(mx0, __shfl_xor_sync(0xffffffffu, mx0, 1));
        mx0 = fmaxf(mx0, __shfl_xor_sync(0xffffffffu, mx0, 2));
        mx1 = fmaxf(mx1, __shfl_xor_sync(0xffffffffu, mx1, 1));
        mx1 = fmaxf(mx1, __shfl_xor_sync(0xffffffffu, mx1, 2));

        const float mn0 = fmaxf(m0, mx0);
        const float mn1 = fmaxf(m1, mx1);
        const float a0 = __expf(m0 - mn0);
        const float a1 = __expf(m1 - mn1);
        m0 = mn0; m1 = mn1;

        float sum0 = 0.0f, sum1 = 0.0f;
#pragma unroll
        for (int t = 0; t < 8; ++t) {
            s[t][0] = __expf(s[t][0] - mn0);
            s[t][1] = __expf(s[t][1] - mn0);
            s[t][2] = __expf(s[t][2] - mn1);
            s[t][3] = __expf(s[t][3] - mn1);
            sum0 += s[t][0] + s[t][1];
            sum1 += s[t][2] + s[t][3];
        }
        sum0 += __shfl_xor_sync(0xffffffffu, sum0, 1);
        sum0 += __shfl_xor_sync(0xffffffffu, sum0, 2);
        sum1 += __shfl_xor_sync(0xffffffffu, sum1, 1);
        sum1 += __shfl_xor_sync(0xffffffffu, sum1, 2);
        l0 = l0 * a0 + sum0;
        l1 = l1 * a1 + sum1;

#pragma unroll
        for (int t = 0; t < 8; ++t) {
            o[t][0] *= a0; o[t][1] *= a0;
            o[t][2] *= a1; o[t][3] *= a1;
        }

        // ---- P fragments (fp16) ----
        uint32_t pH[4][4];
#pragma unroll
        for (int j = 0; j < 4; ++j) {
#pragma unroll
            for (int u = 0; u < 2; ++u) {
#pragma unroll
                for (int w = 0; w < 2; ++w) {
                    __half2 hh = __float22half2_rn(make_float2(
                        s[2 * j + w][2 * u + 0], s[2 * j + w][2 * u + 1]));
                    pH[j][2 * w + u] = *reinterpret_cast<uint32_t*>(&hh);
                }
            }
        }

        // ---- O += P @ V (fp16, 1 pass) ----
#pragma unroll
        for (int j = 0; j < 4; ++j) {
#pragma unroll
            for (int p = 0; p < 4; ++p) {
                uint32_t v4[2][2];
                const uint32_t va = (j * 16 + (lane & 15)) * FROWB
                                  + p * 32 + (lane >> 4) * 16;
                LDSM_X4_T(v4[0][0], v4[0][1], v4[1][0], v4[1][1], vP + va);
#pragma unroll
                for (int u = 0; u < 2; ++u) {
                    float* cc = o[2 * p + u];
                    MMA_FP16(cc[0], cc[1], cc[2], cc[3],
                             pH[j][0], pH[j][1], pH[j][2], pH[j][3],
                             v4[u][0], v4[u][1]);
                }
            }
        }
        __syncthreads();
    }

    // ---- epilogue: normalize, write blocked single fp16 plane A ----
    const float inv0 = 1.0f / l0;
    const float inv1 = 1.0f / l1;
    const int grow = b * Tq + r0g;
#pragma unroll
    for (int t = 0; t < 8; ++t) {
        const int col = h * DHq + t * 8 + quadcol;
        {
            unsigned char* base = ap
                + ((size_t)((grow >> 7) * KCq + (col >> 5))) * XBLK
                + (grow & 127) * 80 + (col & 31) * 2;
            __half2 hh = __float22half2_rn(make_float2(o[t][0] * inv0, o[t][1] * inv0));
            *reinterpret_cast<uint32_t*>(base) = *reinterpret_cast<uint32_t*>(&hh);
        }
        {
            const int grow2 = grow + 8;
            unsigned char* base = ap
                + ((size_t)((grow2 >> 7) * KCq + (col >> 5))) * XBLK
                + (grow2 & 127) * 80 + (col & 31) * 2;
            __half2 hh = __float22half2_rn(make_float2(o[t][2] * inv1, o[t][3] * inv1));
            *reinterpret_cast<uint32_t*>(base) = *reinterpret_cast<uint32_t*>(&hh);
        }
    }
}

// ---------------------------------------------------------------------------
// kernel_launch
// Inputs: x, attention_mask, Wq, Wk, Wv, Wo, bo
// ---------------------------------------------------------------------------
extern "C" void kernel_launch(void* const* d_in, const int* in_sizes, int n_in,
                              void* d_out, int out_size)
{
    (void)in_sizes; (void)n_in; (void)out_size;
    const float* x    = (const float*)d_in[0];
    const float* mask = (const float*)d_in[1];
    const float* Wq   = (const float*)d_in[2];
    const float* Wk   = (const float*)d_in[3];
    const float* Wv   = (const float*)d_in[4];
    const float* Wo   = (const float*)d_in[5];
    const float* bo   = (const float*)d_in[6];
    float* out = (float*)d_out;

    unsigned char *xp, *ap, *w, *qb, *kpb, *vpb, *maskp;
    cudaGetSymbolAddress((void**)&xp, g_xp);
    cudaGetSymbolAddress((void**)&ap, g_ap);
    cudaGetSymbolAddress((void**)&w, g_w);
    cudaGetSymbolAddress((void**)&qb, g_qb);
    cudaGetSymbolAddress((void**)&kpb, g_kp);
    cudaGetSymbolAddress((void**)&vpb, g_vp);
    cudaGetSymbolAddress((void**)&maskp, g_maskp);

    const int M = Bq * Tq;     // 8192
    const int N = INNERq;      // 1024
    const int K = Dq;          // 1024
    const int nx = M * K;

    // Side stream for the mask permute (fork/join is graph-capturable).
    static cudaStream_t s2 = nullptr;
    static cudaEvent_t evFork = nullptr, evJoin = nullptr;
    if (s2 == nullptr) {
        cudaStreamCreateWithFlags(&s2, cudaStreamNonBlocking);
        cudaEventCreateWithFlags(&evFork, cudaEventDisableTiming);
        cudaEventCreateWithFlags(&evJoin, cudaEventDisableTiming);
    }

    cudaEventRecord(evFork, 0);
    cudaStreamWaitEvent(s2, evFork, 0);
    dim3 mGrid(32, 16, Bq);
    mask_permute<<<mGrid, 256, 0, s2>>>(mask, maskp);
    cudaEventRecord(evJoin, s2);

    // main chain: conversions -> blocked layouts
    split_kernel<<<nx / (256 * 4), 256>>>(x, xp);
    dim3 tGrid(N / 32, K / 32, 4), tBlk(32, 8);
    tsplit_kernel<<<tGrid, tBlk>>>(Wq, Wk, Wv, Wo, w, K, N);

    // Q,K,V projections (one launch, 4-stage bulk pipeline, pure fp16)
    cudaFuncSetAttribute(gemm_bulk_kernel,
                         cudaFuncAttributeMaxDynamicSharedMemorySize, GEMM_SMEM);
    dim3 qkvGrid(N / GBN, M / GBM, 3);
    gemm_bulk_kernel<<<qkvGrid, 256, GEMM_SMEM>>>(xp, w, qb, kpb, vpb,
                                                  nullptr, nullptr, M, N, K);

    cudaStreamWaitEvent(0, evJoin, 0);

    // flash attention (pure fp16, 4-stage KV pipeline)
    cudaFuncSetAttribute(flash_mma_kernel,
                         cudaFuncAttributeMaxDynamicSharedMemorySize, FLASH_SMEM);
    dim3 fGrid(Tq / FBQ, Hq, Bq);
    flash_mma_kernel<<<fGrid, 256, FLASH_SMEM>>>(maskp, qb, kpb, vpb, ap);

    // output projection (fp32 + bias, pure fp16)
    dim3 oGrid(N / GBN, M / GBM, 1);
    gemm_bulk_kernel<<<oGrid, 256, GEMM_SMEM>>>(ap, w + 3 * WONE_BYTES,
                                                nullptr, nullptr, nullptr,
                                                out, bo, M, Dq, INNERq);
}